// round 9
// baseline (speedup 1.0000x reference)
#include <cuda_runtime.h>
#include <cuda_fp16.h>
#include <math.h>

#define NN 10000
#define NE 200000
#define D  256
#define EPSF 1e-6f

typedef unsigned long long u64;

// ---------------- scratch (device globals: no allocation allowed) ----------
__device__ __align__(128) float g_u[NN * D];
__device__ __align__(128) float g_h[NN * D];
__device__ __align__(128) float g_xp[NN * D];
__device__ __align__(128) float g_xtan[NN * D];
__device__ __align__(128) __half g_Qh[NN * D];
__device__ __align__(128) __half g_P1h[NN * D];
__device__ __align__(128) __half g_P2h[NN * D];
__device__ __align__(128) float g_H[NN * D];
__device__ __align__(128) float g_agg[NN * D];
__device__ __align__(128) float g_S[NN];
// CSR scratch
__device__ int g_cnt[NN];
__device__ int g_pos[NN];
__device__ int g_off[NN + 1];
__device__ int g_eid[NE];

// ---------------- packed f32x2 helpers (SIMT GEMM) ---------------------------
__device__ __forceinline__ u64 dup2(float v) {
    u64 r; asm("mov.b64 %0,{%1,%1};" : "=l"(r) : "f"(v)); return r;
}
__device__ __forceinline__ void fma2(u64& c, u64 a, u64 b) {
    asm("fma.rn.f32x2 %0,%1,%2,%0;" : "+l"(c) : "l"(a), "l"(b));
}
__device__ __forceinline__ float2 unpack2(u64 v) {
    float2 f; asm("mov.b64 {%0,%1},%2;" : "=f"(f.x), "=f"(f.y) : "l"(v)); return f;
}

// ---------------- tf32 helpers ------------------------------------------------
__device__ __forceinline__ unsigned t32(float f) {
    unsigned r; asm("cvt.rna.tf32.f32 %0,%1;" : "=r"(r) : "f"(f)); return r;
}
__device__ __forceinline__ void mma_tf32(float* d, const uint4& a, const uint2& b) {
    asm volatile(
        "mma.sync.aligned.m16n8k8.row.col.f32.tf32.tf32.f32 "
        "{%0,%1,%2,%3},{%4,%5,%6,%7},{%8,%9},{%0,%1,%2,%3};"
        : "+f"(d[0]), "+f"(d[1]), "+f"(d[2]), "+f"(d[3])
        : "r"(a.x), "r"(a.y), "r"(a.z), "r"(a.w), "r"(b.x), "r"(b.y));
}

// ---------------- misc helpers ------------------------------------------------
__device__ __forceinline__ float warpSum(float v) {
    #pragma unroll
    for (int o = 16; o > 0; o >>= 1) v += __shfl_xor_sync(0xffffffffu, v, o);
    return v;
}
__device__ __forceinline__ float siluf(float x) { return x / (1.f + expf(-x)); }
__device__ __forceinline__ float tanh_ap(float x) {
    float y; asm("tanh.approx.f32 %0,%1;" : "=f"(y) : "f"(x)); return y;
}
__device__ __forceinline__ float sigm_fast(float x) {
    return fmaf(0.5f, tanh_ap(0.5f * x), 0.5f);
}
__device__ __forceinline__ float silu_fast(float x) { return x * sigm_fast(x); }

__device__ __forceinline__ void ld8h(const __half* p, float* o) {
    uint4 v = *(const uint4*)p;
    __half2 h0 = *(__half2*)&v.x, h1 = *(__half2*)&v.y,
            h2 = *(__half2*)&v.z, h3 = *(__half2*)&v.w;
    float2 f;
    f = __half22float2(h0); o[0] = f.x; o[1] = f.y;
    f = __half22float2(h1); o[2] = f.x; o[3] = f.y;
    f = __half22float2(h2); o[4] = f.x; o[5] = f.y;
    f = __half22float2(h3); o[6] = f.x; o[7] = f.y;
}

// ---------------- kernel 1: u = logmap0(x); zero CSR counters ---------------
__global__ void k_logmap0(const float* __restrict__ x) {
    int idx = blockIdx.x * blockDim.x + threadIdx.x;
    if (idx >= NN * D) return;
    int n = idx >> 8;
    int j = idx & (D - 1);
    float x0 = fmaxf(x[n * D], 1.f + EPSF);
    float outv;
    if (j == 0) {
        outv = 0.f;
    } else {
        float dd = acoshf(x0);
        float sc = dd / sqrtf(x0 * x0 - 1.f);
        outv = sc * x[idx];
    }
    g_u[idx] = outv;
    if (idx < NN) g_cnt[idx] = 0;
}

// ---------------- CSR build --------------------------------------------------
__global__ void k_hist(const int* __restrict__ row) {
    int e = blockIdx.x * blockDim.x + threadIdx.x;
    if (e < NE) atomicAdd(&g_cnt[row[e]], 1);
}

__global__ __launch_bounds__(256) void k_scan() {   // single block
    __shared__ int sm[256];
    int t = threadIdx.x;
    int base = t * 40;                               // 256*40 = 10240 >= 10001
    int local = 0;
    for (int i = 0; i < 40; i++) {
        int idx = base + i;
        if (idx < NN) local += g_cnt[idx];
    }
    sm[t] = local;
    __syncthreads();
    #pragma unroll
    for (int o = 1; o < 256; o <<= 1) {
        int v = (t >= o) ? sm[t - o] : 0;
        __syncthreads();
        sm[t] += v;
        __syncthreads();
    }
    int run = sm[t] - local;                         // exclusive prefix
    for (int i = 0; i < 40; i++) {
        int idx = base + i;
        if (idx < NN) {
            g_off[idx] = run;
            g_pos[idx] = run;
            run += g_cnt[idx];
        } else if (idx == NN) {
            g_off[NN] = run;
        }
    }
}

__global__ void k_scatter(const int* __restrict__ row) {
    int e = blockIdx.x * blockDim.x + threadIdx.x;
    if (e >= NE) return;
    int p = atomicAdd(&g_pos[row[e]], 1);
    g_eid[p] = e;
}

// ---------------- SIMT SGEMM (fp32-exact path for W_lin) --------------------
__global__ __launch_bounds__(128) void sgemm32(const float* __restrict__ A,
                                               const float* __restrict__ B,
                                               float* __restrict__ C, int M) {
    __shared__ float As[2][8][128];
    __shared__ u64   Bs[2][8][16];
    const int K = 256, N = 256;
    int tid = threadIdx.x;
    int tm = tid >> 3;
    int tn = tid & 7;
    int rowBase = blockIdx.y * 128;
    int colBase = blockIdx.x * 32;

    int arow = rowBase + tid;
    bool aok = arow < M;
    const float* Aptr = A + (size_t)arow * K;
    int brow = tid >> 4;
    int bcol = (tid & 15) * 2;
    const float* Bptr = B + (size_t)brow * N + colBase + bcol;

    const float4 z4 = make_float4(0.f, 0.f, 0.f, 0.f);

    float4 a0 = aok ? *(const float4*)(Aptr + 0) : z4;
    float4 a1 = aok ? *(const float4*)(Aptr + 4) : z4;
    float2 b0 = *(const float2*)(Bptr);
    As[0][0][tid] = a0.x; As[0][1][tid] = a0.y; As[0][2][tid] = a0.z; As[0][3][tid] = a0.w;
    As[0][4][tid] = a1.x; As[0][5][tid] = a1.y; As[0][6][tid] = a1.z; As[0][7][tid] = a1.w;
    *(float2*)&Bs[0][brow][bcol >> 1] = b0;
    __syncthreads();

    u64 acc[8][2];
    #pragma unroll
    for (int i = 0; i < 8; i++) { acc[i][0] = 0ull; acc[i][1] = 0ull; }

    int buf = 0;
    for (int kb = 0; kb < 32; kb++) {
        if (kb < 31) {
            const float* ap = Aptr + (kb + 1) * 8;
            a0 = aok ? *(const float4*)(ap + 0) : z4;
            a1 = aok ? *(const float4*)(ap + 4) : z4;
            b0 = *(const float2*)(Bptr + (size_t)(kb + 1) * 8 * N);
        }
        #pragma unroll
        for (int k = 0; k < 8; k++) {
            float4 av0 = *(const float4*)&As[buf][k][tm * 8];
            float4 av1 = *(const float4*)&As[buf][k][tm * 8 + 4];
            ulonglong2 bv = *(const ulonglong2*)&Bs[buf][k][tn * 2];
            u64 ad;
            ad = dup2(av0.x); fma2(acc[0][0], ad, bv.x); fma2(acc[0][1], ad, bv.y);
            ad = dup2(av0.y); fma2(acc[1][0], ad, bv.x); fma2(acc[1][1], ad, bv.y);
            ad = dup2(av0.z); fma2(acc[2][0], ad, bv.x); fma2(acc[2][1], ad, bv.y);
            ad = dup2(av0.w); fma2(acc[3][0], ad, bv.x); fma2(acc[3][1], ad, bv.y);
            ad = dup2(av1.x); fma2(acc[4][0], ad, bv.x); fma2(acc[4][1], ad, bv.y);
            ad = dup2(av1.y); fma2(acc[5][0], ad, bv.x); fma2(acc[5][1], ad, bv.y);
            ad = dup2(av1.z); fma2(acc[6][0], ad, bv.x); fma2(acc[6][1], ad, bv.y);
            ad = dup2(av1.w); fma2(acc[7][0], ad, bv.x); fma2(acc[7][1], ad, bv.y);
        }
        if (kb < 31) {
            int nb = buf ^ 1;
            As[nb][0][tid] = a0.x; As[nb][1][tid] = a0.y; As[nb][2][tid] = a0.z; As[nb][3][tid] = a0.w;
            As[nb][4][tid] = a1.x; As[nb][5][tid] = a1.y; As[nb][6][tid] = a1.z; As[nb][7][tid] = a1.w;
            *(float2*)&Bs[nb][brow][bcol >> 1] = b0;
            __syncthreads();
            buf = nb;
        }
    }

    #pragma unroll
    for (int i = 0; i < 8; i++) {
        int gr = rowBase + tm * 8 + i;
        if (gr >= M) continue;
        float2 p0 = unpack2(acc[i][0]);
        float2 p1 = unpack2(acc[i][1]);
        *(float4*)&C[(size_t)gr * N + colBase + tn * 4] =
            make_float4(p0.x, p0.y, p1.x, p1.y);
    }
}

// ---------------- tf32 MMA GEMM: BM=64, BN=128, BK=32, 128 threads -----------
struct StA { float4 f00, f01, f10, f11; };
struct StB { float2 g[8]; };

__device__ __forceinline__ void mma_stage_fetchA(StA& st, const float* pa0,
                                                 const float* pa1, bool ok0,
                                                 bool ok1) {
    const float4 z4 = make_float4(0.f, 0.f, 0.f, 0.f);
    st.f00 = ok0 ? *(const float4*)(pa0)     : z4;
    st.f01 = ok0 ? *(const float4*)(pa0 + 4) : z4;
    st.f10 = ok1 ? *(const float4*)(pa1)     : z4;
    st.f11 = ok1 ? *(const float4*)(pa1 + 4) : z4;
}
__device__ __forceinline__ void mma_stage_storeA(unsigned* dst, const StA& st) {
    const float* a00 = &st.f00.x;
    const float* a01 = &st.f01.x;
    const float* a10 = &st.f10.x;
    const float* a11 = &st.f11.x;
    #pragma unroll
    for (int dl = 0; dl < 4; dl++) {
        uint4 v = make_uint4(t32(a00[dl]), t32(a10[dl]), t32(a01[dl]), t32(a11[dl]));
        ((uint4*)dst)[dl] = v;
    }
}
__device__ __forceinline__ void mma_stage_fetchB(StB& st, const float* pb) {
    #pragma unroll
    for (int j = 0; j < 8; j++) st.g[j] = *(const float2*)(pb + j * 256);
}
__device__ __forceinline__ void mma_stage_storeB(unsigned* dst, const StB& st) {
    uint4 v0 = make_uint4(t32(st.g[0].x), t32(st.g[4].x), t32(st.g[1].x), t32(st.g[5].x));
    uint4 v1 = make_uint4(t32(st.g[2].x), t32(st.g[6].x), t32(st.g[3].x), t32(st.g[7].x));
    uint4 v2 = make_uint4(t32(st.g[0].y), t32(st.g[4].y), t32(st.g[1].y), t32(st.g[5].y));
    uint4 v3 = make_uint4(t32(st.g[2].y), t32(st.g[6].y), t32(st.g[3].y), t32(st.g[7].y));
    ((uint4*)dst)[0] = v0; ((uint4*)dst)[1] = v1;
    ((uint4*)dst)[2] = v2; ((uint4*)dst)[3] = v3;
}

template <int OUT_HALF>
__device__ __forceinline__ void mma_gemm_body(const float* __restrict__ A,
                                              const float* __restrict__ B,
                                              void* __restrict__ Cv, int M) {
    __shared__ __align__(16) unsigned smA[2][2048];
    __shared__ __align__(16) unsigned smB[2][4096];
    int tid = threadIdx.x;
    int lane = tid & 31;
    int w = tid >> 5;
    int wm = w & 1, wn = w >> 1;
    int rowBase = blockIdx.y * 64;
    int colBase = blockIdx.x * 128;

    int aRow0 = rowBase + (tid >> 5) * 16 + (tid & 7);
    const float* pa0 = A + (size_t)aRow0 * 256 + ((tid >> 3) & 3) * 8;
    const float* pa1 = pa0 + 8 * 256;
    bool ok0 = aRow0 < M, ok1 = (aRow0 + 8) < M;
    const float* pb = B + (size_t)((tid >> 2) & 3) * 8 * 256 +
                      colBase + (tid >> 4) * 8 + 2 * (tid & 3);

    StA stA; StB stB0, stB1;
    mma_stage_fetchA(stA, pa0, pa1, ok0, ok1);
    mma_stage_fetchB(stB0, pb);
    mma_stage_fetchB(stB1, pb + 64);
    mma_stage_storeA(&smA[0][tid * 16], stA);
    mma_stage_storeB(&smB[0][tid * 16], stB0);
    mma_stage_storeB(&smB[0][2048 + tid * 16], stB1);
    __syncthreads();

    float d[2][8][4];
    #pragma unroll
    for (int t = 0; t < 2; t++)
        #pragma unroll
        for (int u = 0; u < 8; u++)
            #pragma unroll
            for (int c = 0; c < 4; c++) d[t][u][c] = 0.f;

    int buf = 0;
    for (int kb = 0; kb < 8; kb++) {
        if (kb < 7) {
            mma_stage_fetchA(stA, pa0 + (kb + 1) * 32, pa1 + (kb + 1) * 32, ok0, ok1);
            mma_stage_fetchB(stB0, pb + (size_t)(kb + 1) * 32 * 256);
            mma_stage_fetchB(stB1, pb + (size_t)(kb + 1) * 32 * 256 + 64);
        }
        #pragma unroll
        for (int s = 0; s < 4; s++) {
            uint4 fa0 = *(const uint4*)&smA[buf][((2 * wm + 0) * 4 + s) * 128 + lane * 4];
            uint4 fa1 = *(const uint4*)&smA[buf][((2 * wm + 1) * 4 + s) * 128 + lane * 4];
            uint2 fb[8];
            #pragma unroll
            for (int u = 0; u < 8; u++)
                fb[u] = *(const uint2*)&smB[buf][wn * 2048 + (u * 4 + s) * 64 + lane * 2];
            #pragma unroll
            for (int u = 0; u < 8; u++) {
                mma_tf32(d[0][u], fa0, fb[u]);
                mma_tf32(d[1][u], fa1, fb[u]);
            }
        }
        if (kb < 7) {
            int nb = buf ^ 1;
            mma_stage_storeA(&smA[nb][tid * 16], stA);
            mma_stage_storeB(&smB[nb][tid * 16], stB0);
            mma_stage_storeB(&smB[nb][2048 + tid * 16], stB1);
            __syncthreads();
            buf = nb;
        }
    }

    #pragma unroll
    for (int t = 0; t < 2; t++) {
        int r0 = rowBase + (2 * wm + t) * 16 + (lane >> 2);
        int r1 = r0 + 8;
        #pragma unroll
        for (int u = 0; u < 8; u++) {
            int c0 = colBase + wn * 64 + u * 8 + (lane & 3) * 2;
            if (OUT_HALF) {
                __half* C = (__half*)Cv;
                if (r0 < M)
                    *(__half2*)(C + (size_t)r0 * 256 + c0) =
                        __floats2half2_rn(d[t][u][0], d[t][u][1]);
                if (r1 < M)
                    *(__half2*)(C + (size_t)r1 * 256 + c0) =
                        __floats2half2_rn(d[t][u][2], d[t][u][3]);
            } else {
                float* C = (float*)Cv;
                if (r0 < M)
                    *(float2*)(C + (size_t)r0 * 256 + c0) =
                        make_float2(d[t][u][0], d[t][u][1]);
                if (r1 < M)
                    *(float2*)(C + (size_t)r1 * 256 + c0) =
                        make_float2(d[t][u][2], d[t][u][3]);
            }
        }
    }
}

__global__ __launch_bounds__(128, 3) void mma_qp(const float* __restrict__ We1,
                                                 const float* __restrict__ Wa1) {
    int z = blockIdx.z;
    const float* A = (z == 0) ? g_xp : g_xtan;
    const float* B = (z == 0) ? We1 : (z == 1 ? Wa1 : Wa1 + 256 * 256);
    __half* C = (z == 0) ? g_Qh : (z == 1 ? g_P1h : g_P2h);
    mma_gemm_body<1>(A, B, (void*)C, NN);
}

__global__ __launch_bounds__(128, 3) void mma_agg(const float* __restrict__ We2) {
    mma_gemm_body<0>(g_H, We2, (void*)g_agg, NN);
}

// ---------------- node prep: one warp per node --------------------------------
__global__ __launch_bounds__(256) void k_node_xp(const float* __restrict__ bias) {
    int node = blockIdx.x * 8 + (threadIdx.x >> 5);
    int lane = threadIdx.x & 31;
    int base = lane * 8;

    float h[8];
    const float* hp = g_h + (size_t)node * D + base;
    *(float4*)&h[0] = *(const float4*)(hp);
    *(float4*)&h[4] = *(const float4*)(hp + 4);
    if (lane == 0) h[0] = 0.f;

    float acc = 0.f;
    #pragma unroll
    for (int i = 0; i < 8; i++) acc += h[i] * h[i];
    float r1 = warpSum(acc);
    float nn = sqrtf(fmaxf(r1, EPSF));
    float sh_n = sinhf(nn) / nn;
    float xp00 = coshf(nn);
    float xp0[8];
    #pragma unroll
    for (int i = 0; i < 8; i++) xp0[i] = sh_n * h[i];
    if (lane == 0) xp0[0] = xp00;

    float b[8];
    *(float4*)&b[0] = *(const float4*)(bias + base);
    *(float4*)&b[4] = *(const float4*)(bias + base + 4);
    if (lane == 0) b[0] = 0.f;

    acc = 0.f;
    #pragma unroll
    for (int i = 0; i < 8; i++) acc += xp0[i] * b[i];
    float c = warpSum(acc);
    float fac = c / (1.f + xp00);
    float u[8];
    #pragma unroll
    for (int i = 0; i < 8; i++) u[i] = b[i] + fac * xp0[i];
    if (lane == 0) u[0] += fac;

    acc = 0.f;
    #pragma unroll
    for (int i = 0; i < 8; i++) acc += u[i] * u[i];
    float su2 = warpSum(acc);
    float lin = su2 - 2.f * c * c;
    float nu = sqrtf(fmaxf(lin, EPSF));
    float ch = coshf(nu), sh = sinhf(nu) / nu;

    float xp[8];
    #pragma unroll
    for (int i = 0; i < 8; i++) xp[i] = ch * xp0[i] + sh * u[i];
    float* xpp = g_xp + (size_t)node * D + base;
    *(float4*)(xpp)     = *(float4*)&xp[0];
    *(float4*)(xpp + 4) = *(float4*)&xp[4];

    float xpc0 = ch * xp00 + sh * c;
    float x0c = fmaxf(xpc0, 1.f + EPSF);
    float sc = acoshf(x0c) / sqrtf(x0c * x0c - 1.f);
    float xt[8];
    #pragma unroll
    for (int i = 0; i < 8; i++) xt[i] = sc * xp[i];
    if (lane == 0) xt[0] = 0.f;
    float* xtp = g_xtan + (size_t)node * D + base;
    *(float4*)(xtp)     = *(float4*)&xt[0];
    *(float4*)(xtp + 4) = *(float4*)&xt[4];
}

// ---------------- edge kernel, CSR: one warp per destination node ------------
// Row-side data loaded once per node into registers; H/S accumulate in regs;
// no atomics anywhere.
__global__ __launch_bounds__(256) void k_edge_csr(
    const float* __restrict__ eattr, const int* __restrict__ col,
    const float* __restrict__ emask,
    const float* __restrict__ Wa1, const float* __restrict__ ba1,
    const float* __restrict__ Wa2, const float* __restrict__ ba2,
    const float* __restrict__ We1, const float* __restrict__ be1) {
    __shared__ float sw[8][256];
    int tid = threadIdx.x;
    sw[0][tid] = Wa1[512 * D + tid];
    sw[1][tid] = Wa1[513 * D + tid];
    sw[2][tid] = ba1[tid];
    sw[3][tid] = Wa2[tid];
    sw[4][tid] = We1[tid];
    sw[5][tid] = We1[256 * D + tid];
    sw[6][tid] = We1[257 * D + tid];
    sw[7][tid] = be1[tid];
    __syncthreads();

    int node = blockIdx.x * 8 + (tid >> 5);
    int lane = tid & 31;
    int base = lane * 8;
    float ba2v = ba2[0];

    // row-side data, loaded once
    float xr[8], P1r[8], Qr[8];
    const float* xrp = g_xp + (size_t)node * D + base;
    *(float4*)&xr[0] = *(const float4*)(xrp);
    *(float4*)&xr[4] = *(const float4*)(xrp + 4);
    ld8h(g_P1h + (size_t)node * D + base, P1r);
    ld8h(g_Qh + (size_t)node * D + base, Qr);
    float x0 = __shfl_sync(0xffffffffu, xr[0], 0);

    float Hacc[8] = {0.f, 0.f, 0.f, 0.f, 0.f, 0.f, 0.f, 0.f};
    float Sacc = 0.f;

    int s0 = g_off[node];
    int s1 = g_off[node + 1];

    for (int k = s0; k < s1; k++) {
        int e = g_eid[k];
        int c = col[e];
        const float* xcp = g_xp + (size_t)c * D + base;
        float xc[8];
        *(float4*)&xc[0] = *(const float4*)(xcp);
        *(float4*)&xc[4] = *(const float4*)(xcp + 4);

        float part = 0.f;
        #pragma unroll
        for (int i = 0; i < 8; i++) part -= xr[i] * xc[i];
        part = warpSum(part);

        float y0 = __shfl_sync(0xffffffffu, xc[0], 0);
        float a = fmaxf(part + 2.f * x0 * y0, 1.f + EPSF);
        float dd = acoshf(a);
        float q = sqrtf(a * a - 1.f);
        float s = dd / q;
        float v0 = s * (y0 - a * x0);
        float beta = -v0 / (1.f + x0);
        float alpha = beta - s * a;

        float ea0 = eattr[e];
        float m = emask[e];

        float P2v[8], QC[8];
        ld8h(g_P2h + (size_t)c * D + base, P2v);
        ld8h(g_Qh + (size_t)c * D + base, QC);

        float lp = 0.f;
        #pragma unroll
        for (int i = 0; i < 8; i++) {
            int j = base + i;
            float ha = P1r[i] + P2v[i] + ea0 * sw[0][j] + dd * sw[1][j] + sw[2][j];
            lp += silu_fast(ha) * sw[3][j];
        }
        lp = warpSum(lp);
        float att = m * sigm_fast(lp + ba2v);

        #pragma unroll
        for (int i = 0; i < 8; i++) {
            int j = base + i;
            float hm = alpha * Qr[i] + s * QC[i] + beta * sw[4][j] +
                       ea0 * sw[5][j] + dd * sw[6][j] + sw[7][j];
            Hacc[i] = fmaf(att, silu_fast(hm), Hacc[i]);
        }
        Sacc += att;
    }

    float* Hp = g_H + (size_t)node * D + base;
    *(float4*)(Hp)     = *(float4*)&Hacc[0];
    *(float4*)(Hp + 4) = *(float4*)&Hacc[4];
    if (lane == 0) g_S[node] = Sacc;
}

// ---------------- final node kernel: one warp per node -----------------------
__global__ __launch_bounds__(256) void k_final(const float* __restrict__ be2,
                                               const float* __restrict__ lng,
                                               const float* __restrict__ lnb,
                                               float* __restrict__ out) {
    int node = blockIdx.x * 8 + (threadIdx.x >> 5);
    int lane = threadIdx.x & 31;
    int base = lane * 8;

    float Sv = g_S[node];
    float ag[8], be[8], xp[8];
    const float* agp = g_agg + (size_t)node * D + base;
    *(float4*)&ag[0] = *(const float4*)(agp);
    *(float4*)&ag[4] = *(const float4*)(agp + 4);
    *(float4*)&be[0] = *(const float4*)(be2 + base);
    *(float4*)&be[4] = *(const float4*)(be2 + base + 4);
    const float* xpp = g_xp + (size_t)node * D + base;
    *(float4*)&xp[0] = *(const float4*)(xpp);
    *(float4*)&xp[4] = *(const float4*)(xpp + 4);

    #pragma unroll
    for (int i = 0; i < 8; i++) ag[i] += Sv * be[i];
    if (lane == 0) ag[0] = 0.f;

    float xp0 = __shfl_sync(0xffffffffu, xp[0], 0);

    float acc = 0.f;
    #pragma unroll
    for (int i = 0; i < 8; i++) acc += xp[i] * ag[i];
    float cc = warpSum(acc);
    float fac = cc / (1.f + xp0);
    float sup[8];
    #pragma unroll
    for (int i = 0; i < 8; i++) sup[i] = ag[i] + fac * xp[i];
    if (lane == 0) sup[0] += fac;

    acc = 0.f;
    #pragma unroll
    for (int i = 0; i < 8; i++) acc += sup[i] * sup[i];
    float su2 = warpSum(acc);
    float lin = su2 - 2.f * cc * cc;
    float nu = sqrtf(fmaxf(lin, EPSF));
    float ch = coshf(nu), sh = sinhf(nu) / nu;

    float y[8];
    #pragma unroll
    for (int i = 0; i < 8; i++) y[i] = ch * xp[i] + sh * sup[i];
    float y0 = ch * xp0 + sh * cc;

    float y0c = fmaxf(y0, 1.f + EPSF);
    float sc = acoshf(y0c) / sqrtf(y0c * y0c - 1.f);
    float xo[8];
    #pragma unroll
    for (int i = 0; i < 8; i++) xo[i] = sc * y[i];
    if (lane == 0) xo[0] = 0.f;

    acc = 0.f;
    #pragma unroll
    for (int i = 0; i < 8; i++) acc += xo[i];
    float mean = warpSum(acc) * (1.f / 255.f);
    float dev[8];
    #pragma unroll
    for (int i = 0; i < 8; i++) dev[i] = xo[i] - mean;
    if (lane == 0) dev[0] = 0.f;
    acc = 0.f;
    #pragma unroll
    for (int i = 0; i < 8; i++) acc += dev[i] * dev[i];
    float var = warpSum(acc) * (1.f / 255.f);
    float inv = 1.f / sqrtf(var + 1e-5f);

    float sl[8];
    #pragma unroll
    for (int i = 0; i < 8; i++) {
        int j = base + i;
        float lg = (j > 0) ? lng[j - 1] : 0.f;
        float lb = (j > 0) ? lnb[j - 1] : 0.f;
        float ln = dev[i] * inv * lg + lb;
        sl[i] = siluf(ln);
    }
    if (lane == 0) sl[0] = 0.f;

    acc = 0.f;
    #pragma unroll
    for (int i = 0; i < 8; i++) acc += sl[i] * sl[i];
    float n2 = warpSum(acc);
    float nn = sqrtf(fmaxf(n2, EPSF));
    float shn = sinhf(nn) / nn;

    float o[8];
    #pragma unroll
    for (int i = 0; i < 8; i++) o[i] = shn * sl[i];
    if (lane == 0) o[0] = coshf(nn);
    float* op = out + (size_t)node * D + base;
    *(float4*)(op)     = *(float4*)&o[0];
    *(float4*)(op + 4) = *(float4*)&o[4];
}

// ---------------- launch -----------------------------------------------------
extern "C" void kernel_launch(void* const* d_in, const int* in_sizes, int n_in,
                              void* d_out, int out_size) {
    const float* x     = (const float*)d_in[0];
    const float* eattr = (const float*)d_in[1];
    const int*   row   = (const int*)d_in[2];
    const int*   col   = (const int*)d_in[3];
    const float* emask = (const float*)d_in[5];
    const float* W_lin = (const float*)d_in[6];
    const float* bias  = (const float*)d_in[7];
    const float* W_e1  = (const float*)d_in[8];
    const float* b_e1  = (const float*)d_in[9];
    const float* W_e2  = (const float*)d_in[10];
    const float* b_e2  = (const float*)d_in[11];
    const float* W_a1  = (const float*)d_in[12];
    const float* b_a1  = (const float*)d_in[13];
    const float* W_a2  = (const float*)d_in[14];
    const float* b_a2  = (const float*)d_in[15];
    const float* ln_g  = (const float*)d_in[16];
    const float* ln_b  = (const float*)d_in[17];
    float* out = (float*)d_out;

    float *pu, *ph;
    cudaGetSymbolAddress((void**)&pu, g_u);
    cudaGetSymbolAddress((void**)&ph, g_h);

    dim3 gElem((NN * D + 255) / 256);
    dim3 gEdge((NE + 255) / 256);
    dim3 gGemm32(8, (NN + 127) / 128);
    dim3 gMmaQP(2, (NN + 63) / 64, 3);
    dim3 gMmaAgg(2, (NN + 63) / 64);

    k_logmap0<<<gElem, 256>>>(x);                       // also zeroes g_cnt
    k_hist<<<gEdge, 256>>>(row);
    k_scan<<<1, 256>>>();
    k_scatter<<<gEdge, 256>>>(row);
    sgemm32<<<gGemm32, 128>>>(pu, W_lin, ph, NN);       // fp32-exact
    k_node_xp<<<NN / 8, 256>>>(bias);
    mma_qp<<<gMmaQP, 128>>>(W_e1, W_a1);                // tf32 tensor cores
    k_edge_csr<<<NN / 8, 256>>>(eattr, col, emask, W_a1, b_a1, W_a2, b_a2, W_e1, b_e1);
    mma_agg<<<gMmaAgg, 128>>>(W_e2);                    // tf32 tensor cores
    k_final<<<NN / 8, 256>>>(b_e2, ln_g, ln_b, out);
}

// round 10
// speedup vs baseline: 1.0375x; 1.0375x over previous
#include <cuda_runtime.h>
#include <cuda_fp16.h>
#include <math.h>

#define NN 10000
#define NE 200000
#define D  256
#define EPSF 1e-6f

typedef unsigned long long u64;

// ---------------- scratch (device globals: no allocation allowed) ----------
__device__ __align__(128) float g_u[NN * D];
__device__ __align__(128) float g_h[NN * D];
__device__ __align__(128) float g_xp[NN * D];
__device__ __align__(128) float g_xtan[NN * D];
__device__ __align__(128) __half g_Qh[NN * D];
__device__ __align__(128) __half g_P1h[NN * D];
__device__ __align__(128) __half g_P2h[NN * D];
__device__ __align__(128) float g_H[NN * D];
__device__ __align__(128) float g_agg[NN * D];
__device__ __align__(128) float g_S[NN];
// CSR scratch
__device__ int g_cnt[NN];
__device__ int g_pos[NN];
__device__ int g_off[NN + 1];
__device__ int g_eid[NE];

// ---------------- packed f32x2 helpers (SIMT GEMM) ---------------------------
__device__ __forceinline__ u64 dup2(float v) {
    u64 r; asm("mov.b64 %0,{%1,%1};" : "=l"(r) : "f"(v)); return r;
}
__device__ __forceinline__ void fma2(u64& c, u64 a, u64 b) {
    asm("fma.rn.f32x2 %0,%1,%2,%0;" : "+l"(c) : "l"(a), "l"(b));
}
__device__ __forceinline__ float2 unpack2(u64 v) {
    float2 f; asm("mov.b64 {%0,%1},%2;" : "=f"(f.x), "=f"(f.y) : "l"(v)); return f;
}

// ---------------- tf32 helpers ------------------------------------------------
__device__ __forceinline__ unsigned t32(float f) {
    unsigned r; asm("cvt.rna.tf32.f32 %0,%1;" : "=r"(r) : "f"(f)); return r;
}
__device__ __forceinline__ void mma_tf32(float* d, const uint4& a, const uint2& b) {
    asm volatile(
        "mma.sync.aligned.m16n8k8.row.col.f32.tf32.tf32.f32 "
        "{%0,%1,%2,%3},{%4,%5,%6,%7},{%8,%9},{%0,%1,%2,%3};"
        : "+f"(d[0]), "+f"(d[1]), "+f"(d[2]), "+f"(d[3])
        : "r"(a.x), "r"(a.y), "r"(a.z), "r"(a.w), "r"(b.x), "r"(b.y));
}

// ---------------- misc helpers ------------------------------------------------
__device__ __forceinline__ float warpSum(float v) {
    #pragma unroll
    for (int o = 16; o > 0; o >>= 1) v += __shfl_xor_sync(0xffffffffu, v, o);
    return v;
}
__device__ __forceinline__ float siluf(float x) { return x / (1.f + expf(-x)); }
__device__ __forceinline__ float tanh_ap(float x) {
    float y; asm("tanh.approx.f32 %0,%1;" : "=f"(y) : "f"(x)); return y;
}
__device__ __forceinline__ float sigm_fast(float x) {
    return fmaf(0.5f, tanh_ap(0.5f * x), 0.5f);
}
__device__ __forceinline__ float silu_fast(float x) { return x * sigm_fast(x); }

__device__ __forceinline__ void ld8h(const __half* p, float* o) {
    uint4 v = *(const uint4*)p;
    __half2 h0 = *(__half2*)&v.x, h1 = *(__half2*)&v.y,
            h2 = *(__half2*)&v.z, h3 = *(__half2*)&v.w;
    float2 f;
    f = __half22float2(h0); o[0] = f.x; o[1] = f.y;
    f = __half22float2(h1); o[2] = f.x; o[3] = f.y;
    f = __half22float2(h2); o[4] = f.x; o[5] = f.y;
    f = __half22float2(h3); o[6] = f.x; o[7] = f.y;
}

// ---------------- kernel 1: u = logmap0(x); zero H/S/counters ----------------
__global__ void k_logmap0(const float* __restrict__ x) {
    int idx = blockIdx.x * blockDim.x + threadIdx.x;
    if (idx >= NN * D) return;
    int n = idx >> 8;
    int j = idx & (D - 1);
    float x0 = fmaxf(x[n * D], 1.f + EPSF);
    float outv;
    if (j == 0) {
        outv = 0.f;
    } else {
        float dd = acoshf(x0);
        float sc = dd / sqrtf(x0 * x0 - 1.f);
        outv = sc * x[idx];
    }
    g_u[idx] = outv;
    g_H[idx] = 0.f;
    if (idx < NN) { g_S[idx] = 0.f; g_cnt[idx] = 0; }
}

// ---------------- CSR build --------------------------------------------------
__global__ void k_hist(const int* __restrict__ row) {
    int e = blockIdx.x * blockDim.x + threadIdx.x;
    if (e < NE) atomicAdd(&g_cnt[row[e]], 1);
}

__global__ __launch_bounds__(256) void k_scan() {   // single block
    __shared__ int sm[256];
    int t = threadIdx.x;
    int base = t * 40;                               // 256*40 = 10240 >= 10001
    int local = 0;
    for (int i = 0; i < 40; i++) {
        int idx = base + i;
        if (idx < NN) local += g_cnt[idx];
    }
    sm[t] = local;
    __syncthreads();
    #pragma unroll
    for (int o = 1; o < 256; o <<= 1) {
        int v = (t >= o) ? sm[t - o] : 0;
        __syncthreads();
        sm[t] += v;
        __syncthreads();
    }
    int run = sm[t] - local;                         // exclusive prefix
    for (int i = 0; i < 40; i++) {
        int idx = base + i;
        if (idx < NN) {
            g_off[idx] = run;
            g_pos[idx] = run;
            run += g_cnt[idx];
        } else if (idx == NN) {
            g_off[NN] = run;
        }
    }
}

__global__ void k_scatter(const int* __restrict__ row) {
    int e = blockIdx.x * blockDim.x + threadIdx.x;
    if (e >= NE) return;
    int p = atomicAdd(&g_pos[row[e]], 1);
    g_eid[p] = e;
}

// ---------------- SIMT SGEMM (fp32-exact path for W_lin) --------------------
__global__ __launch_bounds__(128) void sgemm32(const float* __restrict__ A,
                                               const float* __restrict__ B,
                                               float* __restrict__ C, int M) {
    __shared__ float As[2][8][128];
    __shared__ u64   Bs[2][8][16];
    const int K = 256, N = 256;
    int tid = threadIdx.x;
    int tm = tid >> 3;
    int tn = tid & 7;
    int rowBase = blockIdx.y * 128;
    int colBase = blockIdx.x * 32;

    int arow = rowBase + tid;
    bool aok = arow < M;
    const float* Aptr = A + (size_t)arow * K;
    int brow = tid >> 4;
    int bcol = (tid & 15) * 2;
    const float* Bptr = B + (size_t)brow * N + colBase + bcol;

    const float4 z4 = make_float4(0.f, 0.f, 0.f, 0.f);

    float4 a0 = aok ? *(const float4*)(Aptr + 0) : z4;
    float4 a1 = aok ? *(const float4*)(Aptr + 4) : z4;
    float2 b0 = *(const float2*)(Bptr);
    As[0][0][tid] = a0.x; As[0][1][tid] = a0.y; As[0][2][tid] = a0.z; As[0][3][tid] = a0.w;
    As[0][4][tid] = a1.x; As[0][5][tid] = a1.y; As[0][6][tid] = a1.z; As[0][7][tid] = a1.w;
    *(float2*)&Bs[0][brow][bcol >> 1] = b0;
    __syncthreads();

    u64 acc[8][2];
    #pragma unroll
    for (int i = 0; i < 8; i++) { acc[i][0] = 0ull; acc[i][1] = 0ull; }

    int buf = 0;
    for (int kb = 0; kb < 32; kb++) {
        if (kb < 31) {
            const float* ap = Aptr + (kb + 1) * 8;
            a0 = aok ? *(const float4*)(ap + 0) : z4;
            a1 = aok ? *(const float4*)(ap + 4) : z4;
            b0 = *(const float2*)(Bptr + (size_t)(kb + 1) * 8 * N);
        }
        #pragma unroll
        for (int k = 0; k < 8; k++) {
            float4 av0 = *(const float4*)&As[buf][k][tm * 8];
            float4 av1 = *(const float4*)&As[buf][k][tm * 8 + 4];
            ulonglong2 bv = *(const ulonglong2*)&Bs[buf][k][tn * 2];
            u64 ad;
            ad = dup2(av0.x); fma2(acc[0][0], ad, bv.x); fma2(acc[0][1], ad, bv.y);
            ad = dup2(av0.y); fma2(acc[1][0], ad, bv.x); fma2(acc[1][1], ad, bv.y);
            ad = dup2(av0.z); fma2(acc[2][0], ad, bv.x); fma2(acc[2][1], ad, bv.y);
            ad = dup2(av0.w); fma2(acc[3][0], ad, bv.x); fma2(acc[3][1], ad, bv.y);
            ad = dup2(av1.x); fma2(acc[4][0], ad, bv.x); fma2(acc[4][1], ad, bv.y);
            ad = dup2(av1.y); fma2(acc[5][0], ad, bv.x); fma2(acc[5][1], ad, bv.y);
            ad = dup2(av1.z); fma2(acc[6][0], ad, bv.x); fma2(acc[6][1], ad, bv.y);
            ad = dup2(av1.w); fma2(acc[7][0], ad, bv.x); fma2(acc[7][1], ad, bv.y);
        }
        if (kb < 31) {
            int nb = buf ^ 1;
            As[nb][0][tid] = a0.x; As[nb][1][tid] = a0.y; As[nb][2][tid] = a0.z; As[nb][3][tid] = a0.w;
            As[nb][4][tid] = a1.x; As[nb][5][tid] = a1.y; As[nb][6][tid] = a1.z; As[nb][7][tid] = a1.w;
            *(float2*)&Bs[nb][brow][bcol >> 1] = b0;
            __syncthreads();
            buf = nb;
        }
    }

    #pragma unroll
    for (int i = 0; i < 8; i++) {
        int gr = rowBase + tm * 8 + i;
        if (gr >= M) continue;
        float2 p0 = unpack2(acc[i][0]);
        float2 p1 = unpack2(acc[i][1]);
        *(float4*)&C[(size_t)gr * N + colBase + tn * 4] =
            make_float4(p0.x, p0.y, p1.x, p1.y);
    }
}

// ---------------- tf32 MMA GEMM: BM=64, BN=128, BK=32, 128 threads -----------
struct StA { float4 f00, f01, f10, f11; };
struct StB { float2 g[8]; };

__device__ __forceinline__ void mma_stage_fetchA(StA& st, const float* pa0,
                                                 const float* pa1, bool ok0,
                                                 bool ok1) {
    const float4 z4 = make_float4(0.f, 0.f, 0.f, 0.f);
    st.f00 = ok0 ? *(const float4*)(pa0)     : z4;
    st.f01 = ok0 ? *(const float4*)(pa0 + 4) : z4;
    st.f10 = ok1 ? *(const float4*)(pa1)     : z4;
    st.f11 = ok1 ? *(const float4*)(pa1 + 4) : z4;
}
__device__ __forceinline__ void mma_stage_storeA(unsigned* dst, const StA& st) {
    const float* a00 = &st.f00.x;
    const float* a01 = &st.f01.x;
    const float* a10 = &st.f10.x;
    const float* a11 = &st.f11.x;
    #pragma unroll
    for (int dl = 0; dl < 4; dl++) {
        uint4 v = make_uint4(t32(a00[dl]), t32(a10[dl]), t32(a01[dl]), t32(a11[dl]));
        ((uint4*)dst)[dl] = v;
    }
}
__device__ __forceinline__ void mma_stage_fetchB(StB& st, const float* pb) {
    #pragma unroll
    for (int j = 0; j < 8; j++) st.g[j] = *(const float2*)(pb + j * 256);
}
__device__ __forceinline__ void mma_stage_storeB(unsigned* dst, const StB& st) {
    uint4 v0 = make_uint4(t32(st.g[0].x), t32(st.g[4].x), t32(st.g[1].x), t32(st.g[5].x));
    uint4 v1 = make_uint4(t32(st.g[2].x), t32(st.g[6].x), t32(st.g[3].x), t32(st.g[7].x));
    uint4 v2 = make_uint4(t32(st.g[0].y), t32(st.g[4].y), t32(st.g[1].y), t32(st.g[5].y));
    uint4 v3 = make_uint4(t32(st.g[2].y), t32(st.g[6].y), t32(st.g[3].y), t32(st.g[7].y));
    ((uint4*)dst)[0] = v0; ((uint4*)dst)[1] = v1;
    ((uint4*)dst)[2] = v2; ((uint4*)dst)[3] = v3;
}

template <int OUT_HALF>
__device__ __forceinline__ void mma_gemm_body(const float* __restrict__ A,
                                              const float* __restrict__ B,
                                              void* __restrict__ Cv, int M) {
    __shared__ __align__(16) unsigned smA[2][2048];
    __shared__ __align__(16) unsigned smB[2][4096];
    int tid = threadIdx.x;
    int lane = tid & 31;
    int w = tid >> 5;
    int wm = w & 1, wn = w >> 1;
    int rowBase = blockIdx.y * 64;
    int colBase = blockIdx.x * 128;

    int aRow0 = rowBase + (tid >> 5) * 16 + (tid & 7);
    const float* pa0 = A + (size_t)aRow0 * 256 + ((tid >> 3) & 3) * 8;
    const float* pa1 = pa0 + 8 * 256;
    bool ok0 = aRow0 < M, ok1 = (aRow0 + 8) < M;
    const float* pb = B + (size_t)((tid >> 2) & 3) * 8 * 256 +
                      colBase + (tid >> 4) * 8 + 2 * (tid & 3);

    StA stA; StB stB0, stB1;
    mma_stage_fetchA(stA, pa0, pa1, ok0, ok1);
    mma_stage_fetchB(stB0, pb);
    mma_stage_fetchB(stB1, pb + 64);
    mma_stage_storeA(&smA[0][tid * 16], stA);
    mma_stage_storeB(&smB[0][tid * 16], stB0);
    mma_stage_storeB(&smB[0][2048 + tid * 16], stB1);
    __syncthreads();

    float d[2][8][4];
    #pragma unroll
    for (int t = 0; t < 2; t++)
        #pragma unroll
        for (int u = 0; u < 8; u++)
            #pragma unroll
            for (int c = 0; c < 4; c++) d[t][u][c] = 0.f;

    int buf = 0;
    for (int kb = 0; kb < 8; kb++) {
        if (kb < 7) {
            mma_stage_fetchA(stA, pa0 + (kb + 1) * 32, pa1 + (kb + 1) * 32, ok0, ok1);
            mma_stage_fetchB(stB0, pb + (size_t)(kb + 1) * 32 * 256);
            mma_stage_fetchB(stB1, pb + (size_t)(kb + 1) * 32 * 256 + 64);
        }
        #pragma unroll
        for (int s = 0; s < 4; s++) {
            uint4 fa0 = *(const uint4*)&smA[buf][((2 * wm + 0) * 4 + s) * 128 + lane * 4];
            uint4 fa1 = *(const uint4*)&smA[buf][((2 * wm + 1) * 4 + s) * 128 + lane * 4];
            uint2 fb[8];
            #pragma unroll
            for (int u = 0; u < 8; u++)
                fb[u] = *(const uint2*)&smB[buf][wn * 2048 + (u * 4 + s) * 64 + lane * 2];
            #pragma unroll
            for (int u = 0; u < 8; u++) {
                mma_tf32(d[0][u], fa0, fb[u]);
                mma_tf32(d[1][u], fa1, fb[u]);
            }
        }
        if (kb < 7) {
            int nb = buf ^ 1;
            mma_stage_storeA(&smA[nb][tid * 16], stA);
            mma_stage_storeB(&smB[nb][tid * 16], stB0);
            mma_stage_storeB(&smB[nb][2048 + tid * 16], stB1);
            __syncthreads();
            buf = nb;
        }
    }

    #pragma unroll
    for (int t = 0; t < 2; t++) {
        int r0 = rowBase + (2 * wm + t) * 16 + (lane >> 2);
        int r1 = r0 + 8;
        #pragma unroll
        for (int u = 0; u < 8; u++) {
            int c0 = colBase + wn * 64 + u * 8 + (lane & 3) * 2;
            if (OUT_HALF) {
                __half* C = (__half*)Cv;
                if (r0 < M)
                    *(__half2*)(C + (size_t)r0 * 256 + c0) =
                        __floats2half2_rn(d[t][u][0], d[t][u][1]);
                if (r1 < M)
                    *(__half2*)(C + (size_t)r1 * 256 + c0) =
                        __floats2half2_rn(d[t][u][2], d[t][u][3]);
            } else {
                float* C = (float*)Cv;
                if (r0 < M)
                    *(float2*)(C + (size_t)r0 * 256 + c0) =
                        make_float2(d[t][u][0], d[t][u][1]);
                if (r1 < M)
                    *(float2*)(C + (size_t)r1 * 256 + c0) =
                        make_float2(d[t][u][2], d[t][u][3]);
            }
        }
    }
}

__global__ __launch_bounds__(128, 3) void mma_qp(const float* __restrict__ We1,
                                                 const float* __restrict__ Wa1) {
    int z = blockIdx.z;
    const float* A = (z == 0) ? g_xp : g_xtan;
    const float* B = (z == 0) ? We1 : (z == 1 ? Wa1 : Wa1 + 256 * 256);
    __half* C = (z == 0) ? g_Qh : (z == 1 ? g_P1h : g_P2h);
    mma_gemm_body<1>(A, B, (void*)C, NN);
}

__global__ __launch_bounds__(128, 3) void mma_agg(const float* __restrict__ We2) {
    mma_gemm_body<0>(g_H, We2, (void*)g_agg, NN);
}

// ---------------- node prep: one warp per node --------------------------------
__global__ __launch_bounds__(256) void k_node_xp(const float* __restrict__ bias) {
    int node = blockIdx.x * 8 + (threadIdx.x >> 5);
    int lane = threadIdx.x & 31;
    int base = lane * 8;

    float h[8];
    const float* hp = g_h + (size_t)node * D + base;
    *(float4*)&h[0] = *(const float4*)(hp);
    *(float4*)&h[4] = *(const float4*)(hp + 4);
    if (lane == 0) h[0] = 0.f;

    float acc = 0.f;
    #pragma unroll
    for (int i = 0; i < 8; i++) acc += h[i] * h[i];
    float r1 = warpSum(acc);
    float nn = sqrtf(fmaxf(r1, EPSF));
    float sh_n = sinhf(nn) / nn;
    float xp00 = coshf(nn);
    float xp0[8];
    #pragma unroll
    for (int i = 0; i < 8; i++) xp0[i] = sh_n * h[i];
    if (lane == 0) xp0[0] = xp00;

    float b[8];
    *(float4*)&b[0] = *(const float4*)(bias + base);
    *(float4*)&b[4] = *(const float4*)(bias + base + 4);
    if (lane == 0) b[0] = 0.f;

    acc = 0.f;
    #pragma unroll
    for (int i = 0; i < 8; i++) acc += xp0[i] * b[i];
    float c = warpSum(acc);
    float fac = c / (1.f + xp00);
    float u[8];
    #pragma unroll
    for (int i = 0; i < 8; i++) u[i] = b[i] + fac * xp0[i];
    if (lane == 0) u[0] += fac;

    acc = 0.f;
    #pragma unroll
    for (int i = 0; i < 8; i++) acc += u[i] * u[i];
    float su2 = warpSum(acc);
    float lin = su2 - 2.f * c * c;
    float nu = sqrtf(fmaxf(lin, EPSF));
    float ch = coshf(nu), sh = sinhf(nu) / nu;

    float xp[8];
    #pragma unroll
    for (int i = 0; i < 8; i++) xp[i] = ch * xp0[i] + sh * u[i];
    float* xpp = g_xp + (size_t)node * D + base;
    *(float4*)(xpp)     = *(float4*)&xp[0];
    *(float4*)(xpp + 4) = *(float4*)&xp[4];

    float xpc0 = ch * xp00 + sh * c;
    float x0c = fmaxf(xpc0, 1.f + EPSF);
    float sc = acoshf(x0c) / sqrtf(x0c * x0c - 1.f);
    float xt[8];
    #pragma unroll
    for (int i = 0; i < 8; i++) xt[i] = sc * xp[i];
    if (lane == 0) xt[0] = 0.f;
    float* xtp = g_xtan + (size_t)node * D + base;
    *(float4*)(xtp)     = *(float4*)&xt[0];
    *(float4*)(xtp + 4) = *(float4*)&xt[4];
}

// ---------------- edge kernel: row-sorted, 8 edges per warp ------------------
// Row-side data loads once per row-segment within a chunk; H/S accumulate in
// registers and flush via red.global per segment (~11x fewer atomics than
// per-edge, ~45% less gather traffic, 25k warps of parallelism).
__global__ __launch_bounds__(256) void k_edge_chunk(
    const float* __restrict__ eattr, const int* __restrict__ row,
    const int* __restrict__ col, const float* __restrict__ emask,
    const float* __restrict__ Wa1, const float* __restrict__ ba1,
    const float* __restrict__ Wa2, const float* __restrict__ ba2,
    const float* __restrict__ We1, const float* __restrict__ be1) {
    __shared__ float sw[8][256];
    int tid = threadIdx.x;
    sw[0][tid] = Wa1[512 * D + tid];
    sw[1][tid] = Wa1[513 * D + tid];
    sw[2][tid] = ba1[tid];
    sw[3][tid] = Wa2[tid];
    sw[4][tid] = We1[tid];
    sw[5][tid] = We1[256 * D + tid];
    sw[6][tid] = We1[257 * D + tid];
    sw[7][tid] = be1[tid];
    __syncthreads();

    int chunk = blockIdx.x * 8 + (tid >> 5);
    int k0 = chunk * 8;
    if (k0 >= NE) return;
    int k1 = min(k0 + 8, NE);
    int lane = tid & 31;
    int base = lane * 8;
    float ba2v = ba2[0];

    int cur = -1;
    float xr[8], P1r[8], Qr[8];
    float x0 = 0.f;
    float Hacc[8];
    float Sacc = 0.f;

    for (int k = k0; k < k1; k++) {
        int e = g_eid[k];
        int r = row[e];
        if (r != cur) {
            if (cur >= 0) {
                float* Hp = g_H + (size_t)cur * D + base;
                asm volatile("red.global.add.v4.f32 [%0], {%1,%2,%3,%4};"
                             :: "l"(Hp), "f"(Hacc[0]), "f"(Hacc[1]), "f"(Hacc[2]), "f"(Hacc[3])
                             : "memory");
                asm volatile("red.global.add.v4.f32 [%0], {%1,%2,%3,%4};"
                             :: "l"(Hp + 4), "f"(Hacc[4]), "f"(Hacc[5]), "f"(Hacc[6]), "f"(Hacc[7])
                             : "memory");
                if (lane == 0) atomicAdd(&g_S[cur], Sacc);
            }
            cur = r;
            const float* xrp = g_xp + (size_t)r * D + base;
            *(float4*)&xr[0] = *(const float4*)(xrp);
            *(float4*)&xr[4] = *(const float4*)(xrp + 4);
            ld8h(g_P1h + (size_t)r * D + base, P1r);
            ld8h(g_Qh + (size_t)r * D + base, Qr);
            x0 = __shfl_sync(0xffffffffu, xr[0], 0);
            #pragma unroll
            for (int i = 0; i < 8; i++) Hacc[i] = 0.f;
            Sacc = 0.f;
        }

        int c = col[e];
        const float* xcp = g_xp + (size_t)c * D + base;
        float xc[8];
        *(float4*)&xc[0] = *(const float4*)(xcp);
        *(float4*)&xc[4] = *(const float4*)(xcp + 4);

        float part = 0.f;
        #pragma unroll
        for (int i = 0; i < 8; i++) part -= xr[i] * xc[i];
        part = warpSum(part);

        float y0 = __shfl_sync(0xffffffffu, xc[0], 0);
        float a = fmaxf(part + 2.f * x0 * y0, 1.f + EPSF);
        float dd = acoshf(a);
        float q = sqrtf(a * a - 1.f);
        float s = dd / q;
        float v0 = s * (y0 - a * x0);
        float beta = -v0 / (1.f + x0);
        float alpha = beta - s * a;

        float ea0 = eattr[e];
        float m = emask[e];

        float P2v[8], QC[8];
        ld8h(g_P2h + (size_t)c * D + base, P2v);
        ld8h(g_Qh + (size_t)c * D + base, QC);

        float lp = 0.f;
        #pragma unroll
        for (int i = 0; i < 8; i++) {
            int j = base + i;
            float ha = P1r[i] + P2v[i] + ea0 * sw[0][j] + dd * sw[1][j] + sw[2][j];
            lp += silu_fast(ha) * sw[3][j];
        }
        lp = warpSum(lp);
        float att = m * sigm_fast(lp + ba2v);

        #pragma unroll
        for (int i = 0; i < 8; i++) {
            int j = base + i;
            float hm = alpha * Qr[i] + s * QC[i] + beta * sw[4][j] +
                       ea0 * sw[5][j] + dd * sw[6][j] + sw[7][j];
            Hacc[i] = fmaf(att, silu_fast(hm), Hacc[i]);
        }
        Sacc += att;
    }

    if (cur >= 0) {
        float* Hp = g_H + (size_t)cur * D + base;
        asm volatile("red.global.add.v4.f32 [%0], {%1,%2,%3,%4};"
                     :: "l"(Hp), "f"(Hacc[0]), "f"(Hacc[1]), "f"(Hacc[2]), "f"(Hacc[3])
                     : "memory");
        asm volatile("red.global.add.v4.f32 [%0], {%1,%2,%3,%4};"
                     :: "l"(Hp + 4), "f"(Hacc[4]), "f"(Hacc[5]), "f"(Hacc[6]), "f"(Hacc[7])
                     : "memory");
        if (lane == 0) atomicAdd(&g_S[cur], Sacc);
    }
}

// ---------------- final node kernel: one warp per node -----------------------
__global__ __launch_bounds__(256) void k_final(const float* __restrict__ be2,
                                               const float* __restrict__ lng,
                                               const float* __restrict__ lnb,
                                               float* __restrict__ out) {
    int node = blockIdx.x * 8 + (threadIdx.x >> 5);
    int lane = threadIdx.x & 31;
    int base = lane * 8;

    float Sv = g_S[node];
    float ag[8], be[8], xp[8];
    const float* agp = g_agg + (size_t)node * D + base;
    *(float4*)&ag[0] = *(const float4*)(agp);
    *(float4*)&ag[4] = *(const float4*)(agp + 4);
    *(float4*)&be[0] = *(const float4*)(be2 + base);
    *(float4*)&be[4] = *(const float4*)(be2 + base + 4);
    const float* xpp = g_xp + (size_t)node * D + base;
    *(float4*)&xp[0] = *(const float4*)(xpp);
    *(float4*)&xp[4] = *(const float4*)(xpp + 4);

    #pragma unroll
    for (int i = 0; i < 8; i++) ag[i] += Sv * be[i];
    if (lane == 0) ag[0] = 0.f;

    float xp0 = __shfl_sync(0xffffffffu, xp[0], 0);

    float acc = 0.f;
    #pragma unroll
    for (int i = 0; i < 8; i++) acc += xp[i] * ag[i];
    float cc = warpSum(acc);
    float fac = cc / (1.f + xp0);
    float sup[8];
    #pragma unroll
    for (int i = 0; i < 8; i++) sup[i] = ag[i] + fac * xp[i];
    if (lane == 0) sup[0] += fac;

    acc = 0.f;
    #pragma unroll
    for (int i = 0; i < 8; i++) acc += sup[i] * sup[i];
    float su2 = warpSum(acc);
    float lin = su2 - 2.f * cc * cc;
    float nu = sqrtf(fmaxf(lin, EPSF));
    float ch = coshf(nu), sh = sinhf(nu) / nu;

    float y[8];
    #pragma unroll
    for (int i = 0; i < 8; i++) y[i] = ch * xp[i] + sh * sup[i];
    float y0 = ch * xp0 + sh * cc;

    float y0c = fmaxf(y0, 1.f + EPSF);
    float sc = acoshf(y0c) / sqrtf(y0c * y0c - 1.f);
    float xo[8];
    #pragma unroll
    for (int i = 0; i < 8; i++) xo[i] = sc * y[i];
    if (lane == 0) xo[0] = 0.f;

    acc = 0.f;
    #pragma unroll
    for (int i = 0; i < 8; i++) acc += xo[i];
    float mean = warpSum(acc) * (1.f / 255.f);
    float dev[8];
    #pragma unroll
    for (int i = 0; i < 8; i++) dev[i] = xo[i] - mean;
    if (lane == 0) dev[0] = 0.f;
    acc = 0.f;
    #pragma unroll
    for (int i = 0; i < 8; i++) acc += dev[i] * dev[i];
    float var = warpSum(acc) * (1.f / 255.f);
    float inv = 1.f / sqrtf(var + 1e-5f);

    float sl[8];
    #pragma unroll
    for (int i = 0; i < 8; i++) {
        int j = base + i;
        float lg = (j > 0) ? lng[j - 1] : 0.f;
        float lb = (j > 0) ? lnb[j - 1] : 0.f;
        float ln = dev[i] * inv * lg + lb;
        sl[i] = siluf(ln);
    }
    if (lane == 0) sl[0] = 0.f;

    acc = 0.f;
    #pragma unroll
    for (int i = 0; i < 8; i++) acc += sl[i] * sl[i];
    float n2 = warpSum(acc);
    float nn = sqrtf(fmaxf(n2, EPSF));
    float shn = sinhf(nn) / nn;

    float o[8];
    #pragma unroll
    for (int i = 0; i < 8; i++) o[i] = shn * sl[i];
    if (lane == 0) o[0] = coshf(nn);
    float* op = out + (size_t)node * D + base;
    *(float4*)(op)     = *(float4*)&o[0];
    *(float4*)(op + 4) = *(float4*)&o[4];
}

// ---------------- launch -----------------------------------------------------
extern "C" void kernel_launch(void* const* d_in, const int* in_sizes, int n_in,
                              void* d_out, int out_size) {
    const float* x     = (const float*)d_in[0];
    const float* eattr = (const float*)d_in[1];
    const int*   row   = (const int*)d_in[2];
    const int*   col   = (const int*)d_in[3];
    const float* emask = (const float*)d_in[5];
    const float* W_lin = (const float*)d_in[6];
    const float* bias  = (const float*)d_in[7];
    const float* W_e1  = (const float*)d_in[8];
    const float* b_e1  = (const float*)d_in[9];
    const float* W_e2  = (const float*)d_in[10];
    const float* b_e2  = (const float*)d_in[11];
    const float* W_a1  = (const float*)d_in[12];
    const float* b_a1  = (const float*)d_in[13];
    const float* W_a2  = (const float*)d_in[14];
    const float* b_a2  = (const float*)d_in[15];
    const float* ln_g  = (const float*)d_in[16];
    const float* ln_b  = (const float*)d_in[17];
    float* out = (float*)d_out;

    float *pu, *ph;
    cudaGetSymbolAddress((void**)&pu, g_u);
    cudaGetSymbolAddress((void**)&ph, g_h);

    dim3 gElem((NN * D + 255) / 256);
    dim3 gEdge((NE + 255) / 256);
    dim3 gGemm32(8, (NN + 127) / 128);
    dim3 gMmaQP(2, (NN + 63) / 64, 3);
    dim3 gMmaAgg(2, (NN + 63) / 64);
    int nChunks = (NE + 7) / 8;
    int gChunk = (nChunks + 7) / 8;

    k_logmap0<<<gElem, 256>>>(x);                       // zeroes H, S, cnt
    k_hist<<<gEdge, 256>>>(row);
    k_scan<<<1, 256>>>();
    k_scatter<<<gEdge, 256>>>(row);
    sgemm32<<<gGemm32, 128>>>(pu, W_lin, ph, NN);       // fp32-exact
    k_node_xp<<<NN / 8, 256>>>(bias);
    mma_qp<<<gMmaQP, 128>>>(W_e1, W_a1);                // tf32 tensor cores
    k_edge_chunk<<<gChunk, 256>>>(eattr, row, col, emask, W_a1, b_a1, W_a2, b_a2, W_e1, b_e1);
    mma_agg<<<gMmaAgg, 128>>>(W_e2);                    // tf32 tensor cores
    k_final<<<NN / 8, 256>>>(b_e2, ln_g, ln_b, out);
}

// round 11
// speedup vs baseline: 1.0954x; 1.0557x over previous
#include <cuda_runtime.h>
#include <cuda_fp16.h>
#include <math.h>

#define NN 10000
#define NE 200000
#define D  256
#define EPSF 1e-6f

typedef unsigned long long u64;

// ---------------- scratch (device globals: no allocation allowed) ----------
__device__ __align__(128) float g_u[NN * D];
__device__ __align__(128) float g_h[NN * D];
__device__ __align__(128) float g_xp[NN * D];
__device__ __align__(128) __half g_xph[NN * D];   // fp16 copy of xp for edge gathers
__device__ __align__(128) float g_xtan[NN * D];
__device__ __align__(128) __half g_Qh[NN * D];
__device__ __align__(128) __half g_P1h[NN * D];
__device__ __align__(128) __half g_P2h[NN * D];
__device__ __align__(128) float g_H[NN * D];
__device__ __align__(128) float g_agg[NN * D];
__device__ __align__(128) float g_S[NN];

// ---------------- packed f32x2 helpers (SIMT GEMM) ---------------------------
__device__ __forceinline__ u64 dup2(float v) {
    u64 r; asm("mov.b64 %0,{%1,%1};" : "=l"(r) : "f"(v)); return r;
}
__device__ __forceinline__ void fma2(u64& c, u64 a, u64 b) {
    asm("fma.rn.f32x2 %0,%1,%2,%0;" : "+l"(c) : "l"(a), "l"(b));
}
__device__ __forceinline__ float2 unpack2(u64 v) {
    float2 f; asm("mov.b64 {%0,%1},%2;" : "=f"(f.x), "=f"(f.y) : "l"(v)); return f;
}

// ---------------- tf32 helpers ------------------------------------------------
__device__ __forceinline__ unsigned t32(float f) {
    unsigned r; asm("cvt.rna.tf32.f32 %0,%1;" : "=r"(r) : "f"(f)); return r;
}
__device__ __forceinline__ void mma_tf32(float* d, const uint4& a, const uint2& b) {
    asm volatile(
        "mma.sync.aligned.m16n8k8.row.col.f32.tf32.tf32.f32 "
        "{%0,%1,%2,%3},{%4,%5,%6,%7},{%8,%9},{%0,%1,%2,%3};"
        : "+f"(d[0]), "+f"(d[1]), "+f"(d[2]), "+f"(d[3])
        : "r"(a.x), "r"(a.y), "r"(a.z), "r"(a.w), "r"(b.x), "r"(b.y));
}

// ---------------- misc helpers ------------------------------------------------
__device__ __forceinline__ float warpSum(float v) {
    #pragma unroll
    for (int o = 16; o > 0; o >>= 1) v += __shfl_xor_sync(0xffffffffu, v, o);
    return v;
}
__device__ __forceinline__ float siluf(float x) { return x / (1.f + expf(-x)); }
__device__ __forceinline__ float tanh_ap(float x) {
    float y; asm("tanh.approx.f32 %0,%1;" : "=f"(y) : "f"(x)); return y;
}
__device__ __forceinline__ float sigm_fast(float x) {
    return fmaf(0.5f, tanh_ap(0.5f * x), 0.5f);
}
__device__ __forceinline__ float silu_fast(float x) { return x * sigm_fast(x); }

__device__ __forceinline__ void ld8h(const __half* p, float* o) {
    uint4 v = *(const uint4*)p;
    __half2 h0 = *(__half2*)&v.x, h1 = *(__half2*)&v.y,
            h2 = *(__half2*)&v.z, h3 = *(__half2*)&v.w;
    float2 f;
    f = __half22float2(h0); o[0] = f.x; o[1] = f.y;
    f = __half22float2(h1); o[2] = f.x; o[3] = f.y;
    f = __half22float2(h2); o[4] = f.x; o[5] = f.y;
    f = __half22float2(h3); o[6] = f.x; o[7] = f.y;
}

// ---------------- kernel 1: u = logmap0(x), plus zero accumulators ----------
__global__ void k_logmap0(const float* __restrict__ x) {
    int idx = blockIdx.x * blockDim.x + threadIdx.x;
    if (idx >= NN * D) return;
    int n = idx >> 8;
    int j = idx & (D - 1);
    float x0 = fmaxf(x[n * D], 1.f + EPSF);
    float outv;
    if (j == 0) {
        outv = 0.f;
    } else {
        float dd = acoshf(x0);
        float sc = dd / sqrtf(x0 * x0 - 1.f);
        outv = sc * x[idx];
    }
    g_u[idx] = outv;
    g_H[idx] = 0.f;
    if (idx < NN) g_S[idx] = 0.f;
}

// ---------------- SIMT SGEMM (fp32-exact path for W_lin) --------------------
__global__ __launch_bounds__(128) void sgemm32(const float* __restrict__ A,
                                               const float* __restrict__ B,
                                               float* __restrict__ C, int M) {
    __shared__ float As[2][8][128];
    __shared__ u64   Bs[2][8][16];
    const int K = 256, N = 256;
    int tid = threadIdx.x;
    int tm = tid >> 3;
    int tn = tid & 7;
    int rowBase = blockIdx.y * 128;
    int colBase = blockIdx.x * 32;

    int arow = rowBase + tid;
    bool aok = arow < M;
    const float* Aptr = A + (size_t)arow * K;
    int brow = tid >> 4;
    int bcol = (tid & 15) * 2;
    const float* Bptr = B + (size_t)brow * N + colBase + bcol;

    const float4 z4 = make_float4(0.f, 0.f, 0.f, 0.f);

    float4 a0 = aok ? *(const float4*)(Aptr + 0) : z4;
    float4 a1 = aok ? *(const float4*)(Aptr + 4) : z4;
    float2 b0 = *(const float2*)(Bptr);
    As[0][0][tid] = a0.x; As[0][1][tid] = a0.y; As[0][2][tid] = a0.z; As[0][3][tid] = a0.w;
    As[0][4][tid] = a1.x; As[0][5][tid] = a1.y; As[0][6][tid] = a1.z; As[0][7][tid] = a1.w;
    *(float2*)&Bs[0][brow][bcol >> 1] = b0;
    __syncthreads();

    u64 acc[8][2];
    #pragma unroll
    for (int i = 0; i < 8; i++) { acc[i][0] = 0ull; acc[i][1] = 0ull; }

    int buf = 0;
    for (int kb = 0; kb < 32; kb++) {
        if (kb < 31) {
            const float* ap = Aptr + (kb + 1) * 8;
            a0 = aok ? *(const float4*)(ap + 0) : z4;
            a1 = aok ? *(const float4*)(ap + 4) : z4;
            b0 = *(const float2*)(Bptr + (size_t)(kb + 1) * 8 * N);
        }
        #pragma unroll
        for (int k = 0; k < 8; k++) {
            float4 av0 = *(const float4*)&As[buf][k][tm * 8];
            float4 av1 = *(const float4*)&As[buf][k][tm * 8 + 4];
            ulonglong2 bv = *(const ulonglong2*)&Bs[buf][k][tn * 2];
            u64 ad;
            ad = dup2(av0.x); fma2(acc[0][0], ad, bv.x); fma2(acc[0][1], ad, bv.y);
            ad = dup2(av0.y); fma2(acc[1][0], ad, bv.x); fma2(acc[1][1], ad, bv.y);
            ad = dup2(av0.z); fma2(acc[2][0], ad, bv.x); fma2(acc[2][1], ad, bv.y);
            ad = dup2(av0.w); fma2(acc[3][0], ad, bv.x); fma2(acc[3][1], ad, bv.y);
            ad = dup2(av1.x); fma2(acc[4][0], ad, bv.x); fma2(acc[4][1], ad, bv.y);
            ad = dup2(av1.y); fma2(acc[5][0], ad, bv.x); fma2(acc[5][1], ad, bv.y);
            ad = dup2(av1.z); fma2(acc[6][0], ad, bv.x); fma2(acc[6][1], ad, bv.y);
            ad = dup2(av1.w); fma2(acc[7][0], ad, bv.x); fma2(acc[7][1], ad, bv.y);
        }
        if (kb < 31) {
            int nb = buf ^ 1;
            As[nb][0][tid] = a0.x; As[nb][1][tid] = a0.y; As[nb][2][tid] = a0.z; As[nb][3][tid] = a0.w;
            As[nb][4][tid] = a1.x; As[nb][5][tid] = a1.y; As[nb][6][tid] = a1.z; As[nb][7][tid] = a1.w;
            *(float2*)&Bs[nb][brow][bcol >> 1] = b0;
            __syncthreads();
            buf = nb;
        }
    }

    #pragma unroll
    for (int i = 0; i < 8; i++) {
        int gr = rowBase + tm * 8 + i;
        if (gr >= M) continue;
        float2 p0 = unpack2(acc[i][0]);
        float2 p1 = unpack2(acc[i][1]);
        *(float4*)&C[(size_t)gr * N + colBase + tn * 4] =
            make_float4(p0.x, p0.y, p1.x, p1.y);
    }
}

// ---------------- tf32 MMA GEMM: BM=64, BN=128, BK=32, 128 threads -----------
struct StA { float4 f00, f01, f10, f11; };
struct StB { float2 g[8]; };

__device__ __forceinline__ void mma_stage_fetchA(StA& st, const float* pa0,
                                                 const float* pa1, bool ok0,
                                                 bool ok1) {
    const float4 z4 = make_float4(0.f, 0.f, 0.f, 0.f);
    st.f00 = ok0 ? *(const float4*)(pa0)     : z4;
    st.f01 = ok0 ? *(const float4*)(pa0 + 4) : z4;
    st.f10 = ok1 ? *(const float4*)(pa1)     : z4;
    st.f11 = ok1 ? *(const float4*)(pa1 + 4) : z4;
}
__device__ __forceinline__ void mma_stage_storeA(unsigned* dst, const StA& st) {
    const float* a00 = &st.f00.x;
    const float* a01 = &st.f01.x;
    const float* a10 = &st.f10.x;
    const float* a11 = &st.f11.x;
    #pragma unroll
    for (int dl = 0; dl < 4; dl++) {
        uint4 v = make_uint4(t32(a00[dl]), t32(a10[dl]), t32(a01[dl]), t32(a11[dl]));
        ((uint4*)dst)[dl] = v;
    }
}
__device__ __forceinline__ void mma_stage_fetchB(StB& st, const float* pb) {
    #pragma unroll
    for (int j = 0; j < 8; j++) st.g[j] = *(const float2*)(pb + j * 256);
}
__device__ __forceinline__ void mma_stage_storeB(unsigned* dst, const StB& st) {
    uint4 v0 = make_uint4(t32(st.g[0].x), t32(st.g[4].x), t32(st.g[1].x), t32(st.g[5].x));
    uint4 v1 = make_uint4(t32(st.g[2].x), t32(st.g[6].x), t32(st.g[3].x), t32(st.g[7].x));
    uint4 v2 = make_uint4(t32(st.g[0].y), t32(st.g[4].y), t32(st.g[1].y), t32(st.g[5].y));
    uint4 v3 = make_uint4(t32(st.g[2].y), t32(st.g[6].y), t32(st.g[3].y), t32(st.g[7].y));
    ((uint4*)dst)[0] = v0; ((uint4*)dst)[1] = v1;
    ((uint4*)dst)[2] = v2; ((uint4*)dst)[3] = v3;
}

template <int OUT_HALF>
__device__ __forceinline__ void mma_gemm_body(const float* __restrict__ A,
                                              const float* __restrict__ B,
                                              void* __restrict__ Cv, int M) {
    __shared__ __align__(16) unsigned smA[2][2048];
    __shared__ __align__(16) unsigned smB[2][4096];
    int tid = threadIdx.x;
    int lane = tid & 31;
    int w = tid >> 5;
    int wm = w & 1, wn = w >> 1;
    int rowBase = blockIdx.y * 64;
    int colBase = blockIdx.x * 128;

    int aRow0 = rowBase + (tid >> 5) * 16 + (tid & 7);
    const float* pa0 = A + (size_t)aRow0 * 256 + ((tid >> 3) & 3) * 8;
    const float* pa1 = pa0 + 8 * 256;
    bool ok0 = aRow0 < M, ok1 = (aRow0 + 8) < M;
    const float* pb = B + (size_t)((tid >> 2) & 3) * 8 * 256 +
                      colBase + (tid >> 4) * 8 + 2 * (tid & 3);

    StA stA; StB stB0, stB1;
    mma_stage_fetchA(stA, pa0, pa1, ok0, ok1);
    mma_stage_fetchB(stB0, pb);
    mma_stage_fetchB(stB1, pb + 64);
    mma_stage_storeA(&smA[0][tid * 16], stA);
    mma_stage_storeB(&smB[0][tid * 16], stB0);
    mma_stage_storeB(&smB[0][2048 + tid * 16], stB1);
    __syncthreads();

    float d[2][8][4];
    #pragma unroll
    for (int t = 0; t < 2; t++)
        #pragma unroll
        for (int u = 0; u < 8; u++)
            #pragma unroll
            for (int c = 0; c < 4; c++) d[t][u][c] = 0.f;

    int buf = 0;
    for (int kb = 0; kb < 8; kb++) {
        if (kb < 7) {
            mma_stage_fetchA(stA, pa0 + (kb + 1) * 32, pa1 + (kb + 1) * 32, ok0, ok1);
            mma_stage_fetchB(stB0, pb + (size_t)(kb + 1) * 32 * 256);
            mma_stage_fetchB(stB1, pb + (size_t)(kb + 1) * 32 * 256 + 64);
        }
        #pragma unroll
        for (int s = 0; s < 4; s++) {
            uint4 fa0 = *(const uint4*)&smA[buf][((2 * wm + 0) * 4 + s) * 128 + lane * 4];
            uint4 fa1 = *(const uint4*)&smA[buf][((2 * wm + 1) * 4 + s) * 128 + lane * 4];
            uint2 fb[8];
            #pragma unroll
            for (int u = 0; u < 8; u++)
                fb[u] = *(const uint2*)&smB[buf][wn * 2048 + (u * 4 + s) * 64 + lane * 2];
            #pragma unroll
            for (int u = 0; u < 8; u++) {
                mma_tf32(d[0][u], fa0, fb[u]);
                mma_tf32(d[1][u], fa1, fb[u]);
            }
        }
        if (kb < 7) {
            int nb = buf ^ 1;
            mma_stage_storeA(&smA[nb][tid * 16], stA);
            mma_stage_storeB(&smB[nb][tid * 16], stB0);
            mma_stage_storeB(&smB[nb][2048 + tid * 16], stB1);
            __syncthreads();
            buf = nb;
        }
    }

    #pragma unroll
    for (int t = 0; t < 2; t++) {
        int r0 = rowBase + (2 * wm + t) * 16 + (lane >> 2);
        int r1 = r0 + 8;
        #pragma unroll
        for (int u = 0; u < 8; u++) {
            int c0 = colBase + wn * 64 + u * 8 + (lane & 3) * 2;
            if (OUT_HALF) {
                __half* C = (__half*)Cv;
                if (r0 < M)
                    *(__half2*)(C + (size_t)r0 * 256 + c0) =
                        __floats2half2_rn(d[t][u][0], d[t][u][1]);
                if (r1 < M)
                    *(__half2*)(C + (size_t)r1 * 256 + c0) =
                        __floats2half2_rn(d[t][u][2], d[t][u][3]);
            } else {
                float* C = (float*)Cv;
                if (r0 < M)
                    *(float2*)(C + (size_t)r0 * 256 + c0) =
                        make_float2(d[t][u][0], d[t][u][1]);
                if (r1 < M)
                    *(float2*)(C + (size_t)r1 * 256 + c0) =
                        make_float2(d[t][u][2], d[t][u][3]);
            }
        }
    }
}

__global__ __launch_bounds__(128, 3) void mma_qp(const float* __restrict__ We1,
                                                 const float* __restrict__ Wa1) {
    int z = blockIdx.z;
    const float* A = (z == 0) ? g_xp : g_xtan;
    const float* B = (z == 0) ? We1 : (z == 1 ? Wa1 : Wa1 + 256 * 256);
    __half* C = (z == 0) ? g_Qh : (z == 1 ? g_P1h : g_P2h);
    mma_gemm_body<1>(A, B, (void*)C, NN);
}

__global__ __launch_bounds__(128, 3) void mma_agg(const float* __restrict__ We2) {
    mma_gemm_body<0>(g_H, We2, (void*)g_agg, NN);
}

// ---------------- node prep: one warp per node --------------------------------
__global__ __launch_bounds__(256) void k_node_xp(const float* __restrict__ bias) {
    int node = blockIdx.x * 8 + (threadIdx.x >> 5);
    int lane = threadIdx.x & 31;
    int base = lane * 8;

    float h[8];
    const float* hp = g_h + (size_t)node * D + base;
    *(float4*)&h[0] = *(const float4*)(hp);
    *(float4*)&h[4] = *(const float4*)(hp + 4);
    if (lane == 0) h[0] = 0.f;

    float acc = 0.f;
    #pragma unroll
    for (int i = 0; i < 8; i++) acc += h[i] * h[i];
    float r1 = warpSum(acc);
    float nn = sqrtf(fmaxf(r1, EPSF));
    float sh_n = sinhf(nn) / nn;
    float xp00 = coshf(nn);
    float xp0[8];
    #pragma unroll
    for (int i = 0; i < 8; i++) xp0[i] = sh_n * h[i];
    if (lane == 0) xp0[0] = xp00;

    float b[8];
    *(float4*)&b[0] = *(const float4*)(bias + base);
    *(float4*)&b[4] = *(const float4*)(bias + base + 4);
    if (lane == 0) b[0] = 0.f;

    acc = 0.f;
    #pragma unroll
    for (int i = 0; i < 8; i++) acc += xp0[i] * b[i];
    float c = warpSum(acc);
    float fac = c / (1.f + xp00);
    float u[8];
    #pragma unroll
    for (int i = 0; i < 8; i++) u[i] = b[i] + fac * xp0[i];
    if (lane == 0) u[0] += fac;

    acc = 0.f;
    #pragma unroll
    for (int i = 0; i < 8; i++) acc += u[i] * u[i];
    float su2 = warpSum(acc);
    float lin = su2 - 2.f * c * c;
    float nu = sqrtf(fmaxf(lin, EPSF));
    float ch = coshf(nu), sh = sinhf(nu) / nu;

    float xp[8];
    #pragma unroll
    for (int i = 0; i < 8; i++) xp[i] = ch * xp0[i] + sh * u[i];
    float* xpp = g_xp + (size_t)node * D + base;
    *(float4*)(xpp)     = *(float4*)&xp[0];
    *(float4*)(xpp + 4) = *(float4*)&xp[4];

    // fp16 copy for edge-kernel gathers
    {
        __half2 q0 = __floats2half2_rn(xp[0], xp[1]);
        __half2 q1 = __floats2half2_rn(xp[2], xp[3]);
        __half2 q2 = __floats2half2_rn(xp[4], xp[5]);
        __half2 q3 = __floats2half2_rn(xp[6], xp[7]);
        uint4 o;
        o.x = *(unsigned*)&q0; o.y = *(unsigned*)&q1;
        o.z = *(unsigned*)&q2; o.w = *(unsigned*)&q3;
        *(uint4*)(g_xph + (size_t)node * D + base) = o;
    }

    float xpc0 = ch * xp00 + sh * c;
    float x0c = fmaxf(xpc0, 1.f + EPSF);
    float sc = acoshf(x0c) / sqrtf(x0c * x0c - 1.f);
    float xt[8];
    #pragma unroll
    for (int i = 0; i < 8; i++) xt[i] = sc * xp[i];
    if (lane == 0) xt[0] = 0.f;
    float* xtp = g_xtan + (size_t)node * D + base;
    *(float4*)(xtp)     = *(float4*)&xt[0];
    *(float4*)(xtp + 4) = *(float4*)&xt[4];
}

// ---------------- edge kernel: 32 edges per block (4 per warp), fp16 gathers --
__global__ __launch_bounds__(256) void k_edge(
    const float* __restrict__ eattr, const int* __restrict__ row,
    const int* __restrict__ col, const float* __restrict__ emask,
    const float* __restrict__ Wa1, const float* __restrict__ ba1,
    const float* __restrict__ Wa2, const float* __restrict__ ba2,
    const float* __restrict__ We1, const float* __restrict__ be1) {
    __shared__ float sw[8][256];
    int tid = threadIdx.x;
    sw[0][tid] = Wa1[512 * D + tid];
    sw[1][tid] = Wa1[513 * D + tid];
    sw[2][tid] = ba1[tid];
    sw[3][tid] = Wa2[tid];
    sw[4][tid] = We1[tid];
    sw[5][tid] = We1[256 * D + tid];
    sw[6][tid] = We1[257 * D + tid];
    sw[7][tid] = be1[tid];
    __syncthreads();

    int warp = tid >> 5;
    int lane = tid & 31;
    int base = lane * 8;
    float ba2v = ba2[0];

    #pragma unroll
    for (int it = 0; it < 4; it++) {
        int e = blockIdx.x * 32 + it * 8 + warp;

        int r = row[e];
        int c = col[e];

        float xr[8], xc[8];
        ld8h(g_xph + (size_t)r * D + base, xr);
        ld8h(g_xph + (size_t)c * D + base, xc);

        float part = 0.f;
        #pragma unroll
        for (int i = 0; i < 8; i++) part -= xr[i] * xc[i];
        part = warpSum(part);

        float x0 = __shfl_sync(0xffffffffu, xr[0], 0);
        float y0 = __shfl_sync(0xffffffffu, xc[0], 0);

        float a = fmaxf(part + 2.f * x0 * y0, 1.f + EPSF);
        float dd = acoshf(a);
        float q = sqrtf(a * a - 1.f);
        float s = dd / q;
        float v0 = s * (y0 - a * x0);
        float beta = -v0 / (1.f + x0);
        float alpha = beta - s * a;

        float ea0 = eattr[e];
        float m = emask[e];

        float P1v[8], P2v[8];
        ld8h(g_P1h + (size_t)r * D + base, P1v);
        ld8h(g_P2h + (size_t)c * D + base, P2v);

        float lp = 0.f;
        #pragma unroll
        for (int i = 0; i < 8; i++) {
            int j = base + i;
            float ha = P1v[i] + P2v[i] + ea0 * sw[0][j] + dd * sw[1][j] + sw[2][j];
            lp += silu_fast(ha) * sw[3][j];
        }
        lp = warpSum(lp);
        float att = m * sigm_fast(lp + ba2v);

        float QR[8], QC[8];
        ld8h(g_Qh + (size_t)r * D + base, QR);
        ld8h(g_Qh + (size_t)c * D + base, QC);

        float val[8];
        #pragma unroll
        for (int i = 0; i < 8; i++) {
            int j = base + i;
            float hm = alpha * QR[i] + s * QC[i] + beta * sw[4][j] +
                       ea0 * sw[5][j] + dd * sw[6][j] + sw[7][j];
            val[i] = att * silu_fast(hm);
        }

        float* Hr = g_H + (size_t)r * D + base;
        asm volatile("red.global.add.v4.f32 [%0], {%1,%2,%3,%4};"
                     :: "l"(Hr), "f"(val[0]), "f"(val[1]), "f"(val[2]), "f"(val[3])
                     : "memory");
        asm volatile("red.global.add.v4.f32 [%0], {%1,%2,%3,%4};"
                     :: "l"(Hr + 4), "f"(val[4]), "f"(val[5]), "f"(val[6]), "f"(val[7])
                     : "memory");
        if (lane == 0) atomicAdd(&g_S[r], att);
    }
}

// ---------------- final node kernel: one warp per node -----------------------
__global__ __launch_bounds__(256) void k_final(const float* __restrict__ be2,
                                               const float* __restrict__ lng,
                                               const float* __restrict__ lnb,
                                               float* __restrict__ out) {
    int node = blockIdx.x * 8 + (threadIdx.x >> 5);
    int lane = threadIdx.x & 31;
    int base = lane * 8;

    float Sv = g_S[node];
    float ag[8], be[8], xp[8];
    const float* agp = g_agg + (size_t)node * D + base;
    *(float4*)&ag[0] = *(const float4*)(agp);
    *(float4*)&ag[4] = *(const float4*)(agp + 4);
    *(float4*)&be[0] = *(const float4*)(be2 + base);
    *(float4*)&be[4] = *(const float4*)(be2 + base + 4);
    const float* xpp = g_xp + (size_t)node * D + base;
    *(float4*)&xp[0] = *(const float4*)(xpp);
    *(float4*)&xp[4] = *(const float4*)(xpp + 4);

    #pragma unroll
    for (int i = 0; i < 8; i++) ag[i] += Sv * be[i];
    if (lane == 0) ag[0] = 0.f;

    float xp0 = __shfl_sync(0xffffffffu, xp[0], 0);

    float acc = 0.f;
    #pragma unroll
    for (int i = 0; i < 8; i++) acc += xp[i] * ag[i];
    float cc = warpSum(acc);
    float fac = cc / (1.f + xp0);
    float sup[8];
    #pragma unroll
    for (int i = 0; i < 8; i++) sup[i] = ag[i] + fac * xp[i];
    if (lane == 0) sup[0] += fac;

    acc = 0.f;
    #pragma unroll
    for (int i = 0; i < 8; i++) acc += sup[i] * sup[i];
    float su2 = warpSum(acc);
    float lin = su2 - 2.f * cc * cc;
    float nu = sqrtf(fmaxf(lin, EPSF));
    float ch = coshf(nu), sh = sinhf(nu) / nu;

    float y[8];
    #pragma unroll
    for (int i = 0; i < 8; i++) y[i] = ch * xp[i] + sh * sup[i];
    float y0 = ch * xp0 + sh * cc;

    float y0c = fmaxf(y0, 1.f + EPSF);
    float sc = acoshf(y0c) / sqrtf(y0c * y0c - 1.f);
    float xo[8];
    #pragma unroll
    for (int i = 0; i < 8; i++) xo[i] = sc * y[i];
    if (lane == 0) xo[0] = 0.f;

    acc = 0.f;
    #pragma unroll
    for (int i = 0; i < 8; i++) acc += xo[i];
    float mean = warpSum(acc) * (1.f / 255.f);
    float dev[8];
    #pragma unroll
    for (int i = 0; i < 8; i++) dev[i] = xo[i] - mean;
    if (lane == 0) dev[0] = 0.f;
    acc = 0.f;
    #pragma unroll
    for (int i = 0; i < 8; i++) acc += dev[i] * dev[i];
    float var = warpSum(acc) * (1.f / 255.f);
    float inv = 1.f / sqrtf(var + 1e-5f);

    float sl[8];
    #pragma unroll
    for (int i = 0; i < 8; i++) {
        int j = base + i;
        float lg = (j > 0) ? lng[j - 1] : 0.f;
        float lb = (j > 0) ? lnb[j - 1] : 0.f;
        float ln = dev[i] * inv * lg + lb;
        sl[i] = siluf(ln);
    }
    if (lane == 0) sl[0] = 0.f;

    acc = 0.f;
    #pragma unroll
    for (int i = 0; i < 8; i++) acc += sl[i] * sl[i];
    float n2 = warpSum(acc);
    float nn = sqrtf(fmaxf(n2, EPSF));
    float shn = sinhf(nn) / nn;

    float o[8];
    #pragma unroll
    for (int i = 0; i < 8; i++) o[i] = shn * sl[i];
    if (lane == 0) o[0] = coshf(nn);
    float* op = out + (size_t)node * D + base;
    *(float4*)(op)     = *(float4*)&o[0];
    *(float4*)(op + 4) = *(float4*)&o[4];
}

// ---------------- launch -----------------------------------------------------
extern "C" void kernel_launch(void* const* d_in, const int* in_sizes, int n_in,
                              void* d_out, int out_size) {
    const float* x     = (const float*)d_in[0];
    const float* eattr = (const float*)d_in[1];
    const int*   row   = (const int*)d_in[2];
    const int*   col   = (const int*)d_in[3];
    const float* emask = (const float*)d_in[5];
    const float* W_lin = (const float*)d_in[6];
    const float* bias  = (const float*)d_in[7];
    const float* W_e1  = (const float*)d_in[8];
    const float* b_e1  = (const float*)d_in[9];
    const float* W_e2  = (const float*)d_in[10];
    const float* b_e2  = (const float*)d_in[11];
    const float* W_a1  = (const float*)d_in[12];
    const float* b_a1  = (const float*)d_in[13];
    const float* W_a2  = (const float*)d_in[14];
    const float* b_a2  = (const float*)d_in[15];
    const float* ln_g  = (const float*)d_in[16];
    const float* ln_b  = (const float*)d_in[17];
    float* out = (float*)d_out;

    float *pu, *ph;
    cudaGetSymbolAddress((void**)&pu, g_u);
    cudaGetSymbolAddress((void**)&ph, g_h);

    dim3 gElem((NN * D + 255) / 256);
    dim3 gGemm32(8, (NN + 127) / 128);
    dim3 gMmaQP(2, (NN + 63) / 64, 3);
    dim3 gMmaAgg(2, (NN + 63) / 64);

    k_logmap0<<<gElem, 256>>>(x);                       // also zeroes H, S
    sgemm32<<<gGemm32, 128>>>(pu, W_lin, ph, NN);       // fp32-exact
    k_node_xp<<<NN / 8, 256>>>(bias);
    mma_qp<<<gMmaQP, 128>>>(W_e1, W_a1);                // tf32 tensor cores
    k_edge<<<NE / 32, 256>>>(eattr, row, col, emask, W_a1, b_a1, W_a2, b_a2, W_e1, b_e1);
    mma_agg<<<gMmaAgg, 128>>>(W_e2);                    // tf32 tensor cores
    k_final<<<NN / 8, 256>>>(b_e2, ln_g, ln_b, out);
}

// round 12
// speedup vs baseline: 1.1637x; 1.0624x over previous
#include <cuda_runtime.h>
#include <cuda_fp16.h>
#include <math.h>

#define NN 10000
#define NE 200000
#define D  256
#define EPSF 1e-6f

typedef unsigned long long u64;

// ---------------- scratch (device globals: no allocation allowed) ----------
__device__ __align__(128) float g_u[NN * D];
__device__ __align__(128) float g_h[NN * D];
__device__ __align__(128) float g_xp[NN * D];
__device__ __align__(128) __half g_xph[NN * D];   // fp16 copy of xp for edge gathers
__device__ __align__(128) float g_xtan[NN * D];
__device__ __align__(128) __half g_Qh[NN * D];
__device__ __align__(128) __half g_P1h[NN * D];
__device__ __align__(128) __half g_P2h[NN * D];
__device__ __align__(128) float g_H[NN * D];
__device__ __align__(128) float g_agg[NN * D];
__device__ __align__(128) float g_S[NN];

// ---------------- tf32 helpers ------------------------------------------------
__device__ __forceinline__ unsigned t32(float f) {
    unsigned r; asm("cvt.rna.tf32.f32 %0,%1;" : "=r"(r) : "f"(f)); return r;
}
__device__ __forceinline__ void mma_tf32(float* d, const uint4& a, const uint2& b) {
    asm volatile(
        "mma.sync.aligned.m16n8k8.row.col.f32.tf32.tf32.f32 "
        "{%0,%1,%2,%3},{%4,%5,%6,%7},{%8,%9},{%0,%1,%2,%3};"
        : "+f"(d[0]), "+f"(d[1]), "+f"(d[2]), "+f"(d[3])
        : "r"(a.x), "r"(a.y), "r"(a.z), "r"(a.w), "r"(b.x), "r"(b.y));
}

// ---------------- misc helpers ------------------------------------------------
__device__ __forceinline__ float warpSum(float v) {
    #pragma unroll
    for (int o = 16; o > 0; o >>= 1) v += __shfl_xor_sync(0xffffffffu, v, o);
    return v;
}
__device__ __forceinline__ float siluf(float x) { return x / (1.f + expf(-x)); }
__device__ __forceinline__ float tanh_ap(float x) {
    float y; asm("tanh.approx.f32 %0,%1;" : "=f"(y) : "f"(x)); return y;
}
__device__ __forceinline__ float sigm_fast(float x) {
    return fmaf(0.5f, tanh_ap(0.5f * x), 0.5f);
}
__device__ __forceinline__ float silu_fast(float x) { return x * sigm_fast(x); }

__device__ __forceinline__ void ld8h(const __half* p, float* o) {
    uint4 v = *(const uint4*)p;
    __half2 h0 = *(__half2*)&v.x, h1 = *(__half2*)&v.y,
            h2 = *(__half2*)&v.z, h3 = *(__half2*)&v.w;
    float2 f;
    f = __half22float2(h0); o[0] = f.x; o[1] = f.y;
    f = __half22float2(h1); o[2] = f.x; o[3] = f.y;
    f = __half22float2(h2); o[4] = f.x; o[5] = f.y;
    f = __half22float2(h3); o[6] = f.x; o[7] = f.y;
}

// ---------------- kernel 1: u = logmap0(x), plus zero accumulators ----------
__global__ void k_logmap0(const float* __restrict__ x) {
    int idx = blockIdx.x * blockDim.x + threadIdx.x;
    if (idx >= NN * D) return;
    int n = idx >> 8;
    int j = idx & (D - 1);
    float x0 = fmaxf(x[n * D], 1.f + EPSF);
    float outv;
    if (j == 0) {
        outv = 0.f;
    } else {
        float dd = acoshf(x0);
        float sc = dd / sqrtf(x0 * x0 - 1.f);
        outv = sc * x[idx];
    }
    g_u[idx] = outv;
    g_H[idx] = 0.f;
    if (idx < NN) g_S[idx] = 0.f;
}

// ---------------- tf32 MMA GEMM: BM=64, BN=128, BK=32, 128 threads -----------
struct StA { float4 f00, f01, f10, f11; };
struct StB { float2 g[8]; };

__device__ __forceinline__ void mma_stage_fetchA(StA& st, const float* pa0,
                                                 const float* pa1, bool ok0,
                                                 bool ok1) {
    const float4 z4 = make_float4(0.f, 0.f, 0.f, 0.f);
    st.f00 = ok0 ? *(const float4*)(pa0)     : z4;
    st.f01 = ok0 ? *(const float4*)(pa0 + 4) : z4;
    st.f10 = ok1 ? *(const float4*)(pa1)     : z4;
    st.f11 = ok1 ? *(const float4*)(pa1 + 4) : z4;
}
__device__ __forceinline__ void mma_stage_storeA(unsigned* dst, const StA& st) {
    const float* a00 = &st.f00.x;
    const float* a01 = &st.f01.x;
    const float* a10 = &st.f10.x;
    const float* a11 = &st.f11.x;
    #pragma unroll
    for (int dl = 0; dl < 4; dl++) {
        uint4 v = make_uint4(t32(a00[dl]), t32(a10[dl]), t32(a01[dl]), t32(a11[dl]));
        ((uint4*)dst)[dl] = v;
    }
}
__device__ __forceinline__ void mma_stage_fetchB(StB& st, const float* pb) {
    #pragma unroll
    for (int j = 0; j < 8; j++) st.g[j] = *(const float2*)(pb + j * 256);
}
__device__ __forceinline__ void mma_stage_storeB(unsigned* dst, const StB& st) {
    uint4 v0 = make_uint4(t32(st.g[0].x), t32(st.g[4].x), t32(st.g[1].x), t32(st.g[5].x));
    uint4 v1 = make_uint4(t32(st.g[2].x), t32(st.g[6].x), t32(st.g[3].x), t32(st.g[7].x));
    uint4 v2 = make_uint4(t32(st.g[0].y), t32(st.g[4].y), t32(st.g[1].y), t32(st.g[5].y));
    uint4 v3 = make_uint4(t32(st.g[2].y), t32(st.g[6].y), t32(st.g[3].y), t32(st.g[7].y));
    ((uint4*)dst)[0] = v0; ((uint4*)dst)[1] = v1;
    ((uint4*)dst)[2] = v2; ((uint4*)dst)[3] = v3;
}

template <int OUT_HALF>
__device__ __forceinline__ void mma_gemm_body(const float* __restrict__ A,
                                              const float* __restrict__ B,
                                              void* __restrict__ Cv, int M) {
    __shared__ __align__(16) unsigned smA[2][2048];
    __shared__ __align__(16) unsigned smB[2][4096];
    int tid = threadIdx.x;
    int lane = tid & 31;
    int w = tid >> 5;
    int wm = w & 1, wn = w >> 1;
    int rowBase = blockIdx.y * 64;
    int colBase = blockIdx.x * 128;

    int aRow0 = rowBase + (tid >> 5) * 16 + (tid & 7);
    const float* pa0 = A + (size_t)aRow0 * 256 + ((tid >> 3) & 3) * 8;
    const float* pa1 = pa0 + 8 * 256;
    bool ok0 = aRow0 < M, ok1 = (aRow0 + 8) < M;
    const float* pb = B + (size_t)((tid >> 2) & 3) * 8 * 256 +
                      colBase + (tid >> 4) * 8 + 2 * (tid & 3);

    StA stA; StB stB0, stB1;
    mma_stage_fetchA(stA, pa0, pa1, ok0, ok1);
    mma_stage_fetchB(stB0, pb);
    mma_stage_fetchB(stB1, pb + 64);
    mma_stage_storeA(&smA[0][tid * 16], stA);
    mma_stage_storeB(&smB[0][tid * 16], stB0);
    mma_stage_storeB(&smB[0][2048 + tid * 16], stB1);
    __syncthreads();

    float d[2][8][4];
    #pragma unroll
    for (int t = 0; t < 2; t++)
        #pragma unroll
        for (int u = 0; u < 8; u++)
            #pragma unroll
            for (int c = 0; c < 4; c++) d[t][u][c] = 0.f;

    int buf = 0;
    for (int kb = 0; kb < 8; kb++) {
        if (kb < 7) {
            mma_stage_fetchA(stA, pa0 + (kb + 1) * 32, pa1 + (kb + 1) * 32, ok0, ok1);
            mma_stage_fetchB(stB0, pb + (size_t)(kb + 1) * 32 * 256);
            mma_stage_fetchB(stB1, pb + (size_t)(kb + 1) * 32 * 256 + 64);
        }
        #pragma unroll
        for (int s = 0; s < 4; s++) {
            uint4 fa0 = *(const uint4*)&smA[buf][((2 * wm + 0) * 4 + s) * 128 + lane * 4];
            uint4 fa1 = *(const uint4*)&smA[buf][((2 * wm + 1) * 4 + s) * 128 + lane * 4];
            uint2 fb[8];
            #pragma unroll
            for (int u = 0; u < 8; u++)
                fb[u] = *(const uint2*)&smB[buf][wn * 2048 + (u * 4 + s) * 64 + lane * 2];
            #pragma unroll
            for (int u = 0; u < 8; u++) {
                mma_tf32(d[0][u], fa0, fb[u]);
                mma_tf32(d[1][u], fa1, fb[u]);
            }
        }
        if (kb < 7) {
            int nb = buf ^ 1;
            mma_stage_storeA(&smA[nb][tid * 16], stA);
            mma_stage_storeB(&smB[nb][tid * 16], stB0);
            mma_stage_storeB(&smB[nb][2048 + tid * 16], stB1);
            __syncthreads();
            buf = nb;
        }
    }

    #pragma unroll
    for (int t = 0; t < 2; t++) {
        int r0 = rowBase + (2 * wm + t) * 16 + (lane >> 2);
        int r1 = r0 + 8;
        #pragma unroll
        for (int u = 0; u < 8; u++) {
            int c0 = colBase + wn * 64 + u * 8 + (lane & 3) * 2;
            if (OUT_HALF) {
                __half* C = (__half*)Cv;
                if (r0 < M)
                    *(__half2*)(C + (size_t)r0 * 256 + c0) =
                        __floats2half2_rn(d[t][u][0], d[t][u][1]);
                if (r1 < M)
                    *(__half2*)(C + (size_t)r1 * 256 + c0) =
                        __floats2half2_rn(d[t][u][2], d[t][u][3]);
            } else {
                float* C = (float*)Cv;
                if (r0 < M)
                    *(float2*)(C + (size_t)r0 * 256 + c0) =
                        make_float2(d[t][u][0], d[t][u][1]);
                if (r1 < M)
                    *(float2*)(C + (size_t)r1 * 256 + c0) =
                        make_float2(d[t][u][2], d[t][u][3]);
            }
        }
    }
}

__global__ __launch_bounds__(128, 3) void mma_lin(const float* __restrict__ Wlin) {
    mma_gemm_body<0>(g_u, Wlin, (void*)g_h, NN);
}

__global__ __launch_bounds__(128, 3) void mma_qp(const float* __restrict__ We1,
                                                 const float* __restrict__ Wa1) {
    int z = blockIdx.z;
    const float* A = (z == 0) ? g_xp : g_xtan;
    const float* B = (z == 0) ? We1 : (z == 1 ? Wa1 : Wa1 + 256 * 256);
    __half* C = (z == 0) ? g_Qh : (z == 1 ? g_P1h : g_P2h);
    mma_gemm_body<1>(A, B, (void*)C, NN);
}

__global__ __launch_bounds__(128, 3) void mma_agg(const float* __restrict__ We2) {
    mma_gemm_body<0>(g_H, We2, (void*)g_agg, NN);
}

// ---------------- node prep: one warp per node --------------------------------
__global__ __launch_bounds__(256) void k_node_xp(const float* __restrict__ bias) {
    int node = blockIdx.x * 8 + (threadIdx.x >> 5);
    int lane = threadIdx.x & 31;
    int base = lane * 8;

    float h[8];
    const float* hp = g_h + (size_t)node * D + base;
    *(float4*)&h[0] = *(const float4*)(hp);
    *(float4*)&h[4] = *(const float4*)(hp + 4);
    if (lane == 0) h[0] = 0.f;

    float acc = 0.f;
    #pragma unroll
    for (int i = 0; i < 8; i++) acc += h[i] * h[i];
    float r1 = warpSum(acc);
    float nn = sqrtf(fmaxf(r1, EPSF));
    float sh_n = sinhf(nn) / nn;
    float xp00 = coshf(nn);
    float xp0[8];
    #pragma unroll
    for (int i = 0; i < 8; i++) xp0[i] = sh_n * h[i];
    if (lane == 0) xp0[0] = xp00;

    float b[8];
    *(float4*)&b[0] = *(const float4*)(bias + base);
    *(float4*)&b[4] = *(const float4*)(bias + base + 4);
    if (lane == 0) b[0] = 0.f;

    acc = 0.f;
    #pragma unroll
    for (int i = 0; i < 8; i++) acc += xp0[i] * b[i];
    float c = warpSum(acc);
    float fac = c / (1.f + xp00);
    float u[8];
    #pragma unroll
    for (int i = 0; i < 8; i++) u[i] = b[i] + fac * xp0[i];
    if (lane == 0) u[0] += fac;

    acc = 0.f;
    #pragma unroll
    for (int i = 0; i < 8; i++) acc += u[i] * u[i];
    float su2 = warpSum(acc);
    float lin = su2 - 2.f * c * c;
    float nu = sqrtf(fmaxf(lin, EPSF));
    float ch = coshf(nu), sh = sinhf(nu) / nu;

    float xp[8];
    #pragma unroll
    for (int i = 0; i < 8; i++) xp[i] = ch * xp0[i] + sh * u[i];
    float* xpp = g_xp + (size_t)node * D + base;
    *(float4*)(xpp)     = *(float4*)&xp[0];
    *(float4*)(xpp + 4) = *(float4*)&xp[4];

    // fp16 copy for edge-kernel gathers
    {
        __half2 q0 = __floats2half2_rn(xp[0], xp[1]);
        __half2 q1 = __floats2half2_rn(xp[2], xp[3]);
        __half2 q2 = __floats2half2_rn(xp[4], xp[5]);
        __half2 q3 = __floats2half2_rn(xp[6], xp[7]);
        uint4 o;
        o.x = *(unsigned*)&q0; o.y = *(unsigned*)&q1;
        o.z = *(unsigned*)&q2; o.w = *(unsigned*)&q3;
        *(uint4*)(g_xph + (size_t)node * D + base) = o;
    }

    float xpc0 = ch * xp00 + sh * c;
    float x0c = fmaxf(xpc0, 1.f + EPSF);
    float sc = acoshf(x0c) / sqrtf(x0c * x0c - 1.f);
    float xt[8];
    #pragma unroll
    for (int i = 0; i < 8; i++) xt[i] = sc * xp[i];
    if (lane == 0) xt[0] = 0.f;
    float* xtp = g_xtan + (size_t)node * D + base;
    *(float4*)(xtp)     = *(float4*)&xt[0];
    *(float4*)(xtp + 4) = *(float4*)&xt[4];
}

// ---------------- edge kernel: 32 edges per block (4 per warp), fp16 gathers --
__global__ __launch_bounds__(256) void k_edge(
    const float* __restrict__ eattr, const int* __restrict__ row,
    const int* __restrict__ col, const float* __restrict__ emask,
    const float* __restrict__ Wa1, const float* __restrict__ ba1,
    const float* __restrict__ Wa2, const float* __restrict__ ba2,
    const float* __restrict__ We1, const float* __restrict__ be1) {
    __shared__ float sw[8][256];
    int tid = threadIdx.x;
    sw[0][tid] = Wa1[512 * D + tid];
    sw[1][tid] = Wa1[513 * D + tid];
    sw[2][tid] = ba1[tid];
    sw[3][tid] = Wa2[tid];
    sw[4][tid] = We1[tid];
    sw[5][tid] = We1[256 * D + tid];
    sw[6][tid] = We1[257 * D + tid];
    sw[7][tid] = be1[tid];
    __syncthreads();

    int warp = tid >> 5;
    int lane = tid & 31;
    int base = lane * 8;
    float ba2v = ba2[0];

    #pragma unroll
    for (int it = 0; it < 4; it++) {
        int e = blockIdx.x * 32 + it * 8 + warp;

        int r = row[e];
        int c = col[e];

        float xr[8], xc[8];
        ld8h(g_xph + (size_t)r * D + base, xr);
        ld8h(g_xph + (size_t)c * D + base, xc);

        float part = 0.f;
        #pragma unroll
        for (int i = 0; i < 8; i++) part -= xr[i] * xc[i];
        part = warpSum(part);

        float x0 = __shfl_sync(0xffffffffu, xr[0], 0);
        float y0 = __shfl_sync(0xffffffffu, xc[0], 0);

        float a = fmaxf(part + 2.f * x0 * y0, 1.f + EPSF);
        float dd = acoshf(a);
        float q = sqrtf(a * a - 1.f);
        float s = dd / q;
        float v0 = s * (y0 - a * x0);
        float beta = -v0 / (1.f + x0);
        float alpha = beta - s * a;

        float ea0 = eattr[e];
        float m = emask[e];

        float P1v[8], P2v[8];
        ld8h(g_P1h + (size_t)r * D + base, P1v);
        ld8h(g_P2h + (size_t)c * D + base, P2v);

        float lp = 0.f;
        #pragma unroll
        for (int i = 0; i < 8; i++) {
            int j = base + i;
            float ha = P1v[i] + P2v[i] + ea0 * sw[0][j] + dd * sw[1][j] + sw[2][j];
            lp += silu_fast(ha) * sw[3][j];
        }
        lp = warpSum(lp);
        float att = m * sigm_fast(lp + ba2v);

        float QR[8], QC[8];
        ld8h(g_Qh + (size_t)r * D + base, QR);
        ld8h(g_Qh + (size_t)c * D + base, QC);

        float val[8];
        #pragma unroll
        for (int i = 0; i < 8; i++) {
            int j = base + i;
            float hm = alpha * QR[i] + s * QC[i] + beta * sw[4][j] +
                       ea0 * sw[5][j] + dd * sw[6][j] + sw[7][j];
            val[i] = att * silu_fast(hm);
        }

        float* Hr = g_H + (size_t)r * D + base;
        asm volatile("red.global.add.v4.f32 [%0], {%1,%2,%3,%4};"
                     :: "l"(Hr), "f"(val[0]), "f"(val[1]), "f"(val[2]), "f"(val[3])
                     : "memory");
        asm volatile("red.global.add.v4.f32 [%0], {%1,%2,%3,%4};"
                     :: "l"(Hr + 4), "f"(val[4]), "f"(val[5]), "f"(val[6]), "f"(val[7])
                     : "memory");
        if (lane == 0) atomicAdd(&g_S[r], att);
    }
}

// ---------------- final node kernel: one warp per node -----------------------
__global__ __launch_bounds__(256) void k_final(const float* __restrict__ be2,
                                               const float* __restrict__ lng,
                                               const float* __restrict__ lnb,
                                               float* __restrict__ out) {
    int node = blockIdx.x * 8 + (threadIdx.x >> 5);
    int lane = threadIdx.x & 31;
    int base = lane * 8;

    float Sv = g_S[node];
    float ag[8], be[8], xp[8];
    const float* agp = g_agg + (size_t)node * D + base;
    *(float4*)&ag[0] = *(const float4*)(agp);
    *(float4*)&ag[4] = *(const float4*)(agp + 4);
    *(float4*)&be[0] = *(const float4*)(be2 + base);
    *(float4*)&be[4] = *(const float4*)(be2 + base + 4);
    const float* xpp = g_xp + (size_t)node * D + base;
    *(float4*)&xp[0] = *(const float4*)(xpp);
    *(float4*)&xp[4] = *(const float4*)(xpp + 4);

    #pragma unroll
    for (int i = 0; i < 8; i++) ag[i] += Sv * be[i];
    if (lane == 0) ag[0] = 0.f;

    float xp0 = __shfl_sync(0xffffffffu, xp[0], 0);

    float acc = 0.f;
    #pragma unroll
    for (int i = 0; i < 8; i++) acc += xp[i] * ag[i];
    float cc = warpSum(acc);
    float fac = cc / (1.f + xp0);
    float sup[8];
    #pragma unroll
    for (int i = 0; i < 8; i++) sup[i] = ag[i] + fac * xp[i];
    if (lane == 0) sup[0] += fac;

    acc = 0.f;
    #pragma unroll
    for (int i = 0; i < 8; i++) acc += sup[i] * sup[i];
    float su2 = warpSum(acc);
    float lin = su2 - 2.f * cc * cc;
    float nu = sqrtf(fmaxf(lin, EPSF));
    float ch = coshf(nu), sh = sinhf(nu) / nu;

    float y[8];
    #pragma unroll
    for (int i = 0; i < 8; i++) y[i] = ch * xp[i] + sh * sup[i];
    float y0 = ch * xp0 + sh * cc;

    float y0c = fmaxf(y0, 1.f + EPSF);
    float sc = acoshf(y0c) / sqrtf(y0c * y0c - 1.f);
    float xo[8];
    #pragma unroll
    for (int i = 0; i < 8; i++) xo[i] = sc * y[i];
    if (lane == 0) xo[0] = 0.f;

    acc = 0.f;
    #pragma unroll
    for (int i = 0; i < 8; i++) acc += xo[i];
    float mean = warpSum(acc) * (1.f / 255.f);
    float dev[8];
    #pragma unroll
    for (int i = 0; i < 8; i++) dev[i] = xo[i] - mean;
    if (lane == 0) dev[0] = 0.f;
    acc = 0.f;
    #pragma unroll
    for (int i = 0; i < 8; i++) acc += dev[i] * dev[i];
    float var = warpSum(acc) * (1.f / 255.f);
    float inv = 1.f / sqrtf(var + 1e-5f);

    float sl[8];
    #pragma unroll
    for (int i = 0; i < 8; i++) {
        int j = base + i;
        float lg = (j > 0) ? lng[j - 1] : 0.f;
        float lb = (j > 0) ? lnb[j - 1] : 0.f;
        float ln = dev[i] * inv * lg + lb;
        sl[i] = siluf(ln);
    }
    if (lane == 0) sl[0] = 0.f;

    acc = 0.f;
    #pragma unroll
    for (int i = 0; i < 8; i++) acc += sl[i] * sl[i];
    float n2 = warpSum(acc);
    float nn = sqrtf(fmaxf(n2, EPSF));
    float shn = sinhf(nn) / nn;

    float o[8];
    #pragma unroll
    for (int i = 0; i < 8; i++) o[i] = shn * sl[i];
    if (lane == 0) o[0] = coshf(nn);
    float* op = out + (size_t)node * D + base;
    *(float4*)(op)     = *(float4*)&o[0];
    *(float4*)(op + 4) = *(float4*)&o[4];
}

// ---------------- launch -----------------------------------------------------
extern "C" void kernel_launch(void* const* d_in, const int* in_sizes, int n_in,
                              void* d_out, int out_size) {
    const float* x     = (const float*)d_in[0];
    const float* eattr = (const float*)d_in[1];
    const int*   row   = (const int*)d_in[2];
    const int*   col   = (const int*)d_in[3];
    const float* emask = (const float*)d_in[5];
    const float* W_lin = (const float*)d_in[6];
    const float* bias  = (const float*)d_in[7];
    const float* W_e1  = (const float*)d_in[8];
    const float* b_e1  = (const float*)d_in[9];
    const float* W_e2  = (const float*)d_in[10];
    const float* b_e2  = (const float*)d_in[11];
    const float* W_a1  = (const float*)d_in[12];
    const float* b_a1  = (const float*)d_in[13];
    const float* W_a2  = (const float*)d_in[14];
    const float* b_a2  = (const float*)d_in[15];
    const float* ln_g  = (const float*)d_in[16];
    const float* ln_b  = (const float*)d_in[17];
    float* out = (float*)d_out;

    dim3 gElem((NN * D + 255) / 256);
    dim3 gMma(2, (NN + 63) / 64);
    dim3 gMmaQP(2, (NN + 63) / 64, 3);

    k_logmap0<<<gElem, 256>>>(x);                       // also zeroes H, S
    mma_lin<<<gMma, 128>>>(W_lin);                      // tf32 tensor cores
    k_node_xp<<<NN / 8, 256>>>(bias);
    mma_qp<<<gMmaQP, 128>>>(W_e1, W_a1);                // tf32 tensor cores
    k_edge<<<NE / 32, 256>>>(eattr, row, col, emask, W_a1, b_a1, W_a2, b_a2, W_e1, b_e1);
    mma_agg<<<gMma, 128>>>(W_e2);                       // tf32 tensor cores
    k_final<<<NN / 8, 256>>>(b_e2, ln_g, ln_b, out);
}

// round 13
// speedup vs baseline: 1.3034x; 1.1200x over previous
#include <cuda_runtime.h>
#include <cuda_fp16.h>
#include <math.h>

#define NN 10000
#define NE 200000
#define D  256
#define EPSF 1e-6f

typedef unsigned long long u64;

// ---------------- scratch (device globals: no allocation allowed) ----------
__device__ __align__(128) float g_u[NN * D];
__device__ __align__(128) float g_h[NN * D];
__device__ __align__(128) float g_xp[NN * D];
__device__ __align__(128) __half g_xph[NN * D];    // fp16 xp
__device__ __align__(128) __half g_xtanh[NN * D];  // fp16 xtan
__device__ __align__(128) __half g_Qh[NN * D];
__device__ __align__(128) __half g_P1h[NN * D];
__device__ __align__(128) __half g_P2h[NN * D];
__device__ __align__(128) float g_H[NN * D];
__device__ __align__(128) float g_agg[NN * D];
__device__ __align__(128) float g_S[NN];
__device__ __align__(128) __half g_We1h[256 * 256];
__device__ __align__(128) __half g_Wa1h[512 * 256];

// ---------------- tf32 helpers ------------------------------------------------
__device__ __forceinline__ unsigned t32(float f) {
    unsigned r; asm("cvt.rna.tf32.f32 %0,%1;" : "=r"(r) : "f"(f)); return r;
}
__device__ __forceinline__ void mma_tf32(float* d, const uint4& a, const uint2& b) {
    asm volatile(
        "mma.sync.aligned.m16n8k8.row.col.f32.tf32.tf32.f32 "
        "{%0,%1,%2,%3},{%4,%5,%6,%7},{%8,%9},{%0,%1,%2,%3};"
        : "+f"(d[0]), "+f"(d[1]), "+f"(d[2]), "+f"(d[3])
        : "r"(a.x), "r"(a.y), "r"(a.z), "r"(a.w), "r"(b.x), "r"(b.y));
}
// ---------------- fp16 mma ----------------------------------------------------
__device__ __forceinline__ void mma_f16(float* d, const uint4& a, const uint2& b) {
    asm volatile(
        "mma.sync.aligned.m16n8k16.row.col.f32.f16.f16.f32 "
        "{%0,%1,%2,%3},{%4,%5,%6,%7},{%8,%9},{%0,%1,%2,%3};"
        : "+f"(d[0]), "+f"(d[1]), "+f"(d[2]), "+f"(d[3])
        : "r"(a.x), "r"(a.y), "r"(a.z), "r"(a.w), "r"(b.x), "r"(b.y));
}
__device__ __forceinline__ unsigned prmt(unsigned a, unsigned b, unsigned sel) {
    unsigned r; asm("prmt.b32 %0,%1,%2,%3;" : "=r"(r) : "r"(a), "r"(b), "r"(sel));
    return r;
}

// ---------------- misc helpers ------------------------------------------------
__device__ __forceinline__ float warpSum(float v) {
    #pragma unroll
    for (int o = 16; o > 0; o >>= 1) v += __shfl_xor_sync(0xffffffffu, v, o);
    return v;
}
__device__ __forceinline__ float siluf(float x) { return x / (1.f + expf(-x)); }
__device__ __forceinline__ float tanh_ap(float x) {
    float y; asm("tanh.approx.f32 %0,%1;" : "=f"(y) : "f"(x)); return y;
}
__device__ __forceinline__ float sigm_fast(float x) {
    return fmaf(0.5f, tanh_ap(0.5f * x), 0.5f);
}
__device__ __forceinline__ float silu_fast(float x) { return x * sigm_fast(x); }

__device__ __forceinline__ void ld8h(const __half* p, float* o) {
    uint4 v = *(const uint4*)p;
    __half2 h0 = *(__half2*)&v.x, h1 = *(__half2*)&v.y,
            h2 = *(__half2*)&v.z, h3 = *(__half2*)&v.w;
    float2 f;
    f = __half22float2(h0); o[0] = f.x; o[1] = f.y;
    f = __half22float2(h1); o[2] = f.x; o[3] = f.y;
    f = __half22float2(h2); o[4] = f.x; o[5] = f.y;
    f = __half22float2(h3); o[6] = f.x; o[7] = f.y;
}

// ---------------- kernel 1: u = logmap0(x), plus zero accumulators ----------
__global__ void k_logmap0(const float* __restrict__ x) {
    int idx = blockIdx.x * blockDim.x + threadIdx.x;
    if (idx >= NN * D) return;
    int n = idx >> 8;
    int j = idx & (D - 1);
    float x0 = fmaxf(x[n * D], 1.f + EPSF);
    float outv;
    if (j == 0) {
        outv = 0.f;
    } else {
        float dd = acoshf(x0);
        float sc = dd / sqrtf(x0 * x0 - 1.f);
        outv = sc * x[idx];
    }
    g_u[idx] = outv;
    g_H[idx] = 0.f;
    if (idx < NN) g_S[idx] = 0.f;
}

// ---------------- weight fp16 conversion -------------------------------------
__global__ void k_cvt_w(const float* __restrict__ We1, const float* __restrict__ Wa1) {
    int i = blockIdx.x * 256 + threadIdx.x;
    if (i < 256 * 256) g_We1h[i] = __float2half(We1[i]);
    if (i < 512 * 256) g_Wa1h[i] = __float2half(Wa1[i]);
}

// ---------------- tf32 MMA GEMM: BM=64, BN=128, BK=32, 128 threads -----------
struct StA { float4 f00, f01, f10, f11; };
struct StB { float2 g[8]; };

__device__ __forceinline__ void mma_stage_fetchA(StA& st, const float* pa0,
                                                 const float* pa1, bool ok0,
                                                 bool ok1) {
    const float4 z4 = make_float4(0.f, 0.f, 0.f, 0.f);
    st.f00 = ok0 ? *(const float4*)(pa0)     : z4;
    st.f01 = ok0 ? *(const float4*)(pa0 + 4) : z4;
    st.f10 = ok1 ? *(const float4*)(pa1)     : z4;
    st.f11 = ok1 ? *(const float4*)(pa1 + 4) : z4;
}
__device__ __forceinline__ void mma_stage_storeA(unsigned* dst, const StA& st) {
    const float* a00 = &st.f00.x;
    const float* a01 = &st.f01.x;
    const float* a10 = &st.f10.x;
    const float* a11 = &st.f11.x;
    #pragma unroll
    for (int dl = 0; dl < 4; dl++) {
        uint4 v = make_uint4(t32(a00[dl]), t32(a10[dl]), t32(a01[dl]), t32(a11[dl]));
        ((uint4*)dst)[dl] = v;
    }
}
__device__ __forceinline__ void mma_stage_fetchB(StB& st, const float* pb) {
    #pragma unroll
    for (int j = 0; j < 8; j++) st.g[j] = *(const float2*)(pb + j * 256);
}
__device__ __forceinline__ void mma_stage_storeB(unsigned* dst, const StB& st) {
    uint4 v0 = make_uint4(t32(st.g[0].x), t32(st.g[4].x), t32(st.g[1].x), t32(st.g[5].x));
    uint4 v1 = make_uint4(t32(st.g[2].x), t32(st.g[6].x), t32(st.g[3].x), t32(st.g[7].x));
    uint4 v2 = make_uint4(t32(st.g[0].y), t32(st.g[4].y), t32(st.g[1].y), t32(st.g[5].y));
    uint4 v3 = make_uint4(t32(st.g[2].y), t32(st.g[6].y), t32(st.g[3].y), t32(st.g[7].y));
    ((uint4*)dst)[0] = v0; ((uint4*)dst)[1] = v1;
    ((uint4*)dst)[2] = v2; ((uint4*)dst)[3] = v3;
}

__device__ __forceinline__ void mma_gemm_body_f32(const float* __restrict__ A,
                                                  const float* __restrict__ B,
                                                  float* __restrict__ C, int M) {
    __shared__ __align__(16) unsigned smA[2][2048];
    __shared__ __align__(16) unsigned smB[2][4096];
    int tid = threadIdx.x;
    int lane = tid & 31;
    int w = tid >> 5;
    int wm = w & 1, wn = w >> 1;
    int rowBase = blockIdx.y * 64;
    int colBase = blockIdx.x * 128;

    int aRow0 = rowBase + (tid >> 5) * 16 + (tid & 7);
    const float* pa0 = A + (size_t)aRow0 * 256 + ((tid >> 3) & 3) * 8;
    const float* pa1 = pa0 + 8 * 256;
    bool ok0 = aRow0 < M, ok1 = (aRow0 + 8) < M;
    const float* pb = B + (size_t)((tid >> 2) & 3) * 8 * 256 +
                      colBase + (tid >> 4) * 8 + 2 * (tid & 3);

    StA stA; StB stB0, stB1;
    mma_stage_fetchA(stA, pa0, pa1, ok0, ok1);
    mma_stage_fetchB(stB0, pb);
    mma_stage_fetchB(stB1, pb + 64);
    mma_stage_storeA(&smA[0][tid * 16], stA);
    mma_stage_storeB(&smB[0][tid * 16], stB0);
    mma_stage_storeB(&smB[0][2048 + tid * 16], stB1);
    __syncthreads();

    float d[2][8][4];
    #pragma unroll
    for (int t = 0; t < 2; t++)
        #pragma unroll
        for (int u = 0; u < 8; u++)
            #pragma unroll
            for (int c = 0; c < 4; c++) d[t][u][c] = 0.f;

    int buf = 0;
    for (int kb = 0; kb < 8; kb++) {
        if (kb < 7) {
            mma_stage_fetchA(stA, pa0 + (kb + 1) * 32, pa1 + (kb + 1) * 32, ok0, ok1);
            mma_stage_fetchB(stB0, pb + (size_t)(kb + 1) * 32 * 256);
            mma_stage_fetchB(stB1, pb + (size_t)(kb + 1) * 32 * 256 + 64);
        }
        #pragma unroll
        for (int s = 0; s < 4; s++) {
            uint4 fa0 = *(const uint4*)&smA[buf][((2 * wm + 0) * 4 + s) * 128 + lane * 4];
            uint4 fa1 = *(const uint4*)&smA[buf][((2 * wm + 1) * 4 + s) * 128 + lane * 4];
            uint2 fb[8];
            #pragma unroll
            for (int u = 0; u < 8; u++)
                fb[u] = *(const uint2*)&smB[buf][wn * 2048 + (u * 4 + s) * 64 + lane * 2];
            #pragma unroll
            for (int u = 0; u < 8; u++) {
                mma_tf32(d[0][u], fa0, fb[u]);
                mma_tf32(d[1][u], fa1, fb[u]);
            }
        }
        if (kb < 7) {
            int nb = buf ^ 1;
            mma_stage_storeA(&smA[nb][tid * 16], stA);
            mma_stage_storeB(&smB[nb][tid * 16], stB0);
            mma_stage_storeB(&smB[nb][2048 + tid * 16], stB1);
            __syncthreads();
            buf = nb;
        }
    }

    #pragma unroll
    for (int t = 0; t < 2; t++) {
        int r0 = rowBase + (2 * wm + t) * 16 + (lane >> 2);
        int r1 = r0 + 8;
        #pragma unroll
        for (int u = 0; u < 8; u++) {
            int c0 = colBase + wn * 64 + u * 8 + (lane & 3) * 2;
            if (r0 < M)
                *(float2*)(C + (size_t)r0 * 256 + c0) =
                    make_float2(d[t][u][0], d[t][u][1]);
            if (r1 < M)
                *(float2*)(C + (size_t)r1 * 256 + c0) =
                    make_float2(d[t][u][2], d[t][u][3]);
        }
    }
}

__global__ __launch_bounds__(128, 3) void mma_lin(const float* __restrict__ Wlin) {
    mma_gemm_body_f32(g_u, Wlin, g_h, NN);
}
__global__ __launch_bounds__(128, 3) void mma_agg(const float* __restrict__ We2) {
    mma_gemm_body_f32(g_H, We2, g_agg, NN);
}

// ---------------- fp16 MMA GEMM (m16n8k16): BM=64, BN=128, BK=32 -------------
// Fragment-major smem; A staged per (m16 group, k16 slice, lane) as uint4,
// B per (n8 group, k16 slice, lane) as uint2 with PRMT k-pair packing.
__global__ __launch_bounds__(128, 3) void mma_qph() {
    int z = blockIdx.z;
    const __half* A = (z == 0) ? g_xph : g_xtanh;
    const __half* B = (z == 0) ? g_We1h : (z == 1 ? g_Wa1h : g_Wa1h + 256 * 256);
    __half* C = (z == 0) ? g_Qh : (z == 1 ? g_P1h : g_P2h);
    const int M = NN;

    __shared__ __align__(16) unsigned smA[2][1024];   // 4 g x 2 s x 32 lane x 4 w
    __shared__ __align__(16) unsigned smB[2][2048];   // 16 gn x 2 s x 32 lane x 2 w
    int tid = threadIdx.x;
    int lane = tid & 31;
    int w = tid >> 5;
    int wm = w & 1, wn = w >> 1;
    int rowBase = blockIdx.y * 64;
    int colBase = blockIdx.x * 128;

    // A staging map: thread -> (row ar, k16 slice as)
    int ar = tid >> 1;
    int as = tid & 1;
    int aRow = rowBase + ar;
    bool aok = aRow < M;
    const __half* pa = A + (size_t)aRow * 256 + as * 16;
    int ag = ar >> 4;
    int rr = ar & 15;
    int abase = ((ag * 2 + as) * 32 + (rr & 7) * 4) * 4 + (rr >> 3);

    // B staging map: thread -> (k-pair kp2, 16-col block nblk)
    int kp2 = tid & 15;
    int nblk = tid >> 4;
    const __half* pb = B + (size_t)(kp2 * 2) * 256 + colBase + nblk * 16;
    int bs = kp2 >> 3;
    int kk = kp2 & 7;
    int bl4 = kk & 3;
    int breg = kk >> 2;

    const uint4 zz = make_uint4(0u, 0u, 0u, 0u);
    uint4 va, vb, u0, u1, v0, v1;

    va = aok ? *(const uint4*)(pa)     : zz;
    vb = aok ? *(const uint4*)(pa + 8) : zz;
    u0 = *(const uint4*)(pb);
    u1 = *(const uint4*)(pb + 8);
    v0 = *(const uint4*)(pb + 256);
    v1 = *(const uint4*)(pb + 256 + 8);

    {   // stage buf 0
        unsigned* dA = &smA[0][abase];
        dA[0] = va.x; dA[4] = va.y; dA[8]  = va.z; dA[12] = va.w;
        dA[2] = vb.x; dA[6] = vb.y; dA[10] = vb.z; dA[14] = vb.w;
        unsigned ub[8]  = {u0.x, u0.y, u0.z, u0.w, u1.x, u1.y, u1.z, u1.w};
        unsigned vbr[8] = {v0.x, v0.y, v0.z, v0.w, v1.x, v1.y, v1.z, v1.w};
        #pragma unroll
        for (int wi = 0; wi < 8; wi++) {
            unsigned f0 = prmt(ub[wi], vbr[wi], 0x5410);
            unsigned f1 = prmt(ub[wi], vbr[wi], 0x7632);
            int n0 = nblk * 16 + wi * 2;
            int gn = n0 >> 3;
            int l0 = n0 & 7;
            smB[0][((gn * 2 + bs) * 32 + l0 * 4 + bl4) * 2 + breg] = f0;
            smB[0][((gn * 2 + bs) * 32 + (l0 + 1) * 4 + bl4) * 2 + breg] = f1;
        }
    }
    __syncthreads();

    float d[2][8][4];
    #pragma unroll
    for (int t = 0; t < 2; t++)
        #pragma unroll
        for (int u = 0; u < 8; u++)
            #pragma unroll
            for (int c = 0; c < 4; c++) d[t][u][c] = 0.f;

    int buf = 0;
    for (int kb = 0; kb < 8; kb++) {
        if (kb < 7) {
            const __half* pan = pa + (kb + 1) * 32;
            va = aok ? *(const uint4*)(pan)     : zz;
            vb = aok ? *(const uint4*)(pan + 8) : zz;
            const __half* pbn = pb + (size_t)(kb + 1) * 32 * 256;
            u0 = *(const uint4*)(pbn);
            u1 = *(const uint4*)(pbn + 8);
            v0 = *(const uint4*)(pbn + 256);
            v1 = *(const uint4*)(pbn + 256 + 8);
        }
        #pragma unroll
        for (int s = 0; s < 2; s++) {
            uint4 fa0 = *(const uint4*)&smA[buf][(((wm * 2 + 0) * 2 + s) * 32 + lane) * 4];
            uint4 fa1 = *(const uint4*)&smA[buf][(((wm * 2 + 1) * 2 + s) * 32 + lane) * 4];
            uint2 fb[8];
            #pragma unroll
            for (int u = 0; u < 8; u++)
                fb[u] = *(const uint2*)&smB[buf][(((wn * 8 + u) * 2 + s) * 32 + lane) * 2];
            #pragma unroll
            for (int u = 0; u < 8; u++) {
                mma_f16(d[0][u], fa0, fb[u]);
                mma_f16(d[1][u], fa1, fb[u]);
            }
        }
        if (kb < 7) {
            int nb = buf ^ 1;
            unsigned* dA = &smA[nb][abase];
            dA[0] = va.x; dA[4] = va.y; dA[8]  = va.z; dA[12] = va.w;
            dA[2] = vb.x; dA[6] = vb.y; dA[10] = vb.z; dA[14] = vb.w;
            unsigned ub[8]  = {u0.x, u0.y, u0.z, u0.w, u1.x, u1.y, u1.z, u1.w};
            unsigned vbr[8] = {v0.x, v0.y, v0.z, v0.w, v1.x, v1.y, v1.z, v1.w};
            #pragma unroll
            for (int wi = 0; wi < 8; wi++) {
                unsigned f0 = prmt(ub[wi], vbr[wi], 0x5410);
                unsigned f1 = prmt(ub[wi], vbr[wi], 0x7632);
                int n0 = nblk * 16 + wi * 2;
                int gn = n0 >> 3;
                int l0 = n0 & 7;
                smB[nb][((gn * 2 + bs) * 32 + l0 * 4 + bl4) * 2 + breg] = f0;
                smB[nb][((gn * 2 + bs) * 32 + (l0 + 1) * 4 + bl4) * 2 + breg] = f1;
            }
            __syncthreads();
            buf = nb;
        }
    }

    #pragma unroll
    for (int t = 0; t < 2; t++) {
        int r0 = rowBase + (2 * wm + t) * 16 + (lane >> 2);
        int r1 = r0 + 8;
        #pragma unroll
        for (int u = 0; u < 8; u++) {
            int c0 = colBase + wn * 64 + u * 8 + (lane & 3) * 2;
            if (r0 < M)
                *(__half2*)(C + (size_t)r0 * 256 + c0) =
                    __floats2half2_rn(d[t][u][0], d[t][u][1]);
            if (r1 < M)
                *(__half2*)(C + (size_t)r1 * 256 + c0) =
                    __floats2half2_rn(d[t][u][2], d[t][u][3]);
        }
    }
}

// ---------------- node prep: one warp per node --------------------------------
__global__ __launch_bounds__(256) void k_node_xp(const float* __restrict__ bias) {
    int node = blockIdx.x * 8 + (threadIdx.x >> 5);
    int lane = threadIdx.x & 31;
    int base = lane * 8;

    float h[8];
    const float* hp = g_h + (size_t)node * D + base;
    *(float4*)&h[0] = *(const float4*)(hp);
    *(float4*)&h[4] = *(const float4*)(hp + 4);
    if (lane == 0) h[0] = 0.f;

    float acc = 0.f;
    #pragma unroll
    for (int i = 0; i < 8; i++) acc += h[i] * h[i];
    float r1 = warpSum(acc);
    float nn = sqrtf(fmaxf(r1, EPSF));
    float sh_n = sinhf(nn) / nn;
    float xp00 = coshf(nn);
    float xp0[8];
    #pragma unroll
    for (int i = 0; i < 8; i++) xp0[i] = sh_n * h[i];
    if (lane == 0) xp0[0] = xp00;

    float b[8];
    *(float4*)&b[0] = *(const float4*)(bias + base);
    *(float4*)&b[4] = *(const float4*)(bias + base + 4);
    if (lane == 0) b[0] = 0.f;

    acc = 0.f;
    #pragma unroll
    for (int i = 0; i < 8; i++) acc += xp0[i] * b[i];
    float c = warpSum(acc);
    float fac = c / (1.f + xp00);
    float u[8];
    #pragma unroll
    for (int i = 0; i < 8; i++) u[i] = b[i] + fac * xp0[i];
    if (lane == 0) u[0] += fac;

    acc = 0.f;
    #pragma unroll
    for (int i = 0; i < 8; i++) acc += u[i] * u[i];
    float su2 = warpSum(acc);
    float lin = su2 - 2.f * c * c;
    float nu = sqrtf(fmaxf(lin, EPSF));
    float ch = coshf(nu), sh = sinhf(nu) / nu;

    float xp[8];
    #pragma unroll
    for (int i = 0; i < 8; i++) xp[i] = ch * xp0[i] + sh * u[i];
    float* xpp = g_xp + (size_t)node * D + base;
    *(float4*)(xpp)     = *(float4*)&xp[0];
    *(float4*)(xpp + 4) = *(float4*)&xp[4];

    // fp16 copy of xp
    {
        __half2 q0 = __floats2half2_rn(xp[0], xp[1]);
        __half2 q1 = __floats2half2_rn(xp[2], xp[3]);
        __half2 q2 = __floats2half2_rn(xp[4], xp[5]);
        __half2 q3 = __floats2half2_rn(xp[6], xp[7]);
        uint4 o;
        o.x = *(unsigned*)&q0; o.y = *(unsigned*)&q1;
        o.z = *(unsigned*)&q2; o.w = *(unsigned*)&q3;
        *(uint4*)(g_xph + (size_t)node * D + base) = o;
    }

    float xpc0 = ch * xp00 + sh * c;
    float x0c = fmaxf(xpc0, 1.f + EPSF);
    float sc = acoshf(x0c) / sqrtf(x0c * x0c - 1.f);
    float xt[8];
    #pragma unroll
    for (int i = 0; i < 8; i++) xt[i] = sc * xp[i];
    if (lane == 0) xt[0] = 0.f;
    // fp16 xtan
    {
        __half2 q0 = __floats2half2_rn(xt[0], xt[1]);
        __half2 q1 = __floats2half2_rn(xt[2], xt[3]);
        __half2 q2 = __floats2half2_rn(xt[4], xt[5]);
        __half2 q3 = __floats2half2_rn(xt[6], xt[7]);
        uint4 o;
        o.x = *(unsigned*)&q0; o.y = *(unsigned*)&q1;
        o.z = *(unsigned*)&q2; o.w = *(unsigned*)&q3;
        *(uint4*)(g_xtanh + (size_t)node * D + base) = o;
    }
}

// ---------------- edge kernel: 32 edges per block (4 per warp), fp16 gathers --
__global__ __launch_bounds__(256) void k_edge(
    const float* __restrict__ eattr, const int* __restrict__ row,
    const int* __restrict__ col, const float* __restrict__ emask,
    const float* __restrict__ Wa1, const float* __restrict__ ba1,
    const float* __restrict__ Wa2, const float* __restrict__ ba2,
    const float* __restrict__ We1, const float* __restrict__ be1) {
    __shared__ float sw[8][256];
    int tid = threadIdx.x;
    sw[0][tid] = Wa1[512 * D + tid];
    sw[1][tid] = Wa1[513 * D + tid];
    sw[2][tid] = ba1[tid];
    sw[3][tid] = Wa2[tid];
    sw[4][tid] = We1[tid];
    sw[5][tid] = We1[256 * D + tid];
    sw[6][tid] = We1[257 * D + tid];
    sw[7][tid] = be1[tid];
    __syncthreads();

    int warp = tid >> 5;
    int lane = tid & 31;
    int base = lane * 8;
    float ba2v = ba2[0];

    #pragma unroll
    for (int it = 0; it < 4; it++) {
        int e = blockIdx.x * 32 + it * 8 + warp;

        int r = row[e];
        int c = col[e];

        float xr[8], xc[8];
        ld8h(g_xph + (size_t)r * D + base, xr);
        ld8h(g_xph + (size_t)c * D + base, xc);

        float part = 0.f;
        #pragma unroll
        for (int i = 0; i < 8; i++) part -= xr[i] * xc[i];
        part = warpSum(part);

        float x0 = __shfl_sync(0xffffffffu, xr[0], 0);
        float y0 = __shfl_sync(0xffffffffu, xc[0], 0);

        float a = fmaxf(part + 2.f * x0 * y0, 1.f + EPSF);
        float dd = acoshf(a);
        float q = sqrtf(a * a - 1.f);
        float s = dd / q;
        float v0 = s * (y0 - a * x0);
        float beta = -v0 / (1.f + x0);
        float alpha = beta - s * a;

        float ea0 = eattr[e];
        float m = emask[e];

        float P1v[8], P2v[8];
        ld8h(g_P1h + (size_t)r * D + base, P1v);
        ld8h(g_P2h + (size_t)c * D + base, P2v);

        float lp = 0.f;
        #pragma unroll
        for (int i = 0; i < 8; i++) {
            int j = base + i;
            float ha = P1v[i] + P2v[i] + ea0 * sw[0][j] + dd * sw[1][j] + sw[2][j];
            lp += silu_fast(ha) * sw[3][j];
        }
        lp = warpSum(lp);
        float att = m * sigm_fast(lp + ba2v);

        float QR[8], QC[8];
        ld8h(g_Qh + (size_t)r * D + base, QR);
        ld8h(g_Qh + (size_t)c * D + base, QC);

        float val[8];
        #pragma unroll
        for (int i = 0; i < 8; i++) {
            int j = base + i;
            float hm = alpha * QR[i] + s * QC[i] + beta * sw[4][j] +
                       ea0 * sw[5][j] + dd * sw[6][j] + sw[7][j];
            val[i] = att * silu_fast(hm);
        }

        float* Hr = g_H + (size_t)r * D + base;
        asm volatile("red.global.add.v4.f32 [%0], {%1,%2,%3,%4};"
                     :: "l"(Hr), "f"(val[0]), "f"(val[1]), "f"(val[2]), "f"(val[3])
                     : "memory");
        asm volatile("red.global.add.v4.f32 [%0], {%1,%2,%3,%4};"
                     :: "l"(Hr + 4), "f"(val[4]), "f"(val[5]), "f"(val[6]), "f"(val[7])
                     : "memory");
        if (lane == 0) atomicAdd(&g_S[r], att);
    }
}

// ---------------- final node kernel: one warp per node -----------------------
__global__ __launch_bounds__(256) void k_final(const float* __restrict__ be2,
                                               const float* __restrict__ lng,
                                               const float* __restrict__ lnb,
                                               float* __restrict__ out) {
    int node = blockIdx.x * 8 + (threadIdx.x >> 5);
    int lane = threadIdx.x & 31;
    int base = lane * 8;

    float Sv = g_S[node];
    float ag[8], be[8], xp[8];
    const float* agp = g_agg + (size_t)node * D + base;
    *(float4*)&ag[0] = *(const float4*)(agp);
    *(float4*)&ag[4] = *(const float4*)(agp + 4);
    *(float4*)&be[0] = *(const float4*)(be2 + base);
    *(float4*)&be[4] = *(const float4*)(be2 + base + 4);
    const float* xpp = g_xp + (size_t)node * D + base;
    *(float4*)&xp[0] = *(const float4*)(xpp);
    *(float4*)&xp[4] = *(const float4*)(xpp + 4);

    #pragma unroll
    for (int i = 0; i < 8; i++) ag[i] += Sv * be[i];
    if (lane == 0) ag[0] = 0.f;

    float xp0 = __shfl_sync(0xffffffffu, xp[0], 0);

    float acc = 0.f;
    #pragma unroll
    for (int i = 0; i < 8; i++) acc += xp[i] * ag[i];
    float cc = warpSum(acc);
    float fac = cc / (1.f + xp0);
    float sup[8];
    #pragma unroll
    for (int i = 0; i < 8; i++) sup[i] = ag[i] + fac * xp[i];
    if (lane == 0) sup[0] += fac;

    acc = 0.f;
    #pragma unroll
    for (int i = 0; i < 8; i++) acc += sup[i] * sup[i];
    float su2 = warpSum(acc);
    float lin = su2 - 2.f * cc * cc;
    float nu = sqrtf(fmaxf(lin, EPSF));
    float ch = coshf(nu), sh = sinhf(nu) / nu;

    float y[8];
    #pragma unroll
    for (int i = 0; i < 8; i++) y[i] = ch * xp[i] + sh * sup[i];
    float y0 = ch * xp0 + sh * cc;

    float y0c = fmaxf(y0, 1.f + EPSF);
    float sc = acoshf(y0c) / sqrtf(y0c * y0c - 1.f);
    float xo[8];
    #pragma unroll
    for (int i = 0; i < 8; i++) xo[i] = sc * y[i];
    if (lane == 0) xo[0] = 0.f;

    acc = 0.f;
    #pragma unroll
    for (int i = 0; i < 8; i++) acc += xo[i];
    float mean = warpSum(acc) * (1.f / 255.f);
    float dev[8];
    #pragma unroll
    for (int i = 0; i < 8; i++) dev[i] = xo[i] - mean;
    if (lane == 0) dev[0] = 0.f;
    acc = 0.f;
    #pragma unroll
    for (int i = 0; i < 8; i++) acc += dev[i] * dev[i];
    float var = warpSum(acc) * (1.f / 255.f);
    float inv = 1.f / sqrtf(var + 1e-5f);

    float sl[8];
    #pragma unroll
    for (int i = 0; i < 8; i++) {
        int j = base + i;
        float lg = (j > 0) ? lng[j - 1] : 0.f;
        float lb = (j > 0) ? lnb[j - 1] : 0.f;
        float ln = dev[i] * inv * lg + lb;
        sl[i] = siluf(ln);
    }
    if (lane == 0) sl[0] = 0.f;

    acc = 0.f;
    #pragma unroll
    for (int i = 0; i < 8; i++) acc += sl[i] * sl[i];
    float n2 = warpSum(acc);
    float nn = sqrtf(fmaxf(n2, EPSF));
    float shn = sinhf(nn) / nn;

    float o[8];
    #pragma unroll
    for (int i = 0; i < 8; i++) o[i] = shn * sl[i];
    if (lane == 0) o[0] = coshf(nn);
    float* op = out + (size_t)node * D + base;
    *(float4*)(op)     = *(float4*)&o[0];
    *(float4*)(op + 4) = *(float4*)&o[4];
}

// ---------------- launch -----------------------------------------------------
extern "C" void kernel_launch(void* const* d_in, const int* in_sizes, int n_in,
                              void* d_out, int out_size) {
    const float* x     = (const float*)d_in[0];
    const float* eattr = (const float*)d_in[1];
    const int*   row   = (const int*)d_in[2];
    const int*   col   = (const int*)d_in[3];
    const float* emask = (const float*)d_in[5];
    const float* W_lin = (const float*)d_in[6];
    const float* bias  = (const float*)d_in[7];
    const float* W_e1  = (const float*)d_in[8];
    const float* b_e1  = (const float*)d_in[9];
    const float* W_e2  = (const float*)d_in[10];
    const float* b_e2  = (const float*)d_in[11];
    const float* W_a1  = (const float*)d_in[12];
    const float* b_a1  = (const float*)d_in[13];
    const float* W_a2  = (const float*)d_in[14];
    const float* b_a2  = (const float*)d_in[15];
    const float* ln_g  = (const float*)d_in[16];
    const float* ln_b  = (const float*)d_in[17];
    float* out = (float*)d_out;

    dim3 gElem((NN * D + 255) / 256);
    dim3 gMma(2, (NN + 63) / 64);
    dim3 gMmaQP(2, (NN + 63) / 64, 3);

    k_logmap0<<<gElem, 256>>>(x);                       // also zeroes H, S
    k_cvt_w<<<512, 256>>>(W_e1, W_a1);                  // weights -> fp16
    mma_lin<<<gMma, 128>>>(W_lin);                      // tf32
    k_node_xp<<<NN / 8, 256>>>(bias);
    mma_qph<<<gMmaQP, 128>>>();                         // fp16 m16n8k16
    k_edge<<<NE / 32, 256>>>(eattr, row, col, emask, W_a1, b_a1, W_a2, b_a2, W_e1, b_e1);
    mma_agg<<<gMma, 128>>>(W_e2);                       // tf32
    k_final<<<NN / 8, 256>>>(b_e2, ln_g, ln_b, out);
}

// round 14
// speedup vs baseline: 1.3438x; 1.0310x over previous
#include <cuda_runtime.h>
#include <cuda_fp16.h>
#include <math.h>

#define NN 10000
#define NE 200000
#define D  256
#define EPSF 1e-6f

typedef unsigned long long u64;

// ---------------- scratch (device globals: no allocation allowed) ----------
__device__ __align__(128) float g_u[NN * D];
__device__ __align__(128) float g_h[NN * D];
__device__ __align__(128) float g_xp[NN * D];
__device__ __align__(128) __half g_xph[NN * D];    // fp16 xp
__device__ __align__(128) __half g_xtanh[NN * D];  // fp16 xtan
__device__ __align__(128) __half g_Qh[NN * D];
__device__ __align__(128) __half g_P1h[NN * D];
__device__ __align__(128) __half g_P2h[NN * D];
__device__ __align__(128) float g_H[NN * D];
__device__ __align__(128) float g_agg[NN * D];
__device__ __align__(128) float g_S[NN];
__device__ __align__(128) __half g_We1h[256 * 256];
__device__ __align__(128) __half g_Wa1h[512 * 256];

// ---------------- tf32 helpers ------------------------------------------------
__device__ __forceinline__ unsigned t32(float f) {
    unsigned r; asm("cvt.rna.tf32.f32 %0,%1;" : "=r"(r) : "f"(f)); return r;
}
__device__ __forceinline__ void mma_tf32(float* d, const uint4& a, const uint2& b) {
    asm volatile(
        "mma.sync.aligned.m16n8k8.row.col.f32.tf32.tf32.f32 "
        "{%0,%1,%2,%3},{%4,%5,%6,%7},{%8,%9},{%0,%1,%2,%3};"
        : "+f"(d[0]), "+f"(d[1]), "+f"(d[2]), "+f"(d[3])
        : "r"(a.x), "r"(a.y), "r"(a.z), "r"(a.w), "r"(b.x), "r"(b.y));
}
// ---------------- fp16 mma ----------------------------------------------------
__device__ __forceinline__ void mma_f16(float* d, const uint4& a, const uint2& b) {
    asm volatile(
        "mma.sync.aligned.m16n8k16.row.col.f32.f16.f16.f32 "
        "{%0,%1,%2,%3},{%4,%5,%6,%7},{%8,%9},{%0,%1,%2,%3};"
        : "+f"(d[0]), "+f"(d[1]), "+f"(d[2]), "+f"(d[3])
        : "r"(a.x), "r"(a.y), "r"(a.z), "r"(a.w), "r"(b.x), "r"(b.y));
}
__device__ __forceinline__ unsigned prmt(unsigned a, unsigned b, unsigned sel) {
    unsigned r; asm("prmt.b32 %0,%1,%2,%3;" : "=r"(r) : "r"(a), "r"(b), "r"(sel));
    return r;
}

// ---------------- misc helpers ------------------------------------------------
__device__ __forceinline__ float warpSum(float v) {
    #pragma unroll
    for (int o = 16; o > 0; o >>= 1) v += __shfl_xor_sync(0xffffffffu, v, o);
    return v;
}
__device__ __forceinline__ float siluf(float x) { return x / (1.f + expf(-x)); }
__device__ __forceinline__ float tanh_ap(float x) {
    float y; asm("tanh.approx.f32 %0,%1;" : "=f"(y) : "f"(x)); return y;
}
__device__ __forceinline__ float sigm_fast(float x) {
    return fmaf(0.5f, tanh_ap(0.5f * x), 0.5f);
}
__device__ __forceinline__ float silu_fast(float x) { return x * sigm_fast(x); }

__device__ __forceinline__ void ld8h(const __half* p, float* o) {
    uint4 v = *(const uint4*)p;
    __half2 h0 = *(__half2*)&v.x, h1 = *(__half2*)&v.y,
            h2 = *(__half2*)&v.z, h3 = *(__half2*)&v.w;
    float2 f;
    f = __half22float2(h0); o[0] = f.x; o[1] = f.y;
    f = __half22float2(h1); o[2] = f.x; o[3] = f.y;
    f = __half22float2(h2); o[4] = f.x; o[5] = f.y;
    f = __half22float2(h3); o[6] = f.x; o[7] = f.y;
}

// ---------------- fused kernel 1: logmap0 (warp-per-node) + zero + cvt_w ------
// blocks [0, NN/8): 8 nodes each (warp per node); blocks [NN/8, +768): weight cvt
#define LOG_BLOCKS (NN / 8)
__global__ __launch_bounds__(256) void k_logmap0_fused(
    const float* __restrict__ x, const float* __restrict__ We1,
    const float* __restrict__ Wa1) {
    int b = blockIdx.x;
    int tid = threadIdx.x;
    if (b >= LOG_BLOCKS) {
        int i = (b - LOG_BLOCKS) * 256 + tid;
        if (i < 256 * 256) g_We1h[i] = __float2half(We1[i]);
        if (i < 512 * 256) g_Wa1h[i] = __float2half(Wa1[i]);
        return;
    }
    int node = b * 8 + (tid >> 5);
    int lane = tid & 31;
    int base = lane * 8;

    float xv[8];
    const float* xp = x + (size_t)node * D + base;
    *(float4*)&xv[0] = *(const float4*)(xp);
    *(float4*)&xv[4] = *(const float4*)(xp + 4);

    float x0 = fmaxf(__shfl_sync(0xffffffffu, xv[0], 0), 1.f + EPSF);
    float sc = acoshf(x0) / sqrtf(x0 * x0 - 1.f);

    float uo[8];
    #pragma unroll
    for (int i = 0; i < 8; i++) uo[i] = sc * xv[i];
    if (lane == 0) uo[0] = 0.f;

    float* up = g_u + (size_t)node * D + base;
    *(float4*)(up)     = *(float4*)&uo[0];
    *(float4*)(up + 4) = *(float4*)&uo[4];

    // zero H row and S
    const float4 z4 = make_float4(0.f, 0.f, 0.f, 0.f);
    float* Hp = g_H + (size_t)node * D + base;
    *(float4*)(Hp)     = z4;
    *(float4*)(Hp + 4) = z4;
    if (lane == 0) g_S[node] = 0.f;
}

// ---------------- tf32 MMA GEMM: BM=64, BN=128, BK=32, 128 threads -----------
struct StA { float4 f00, f01, f10, f11; };
struct StB { float2 g[8]; };

__device__ __forceinline__ void mma_stage_fetchA(StA& st, const float* pa0,
                                                 const float* pa1, bool ok0,
                                                 bool ok1) {
    const float4 z4 = make_float4(0.f, 0.f, 0.f, 0.f);
    st.f00 = ok0 ? *(const float4*)(pa0)     : z4;
    st.f01 = ok0 ? *(const float4*)(pa0 + 4) : z4;
    st.f10 = ok1 ? *(const float4*)(pa1)     : z4;
    st.f11 = ok1 ? *(const float4*)(pa1 + 4) : z4;
}
__device__ __forceinline__ void mma_stage_storeA(unsigned* dst, const StA& st) {
    const float* a00 = &st.f00.x;
    const float* a01 = &st.f01.x;
    const float* a10 = &st.f10.x;
    const float* a11 = &st.f11.x;
    #pragma unroll
    for (int dl = 0; dl < 4; dl++) {
        uint4 v = make_uint4(t32(a00[dl]), t32(a10[dl]), t32(a01[dl]), t32(a11[dl]));
        ((uint4*)dst)[dl] = v;
    }
}
__device__ __forceinline__ void mma_stage_fetchB(StB& st, const float* pb) {
    #pragma unroll
    for (int j = 0; j < 8; j++) st.g[j] = *(const float2*)(pb + j * 256);
}
__device__ __forceinline__ void mma_stage_storeB(unsigned* dst, const StB& st) {
    uint4 v0 = make_uint4(t32(st.g[0].x), t32(st.g[4].x), t32(st.g[1].x), t32(st.g[5].x));
    uint4 v1 = make_uint4(t32(st.g[2].x), t32(st.g[6].x), t32(st.g[3].x), t32(st.g[7].x));
    uint4 v2 = make_uint4(t32(st.g[0].y), t32(st.g[4].y), t32(st.g[1].y), t32(st.g[5].y));
    uint4 v3 = make_uint4(t32(st.g[2].y), t32(st.g[6].y), t32(st.g[3].y), t32(st.g[7].y));
    ((uint4*)dst)[0] = v0; ((uint4*)dst)[1] = v1;
    ((uint4*)dst)[2] = v2; ((uint4*)dst)[3] = v3;
}

__device__ __forceinline__ void mma_gemm_body_f32(const float* __restrict__ A,
                                                  const float* __restrict__ B,
                                                  float* __restrict__ C, int M) {
    __shared__ __align__(16) unsigned smA[2][2048];
    __shared__ __align__(16) unsigned smB[2][4096];
    int tid = threadIdx.x;
    int lane = tid & 31;
    int w = tid >> 5;
    int wm = w & 1, wn = w >> 1;
    int rowBase = blockIdx.y * 64;
    int colBase = blockIdx.x * 128;

    int aRow0 = rowBase + (tid >> 5) * 16 + (tid & 7);
    const float* pa0 = A + (size_t)aRow0 * 256 + ((tid >> 3) & 3) * 8;
    const float* pa1 = pa0 + 8 * 256;
    bool ok0 = aRow0 < M, ok1 = (aRow0 + 8) < M;
    const float* pb = B + (size_t)((tid >> 2) & 3) * 8 * 256 +
                      colBase + (tid >> 4) * 8 + 2 * (tid & 3);

    StA stA; StB stB0, stB1;
    mma_stage_fetchA(stA, pa0, pa1, ok0, ok1);
    mma_stage_fetchB(stB0, pb);
    mma_stage_fetchB(stB1, pb + 64);
    mma_stage_storeA(&smA[0][tid * 16], stA);
    mma_stage_storeB(&smB[0][tid * 16], stB0);
    mma_stage_storeB(&smB[0][2048 + tid * 16], stB1);
    __syncthreads();

    float d[2][8][4];
    #pragma unroll
    for (int t = 0; t < 2; t++)
        #pragma unroll
        for (int u = 0; u < 8; u++)
            #pragma unroll
            for (int c = 0; c < 4; c++) d[t][u][c] = 0.f;

    int buf = 0;
    for (int kb = 0; kb < 8; kb++) {
        if (kb < 7) {
            mma_stage_fetchA(stA, pa0 + (kb + 1) * 32, pa1 + (kb + 1) * 32, ok0, ok1);
            mma_stage_fetchB(stB0, pb + (size_t)(kb + 1) * 32 * 256);
            mma_stage_fetchB(stB1, pb + (size_t)(kb + 1) * 32 * 256 + 64);
        }
        #pragma unroll
        for (int s = 0; s < 4; s++) {
            uint4 fa0 = *(const uint4*)&smA[buf][((2 * wm + 0) * 4 + s) * 128 + lane * 4];
            uint4 fa1 = *(const uint4*)&smA[buf][((2 * wm + 1) * 4 + s) * 128 + lane * 4];
            uint2 fb[8];
            #pragma unroll
            for (int u = 0; u < 8; u++)
                fb[u] = *(const uint2*)&smB[buf][wn * 2048 + (u * 4 + s) * 64 + lane * 2];
            #pragma unroll
            for (int u = 0; u < 8; u++) {
                mma_tf32(d[0][u], fa0, fb[u]);
                mma_tf32(d[1][u], fa1, fb[u]);
            }
        }
        if (kb < 7) {
            int nb = buf ^ 1;
            mma_stage_storeA(&smA[nb][tid * 16], stA);
            mma_stage_storeB(&smB[nb][tid * 16], stB0);
            mma_stage_storeB(&smB[nb][2048 + tid * 16], stB1);
            __syncthreads();
            buf = nb;
        }
    }

    #pragma unroll
    for (int t = 0; t < 2; t++) {
        int r0 = rowBase + (2 * wm + t) * 16 + (lane >> 2);
        int r1 = r0 + 8;
        #pragma unroll
        for (int u = 0; u < 8; u++) {
            int c0 = colBase + wn * 64 + u * 8 + (lane & 3) * 2;
            if (r0 < M)
                *(float2*)(C + (size_t)r0 * 256 + c0) =
                    make_float2(d[t][u][0], d[t][u][1]);
            if (r1 < M)
                *(float2*)(C + (size_t)r1 * 256 + c0) =
                    make_float2(d[t][u][2], d[t][u][3]);
        }
    }
}

__global__ __launch_bounds__(128, 3) void mma_lin(const float* __restrict__ Wlin) {
    mma_gemm_body_f32(g_u, Wlin, g_h, NN);
}
__global__ __launch_bounds__(128, 3) void mma_agg(const float* __restrict__ We2) {
    mma_gemm_body_f32(g_H, We2, g_agg, NN);
}

// ---------------- fp16 MMA GEMM (m16n8k16): BM=64, BN=128, BK=32 -------------
__global__ __launch_bounds__(128, 3) void mma_qph() {
    int z = blockIdx.z;
    const __half* A = (z == 0) ? g_xph : g_xtanh;
    const __half* B = (z == 0) ? g_We1h : (z == 1 ? g_Wa1h : g_Wa1h + 256 * 256);
    __half* C = (z == 0) ? g_Qh : (z == 1 ? g_P1h : g_P2h);
    const int M = NN;

    __shared__ __align__(16) unsigned smA[2][1024];
    __shared__ __align__(16) unsigned smB[2][2048];
    int tid = threadIdx.x;
    int lane = tid & 31;
    int w = tid >> 5;
    int wm = w & 1, wn = w >> 1;
    int rowBase = blockIdx.y * 64;
    int colBase = blockIdx.x * 128;

    int ar = tid >> 1;
    int as = tid & 1;
    int aRow = rowBase + ar;
    bool aok = aRow < M;
    const __half* pa = A + (size_t)aRow * 256 + as * 16;
    int ag = ar >> 4;
    int rr = ar & 15;
    int abase = ((ag * 2 + as) * 32 + (rr & 7) * 4) * 4 + (rr >> 3);

    int kp2 = tid & 15;
    int nblk = tid >> 4;
    const __half* pb = B + (size_t)(kp2 * 2) * 256 + colBase + nblk * 16;
    int bs = kp2 >> 3;
    int kk = kp2 & 7;
    int bl4 = kk & 3;
    int breg = kk >> 2;

    const uint4 zz = make_uint4(0u, 0u, 0u, 0u);
    uint4 va, vb, u0, u1, v0, v1;

    va = aok ? *(const uint4*)(pa)     : zz;
    vb = aok ? *(const uint4*)(pa + 8) : zz;
    u0 = *(const uint4*)(pb);
    u1 = *(const uint4*)(pb + 8);
    v0 = *(const uint4*)(pb + 256);
    v1 = *(const uint4*)(pb + 256 + 8);

    {
        unsigned* dA = &smA[0][abase];
        dA[0] = va.x; dA[4] = va.y; dA[8]  = va.z; dA[12] = va.w;
        dA[2] = vb.x; dA[6] = vb.y; dA[10] = vb.z; dA[14] = vb.w;
        unsigned ub[8]  = {u0.x, u0.y, u0.z, u0.w, u1.x, u1.y, u1.z, u1.w};
        unsigned vbr[8] = {v0.x, v0.y, v0.z, v0.w, v1.x, v1.y, v1.z, v1.w};
        #pragma unroll
        for (int wi = 0; wi < 8; wi++) {
            unsigned f0 = prmt(ub[wi], vbr[wi], 0x5410);
            unsigned f1 = prmt(ub[wi], vbr[wi], 0x7632);
            int n0 = nblk * 16 + wi * 2;
            int gn = n0 >> 3;
            int l0 = n0 & 7;
            smB[0][((gn * 2 + bs) * 32 + l0 * 4 + bl4) * 2 + breg] = f0;
            smB[0][((gn * 2 + bs) * 32 + (l0 + 1) * 4 + bl4) * 2 + breg] = f1;
        }
    }
    __syncthreads();

    float d[2][8][4];
    #pragma unroll
    for (int t = 0; t < 2; t++)
        #pragma unroll
        for (int u = 0; u < 8; u++)
            #pragma unroll
            for (int c = 0; c < 4; c++) d[t][u][c] = 0.f;

    int buf = 0;
    for (int kb = 0; kb < 8; kb++) {
        if (kb < 7) {
            const __half* pan = pa + (kb + 1) * 32;
            va = aok ? *(const uint4*)(pan)     : zz;
            vb = aok ? *(const uint4*)(pan + 8) : zz;
            const __half* pbn = pb + (size_t)(kb + 1) * 32 * 256;
            u0 = *(const uint4*)(pbn);
            u1 = *(const uint4*)(pbn + 8);
            v0 = *(const uint4*)(pbn + 256);
            v1 = *(const uint4*)(pbn + 256 + 8);
        }
        #pragma unroll
        for (int s = 0; s < 2; s++) {
            uint4 fa0 = *(const uint4*)&smA[buf][(((wm * 2 + 0) * 2 + s) * 32 + lane) * 4];
            uint4 fa1 = *(const uint4*)&smA[buf][(((wm * 2 + 1) * 2 + s) * 32 + lane) * 4];
            uint2 fb[8];
            #pragma unroll
            for (int u = 0; u < 8; u++)
                fb[u] = *(const uint2*)&smB[buf][(((wn * 8 + u) * 2 + s) * 32 + lane) * 2];
            #pragma unroll
            for (int u = 0; u < 8; u++) {
                mma_f16(d[0][u], fa0, fb[u]);
                mma_f16(d[1][u], fa1, fb[u]);
            }
        }
        if (kb < 7) {
            int nb = buf ^ 1;
            unsigned* dA = &smA[nb][abase];
            dA[0] = va.x; dA[4] = va.y; dA[8]  = va.z; dA[12] = va.w;
            dA[2] = vb.x; dA[6] = vb.y; dA[10] = vb.z; dA[14] = vb.w;
            unsigned ub[8]  = {u0.x, u0.y, u0.z, u0.w, u1.x, u1.y, u1.z, u1.w};
            unsigned vbr[8] = {v0.x, v0.y, v0.z, v0.w, v1.x, v1.y, v1.z, v1.w};
            #pragma unroll
            for (int wi = 0; wi < 8; wi++) {
                unsigned f0 = prmt(ub[wi], vbr[wi], 0x5410);
                unsigned f1 = prmt(ub[wi], vbr[wi], 0x7632);
                int n0 = nblk * 16 + wi * 2;
                int gn = n0 >> 3;
                int l0 = n0 & 7;
                smB[nb][((gn * 2 + bs) * 32 + l0 * 4 + bl4) * 2 + breg] = f0;
                smB[nb][((gn * 2 + bs) * 32 + (l0 + 1) * 4 + bl4) * 2 + breg] = f1;
            }
            __syncthreads();
            buf = nb;
        }
    }

    #pragma unroll
    for (int t = 0; t < 2; t++) {
        int r0 = rowBase + (2 * wm + t) * 16 + (lane >> 2);
        int r1 = r0 + 8;
        #pragma unroll
        for (int u = 0; u < 8; u++) {
            int c0 = colBase + wn * 64 + u * 8 + (lane & 3) * 2;
            if (r0 < M)
                *(__half2*)(C + (size_t)r0 * 256 + c0) =
                    __floats2half2_rn(d[t][u][0], d[t][u][1]);
            if (r1 < M)
                *(__half2*)(C + (size_t)r1 * 256 + c0) =
                    __floats2half2_rn(d[t][u][2], d[t][u][3]);
        }
    }
}

// ---------------- node prep: one warp per node --------------------------------
__global__ __launch_bounds__(256) void k_node_xp(const float* __restrict__ bias) {
    int node = blockIdx.x * 8 + (threadIdx.x >> 5);
    int lane = threadIdx.x & 31;
    int base = lane * 8;

    float h[8];
    const float* hp = g_h + (size_t)node * D + base;
    *(float4*)&h[0] = *(const float4*)(hp);
    *(float4*)&h[4] = *(const float4*)(hp + 4);
    if (lane == 0) h[0] = 0.f;

    float acc = 0.f;
    #pragma unroll
    for (int i = 0; i < 8; i++) acc += h[i] * h[i];
    float r1 = warpSum(acc);
    float nn = sqrtf(fmaxf(r1, EPSF));
    float sh_n = sinhf(nn) / nn;
    float xp00 = coshf(nn);
    float xp0[8];
    #pragma unroll
    for (int i = 0; i < 8; i++) xp0[i] = sh_n * h[i];
    if (lane == 0) xp0[0] = xp00;

    float b[8];
    *(float4*)&b[0] = *(const float4*)(bias + base);
    *(float4*)&b[4] = *(const float4*)(bias + base + 4);
    if (lane == 0) b[0] = 0.f;

    acc = 0.f;
    #pragma unroll
    for (int i = 0; i < 8; i++) acc += xp0[i] * b[i];
    float c = warpSum(acc);
    float fac = c / (1.f + xp00);
    float u[8];
    #pragma unroll
    for (int i = 0; i < 8; i++) u[i] = b[i] + fac * xp0[i];
    if (lane == 0) u[0] += fac;

    acc = 0.f;
    #pragma unroll
    for (int i = 0; i < 8; i++) acc += u[i] * u[i];
    float su2 = warpSum(acc);
    float lin = su2 - 2.f * c * c;
    float nu = sqrtf(fmaxf(lin, EPSF));
    float ch = coshf(nu), sh = sinhf(nu) / nu;

    float xp[8];
    #pragma unroll
    for (int i = 0; i < 8; i++) xp[i] = ch * xp0[i] + sh * u[i];
    float* xpp = g_xp + (size_t)node * D + base;
    *(float4*)(xpp)     = *(float4*)&xp[0];
    *(float4*)(xpp + 4) = *(float4*)&xp[4];

    {
        __half2 q0 = __floats2half2_rn(xp[0], xp[1]);
        __half2 q1 = __floats2half2_rn(xp[2], xp[3]);
        __half2 q2 = __floats2half2_rn(xp[4], xp[5]);
        __half2 q3 = __floats2half2_rn(xp[6], xp[7]);
        uint4 o;
        o.x = *(unsigned*)&q0; o.y = *(unsigned*)&q1;
        o.z = *(unsigned*)&q2; o.w = *(unsigned*)&q3;
        *(uint4*)(g_xph + (size_t)node * D + base) = o;
    }

    float xpc0 = ch * xp00 + sh * c;
    float x0c = fmaxf(xpc0, 1.f + EPSF);
    float sc = acoshf(x0c) / sqrtf(x0c * x0c - 1.f);
    float xt[8];
    #pragma unroll
    for (int i = 0; i < 8; i++) xt[i] = sc * xp[i];
    if (lane == 0) xt[0] = 0.f;
    {
        __half2 q0 = __floats2half2_rn(xt[0], xt[1]);
        __half2 q1 = __floats2half2_rn(xt[2], xt[3]);
        __half2 q2 = __floats2half2_rn(xt[4], xt[5]);
        __half2 q3 = __floats2half2_rn(xt[6], xt[7]);
        uint4 o;
        o.x = *(unsigned*)&q0; o.y = *(unsigned*)&q1;
        o.z = *(unsigned*)&q2; o.w = *(unsigned*)&q3;
        *(uint4*)(g_xtanh + (size_t)node * D + base) = o;
    }
}

// ---------------- edge kernel: 32 edges per block (4 per warp), fp16 gathers --
__global__ __launch_bounds__(256) void k_edge(
    const float* __restrict__ eattr, const int* __restrict__ row,
    const int* __restrict__ col, const float* __restrict__ emask,
    const float* __restrict__ Wa1, const float* __restrict__ ba1,
    const float* __restrict__ Wa2, const float* __restrict__ ba2,
    const float* __restrict__ We1, const float* __restrict__ be1) {
    __shared__ float sw[8][256];
    int tid = threadIdx.x;
    sw[0][tid] = Wa1[512 * D + tid];
    sw[1][tid] = Wa1[513 * D + tid];
    sw[2][tid] = ba1[tid];
    sw[3][tid] = Wa2[tid];
    sw[4][tid] = We1[tid];
    sw[5][tid] = We1[256 * D + tid];
    sw[6][tid] = We1[257 * D + tid];
    sw[7][tid] = be1[tid];
    __syncthreads();

    int warp = tid >> 5;
    int lane = tid & 31;
    int base = lane * 8;
    float ba2v = ba2[0];

    #pragma unroll
    for (int it = 0; it < 4; it++) {
        int e = blockIdx.x * 32 + it * 8 + warp;

        int r = row[e];
        int c = col[e];

        float xr[8], xc[8];
        ld8h(g_xph + (size_t)r * D + base, xr);
        ld8h(g_xph + (size_t)c * D + base, xc);

        float part = 0.f;
        #pragma unroll
        for (int i = 0; i < 8; i++) part -= xr[i] * xc[i];
        part = warpSum(part);

        float x0 = __shfl_sync(0xffffffffu, xr[0], 0);
        float y0 = __shfl_sync(0xffffffffu, xc[0], 0);

        float a = fmaxf(part + 2.f * x0 * y0, 1.f + EPSF);
        float dd = acoshf(a);
        float q = sqrtf(a * a - 1.f);
        float s = dd / q;
        float v0 = s * (y0 - a * x0);
        float beta = -v0 / (1.f + x0);
        float alpha = beta - s * a;

        float ea0 = eattr[e];
        float m = emask[e];

        float P1v[8], P2v[8];
        ld8h(g_P1h + (size_t)r * D + base, P1v);
        ld8h(g_P2h + (size_t)c * D + base, P2v);

        float lp = 0.f;
        #pragma unroll
        for (int i = 0; i < 8; i++) {
            int j = base + i;
            float ha = P1v[i] + P2v[i] + ea0 * sw[0][j] + dd * sw[1][j] + sw[2][j];
            lp += silu_fast(ha) * sw[3][j];
        }
        lp = warpSum(lp);
        float att = m * sigm_fast(lp + ba2v);

        float QR[8], QC[8];
        ld8h(g_Qh + (size_t)r * D + base, QR);
        ld8h(g_Qh + (size_t)c * D + base, QC);

        float val[8];
        #pragma unroll
        for (int i = 0; i < 8; i++) {
            int j = base + i;
            float hm = alpha * QR[i] + s * QC[i] + beta * sw[4][j] +
                       ea0 * sw[5][j] + dd * sw[6][j] + sw[7][j];
            val[i] = att * silu_fast(hm);
        }

        float* Hr = g_H + (size_t)r * D + base;
        asm volatile("red.global.add.v4.f32 [%0], {%1,%2,%3,%4};"
                     :: "l"(Hr), "f"(val[0]), "f"(val[1]), "f"(val[2]), "f"(val[3])
                     : "memory");
        asm volatile("red.global.add.v4.f32 [%0], {%1,%2,%3,%4};"
                     :: "l"(Hr + 4), "f"(val[4]), "f"(val[5]), "f"(val[6]), "f"(val[7])
                     : "memory");
        if (lane == 0) atomicAdd(&g_S[r], att);
    }
}

// ---------------- final node kernel: one warp per node -----------------------
__global__ __launch_bounds__(256) void k_final(const float* __restrict__ be2,
                                               const float* __restrict__ lng,
                                               const float* __restrict__ lnb,
                                               float* __restrict__ out) {
    int node = blockIdx.x * 8 + (threadIdx.x >> 5);
    int lane = threadIdx.x & 31;
    int base = lane * 8;

    float Sv = g_S[node];
    float ag[8], be[8], xp[8];
    const float* agp = g_agg + (size_t)node * D + base;
    *(float4*)&ag[0] = *(const float4*)(agp);
    *(float4*)&ag[4] = *(const float4*)(agp + 4);
    *(float4*)&be[0] = *(const float4*)(be2 + base);
    *(float4*)&be[4] = *(const float4*)(be2 + base + 4);
    const float* xpp = g_xp + (size_t)node * D + base;
    *(float4*)&xp[0] = *(const float4*)(xpp);
    *(float4*)&xp[4] = *(const float4*)(xpp + 4);

    #pragma unroll
    for (int i = 0; i < 8; i++) ag[i] += Sv * be[i];
    if (lane == 0) ag[0] = 0.f;

    float xp0 = __shfl_sync(0xffffffffu, xp[0], 0);

    float acc = 0.f;
    #pragma unroll
    for (int i = 0; i < 8; i++) acc += xp[i] * ag[i];
    float cc = warpSum(acc);
    float fac = cc / (1.f + xp0);
    float sup[8];
    #pragma unroll
    for (int i = 0; i < 8; i++) sup[i] = ag[i] + fac * xp[i];
    if (lane == 0) sup[0] += fac;

    acc = 0.f;
    #pragma unroll
    for (int i = 0; i < 8; i++) acc += sup[i] * sup[i];
    float su2 = warpSum(acc);
    float lin = su2 - 2.f * cc * cc;
    float nu = sqrtf(fmaxf(lin, EPSF));
    float ch = coshf(nu), sh = sinhf(nu) / nu;

    float y[8];
    #pragma unroll
    for (int i = 0; i < 8; i++) y[i] = ch * xp[i] + sh * sup[i];
    float y0 = ch * xp0 + sh * cc;

    float y0c = fmaxf(y0, 1.f + EPSF);
    float sc = acoshf(y0c) / sqrtf(y0c * y0c - 1.f);
    float xo[8];
    #pragma unroll
    for (int i = 0; i < 8; i++) xo[i] = sc * y[i];
    if (lane == 0) xo[0] = 0.f;

    acc = 0.f;
    #pragma unroll
    for (int i = 0; i < 8; i++) acc += xo[i];
    float mean = warpSum(acc) * (1.f / 255.f);
    float dev[8];
    #pragma unroll
    for (int i = 0; i < 8; i++) dev[i] = xo[i] - mean;
    if (lane == 0) dev[0] = 0.f;
    acc = 0.f;
    #pragma unroll
    for (int i = 0; i < 8; i++) acc += dev[i] * dev[i];
    float var = warpSum(acc) * (1.f / 255.f);
    float inv = 1.f / sqrtf(var + 1e-5f);

    float sl[8];
    #pragma unroll
    for (int i = 0; i < 8; i++) {
        int j = base + i;
        float lg = (j > 0) ? lng[j - 1] : 0.f;
        float lb = (j > 0) ? lnb[j - 1] : 0.f;
        float ln = dev[i] * inv * lg + lb;
        sl[i] = siluf(ln);
    }
    if (lane == 0) sl[0] = 0.f;

    acc = 0.f;
    #pragma unroll
    for (int i = 0; i < 8; i++) acc += sl[i] * sl[i];
    float n2 = warpSum(acc);
    float nn = sqrtf(fmaxf(n2, EPSF));
    float shn = sinhf(nn) / nn;

    float o[8];
    #pragma unroll
    for (int i = 0; i < 8; i++) o[i] = shn * sl[i];
    if (lane == 0) o[0] = coshf(nn);
    float* op = out + (size_t)node * D + base;
    *(float4*)(op)     = *(float4*)&o[0];
    *(float4*)(op + 4) = *(float4*)&o[4];
}

// ---------------- launch -----------------------------------------------------
extern "C" void kernel_launch(void* const* d_in, const int* in_sizes, int n_in,
                              void* d_out, int out_size) {
    const float* x     = (const float*)d_in[0];
    const float* eattr = (const float*)d_in[1];
    const int*   row   = (const int*)d_in[2];
    const int*   col   = (const int*)d_in[3];
    const float* emask = (const float*)d_in[5];
    const float* W_lin = (const float*)d_in[6];
    const float* bias  = (const float*)d_in[7];
    const float* W_e1  = (const float*)d_in[8];
    const float* b_e1  = (const float*)d_in[9];
    const float* W_e2  = (const float*)d_in[10];
    const float* b_e2  = (const float*)d_in[11];
    const float* W_a1  = (const float*)d_in[12];
    const float* b_a1  = (const float*)d_in[13];
    const float* W_a2  = (const float*)d_in[14];
    const float* b_a2  = (const float*)d_in[15];
    const float* ln_g  = (const float*)d_in[16];
    const float* ln_b  = (const float*)d_in[17];
    float* out = (float*)d_out;

    dim3 gMma(2, (NN + 63) / 64);
    dim3 gMmaQP(2, (NN + 63) / 64, 3);

    k_logmap0_fused<<<LOG_BLOCKS + 768, 256>>>(x, W_e1, W_a1);  // logmap + zero + cvt
    mma_lin<<<gMma, 128>>>(W_lin);                      // tf32
    k_node_xp<<<NN / 8, 256>>>(bias);
    mma_qph<<<gMmaQP, 128>>>();                         // fp16 m16n8k16
    k_edge<<<NE / 32, 256>>>(eattr, row, col, emask, W_a1, b_a1, W_a2, b_a2, W_e1, b_e1);
    mma_agg<<<gMma, 128>>>(W_e2);                       // tf32
    k_final<<<NN / 8, 256>>>(b_e2, ln_g, ln_b, out);
}

// round 15
// speedup vs baseline: 1.4879x; 1.1073x over previous
#include <cuda_runtime.h>
#include <cuda_fp16.h>
#include <math.h>

#define NN 10000
#define NE 200000
#define D  256
#define EPSF 1e-6f

typedef unsigned long long u64;

// ---------------- scratch (device globals: no allocation allowed) ----------
__device__ __align__(128) float g_u[NN * D];
__device__ __align__(128) float g_h[NN * D];
__device__ __align__(128) float g_xp[NN * D];
__device__ __align__(128) __half g_xph[NN * D];    // fp16 xp
__device__ __align__(128) __half g_xtanh[NN * D];  // fp16 xtan
__device__ __align__(128) __half g_Qh[NN * D];
__device__ __align__(128) __half g_P1h[NN * D];
__device__ __align__(128) __half g_P2h[NN * D];
__device__ __align__(128) float g_H[NN * D];
__device__ __align__(128) float g_agg[NN * D];
__device__ __align__(128) float g_S[NN];
// fragment-packed weight images
__device__ __align__(128) unsigned g_WlinP[65536];      // tf32 packed
__device__ __align__(128) unsigned g_We2P[65536];       // tf32 packed
__device__ __align__(128) unsigned g_WqpP[3 * 32768];   // fp16 packed (We1,Wa1P1,Wa1P2)

// ---------------- tf32 helpers ------------------------------------------------
__device__ __forceinline__ unsigned t32(float f) {
    unsigned r; asm("cvt.rna.tf32.f32 %0,%1;" : "=r"(r) : "f"(f)); return r;
}
__device__ __forceinline__ void mma_tf32(float* d, const uint4& a, const uint2& b) {
    asm volatile(
        "mma.sync.aligned.m16n8k8.row.col.f32.tf32.tf32.f32 "
        "{%0,%1,%2,%3},{%4,%5,%6,%7},{%8,%9},{%0,%1,%2,%3};"
        : "+f"(d[0]), "+f"(d[1]), "+f"(d[2]), "+f"(d[3])
        : "r"(a.x), "r"(a.y), "r"(a.z), "r"(a.w), "r"(b.x), "r"(b.y));
}
__device__ __forceinline__ void mma_f16(float* d, const uint4& a, const uint2& b) {
    asm volatile(
        "mma.sync.aligned.m16n8k16.row.col.f32.f16.f16.f32 "
        "{%0,%1,%2,%3},{%4,%5,%6,%7},{%8,%9},{%0,%1,%2,%3};"
        : "+f"(d[0]), "+f"(d[1]), "+f"(d[2]), "+f"(d[3])
        : "r"(a.x), "r"(a.y), "r"(a.z), "r"(a.w), "r"(b.x), "r"(b.y));
}

// ---------------- misc helpers ------------------------------------------------
__device__ __forceinline__ float warpSum(float v) {
    #pragma unroll
    for (int o = 16; o > 0; o >>= 1) v += __shfl_xor_sync(0xffffffffu, v, o);
    return v;
}
__device__ __forceinline__ float siluf(float x) { return x / (1.f + expf(-x)); }
__device__ __forceinline__ float tanh_ap(float x) {
    float y; asm("tanh.approx.f32 %0,%1;" : "=f"(y) : "f"(x)); return y;
}
__device__ __forceinline__ float sigm_fast(float x) {
    return fmaf(0.5f, tanh_ap(0.5f * x), 0.5f);
}
__device__ __forceinline__ float silu_fast(float x) { return x * sigm_fast(x); }

__device__ __forceinline__ void ld8h(const __half* p, float* o) {
    uint4 v = *(const uint4*)p;
    __half2 h0 = *(__half2*)&v.x, h1 = *(__half2*)&v.y,
            h2 = *(__half2*)&v.z, h3 = *(__half2*)&v.w;
    float2 f;
    f = __half22float2(h0); o[0] = f.x; o[1] = f.y;
    f = __half22float2(h1); o[2] = f.x; o[3] = f.y;
    f = __half22float2(h2); o[4] = f.x; o[5] = f.y;
    f = __half22float2(h3); o[6] = f.x; o[7] = f.y;
}

// ---------------- tf32 staging helpers (shared by GEMM + pack) ---------------
struct StA { float4 f00, f01, f10, f11; };
struct StB { float2 g[8]; };

__device__ __forceinline__ void mma_stage_fetchA(StA& st, const float* pa0,
                                                 const float* pa1, bool ok0,
                                                 bool ok1) {
    const float4 z4 = make_float4(0.f, 0.f, 0.f, 0.f);
    st.f00 = ok0 ? *(const float4*)(pa0)     : z4;
    st.f01 = ok0 ? *(const float4*)(pa0 + 4) : z4;
    st.f10 = ok1 ? *(const float4*)(pa1)     : z4;
    st.f11 = ok1 ? *(const float4*)(pa1 + 4) : z4;
}
__device__ __forceinline__ void mma_stage_storeA(unsigned* dst, const StA& st) {
    const float* a00 = &st.f00.x;
    const float* a01 = &st.f01.x;
    const float* a10 = &st.f10.x;
    const float* a11 = &st.f11.x;
    #pragma unroll
    for (int dl = 0; dl < 4; dl++) {
        uint4 v = make_uint4(t32(a00[dl]), t32(a10[dl]), t32(a01[dl]), t32(a11[dl]));
        ((uint4*)dst)[dl] = v;
    }
}
__device__ __forceinline__ void mma_stage_fetchB(StB& st, const float* pb) {
    #pragma unroll
    for (int j = 0; j < 8; j++) st.g[j] = *(const float2*)(pb + j * 256);
}
__device__ __forceinline__ void mma_stage_storeB(unsigned* dst, const StB& st) {
    uint4 v0 = make_uint4(t32(st.g[0].x), t32(st.g[4].x), t32(st.g[1].x), t32(st.g[5].x));
    uint4 v1 = make_uint4(t32(st.g[2].x), t32(st.g[6].x), t32(st.g[3].x), t32(st.g[7].x));
    uint4 v2 = make_uint4(t32(st.g[0].y), t32(st.g[4].y), t32(st.g[1].y), t32(st.g[5].y));
    uint4 v3 = make_uint4(t32(st.g[2].y), t32(st.g[6].y), t32(st.g[3].y), t32(st.g[7].y));
    ((uint4*)dst)[0] = v0; ((uint4*)dst)[1] = v1;
    ((uint4*)dst)[2] = v2; ((uint4*)dst)[3] = v3;
}

// ---------------- fused: logmap0 + zero + weight fragment-packing ------------
#define LOG_BLOCKS (NN / 8)
__global__ __launch_bounds__(256) void k_logmap0_fused(
    const float* __restrict__ x, const float* __restrict__ We1,
    const float* __restrict__ Wa1, const float* __restrict__ Wlin,
    const float* __restrict__ We2) {
    int b = blockIdx.x;
    int tid = threadIdx.x;
    if (b >= LOG_BLOCKS) {
        int pb = b - LOG_BLOCKS;
        if (pb < 32) {
            // tf32 pack (Wlin / We2): mirror of mma_gemm_body_f32 B staging
            const float* W = (pb < 16) ? Wlin : We2;
            unsigned* P = (pb < 16) ? g_WlinP : g_We2P;
            int t = (pb & 15) * 256 + tid;           // 0..4095
            int half = t & 1;
            int tt = (t >> 1) & 127;
            int kb = (t >> 8) & 7;
            int colBlk = t >> 11;
            const float* pbs = W + ((tt >> 2) & 3) * 8 * 256 + colBlk * 128 +
                               (tt >> 4) * 8 + 2 * (tt & 3) + half * 64 +
                               kb * 32 * 256;
            StB st; mma_stage_fetchB(st, pbs);
            mma_stage_storeB(P + colBlk * 32768 + kb * 4096 + half * 2048 + tt * 16, st);
        } else {
            // fp16 pack (We1, Wa1[0:256], Wa1[256:512]): mirror of mma_qph B staging
            int t = (pb - 32) * 256 + tid;           // 0..6143
            int m = t >> 11;
            int tt = t & 2047;
            int tid128 = tt & 127;
            int kb = (tt >> 7) & 7;
            int colBlk = tt >> 10;
            const float* W = (m == 0) ? We1 : Wa1 + (m - 1) * 256 * 256;
            unsigned* P = g_WqpP + m * 32768 + colBlk * 16384 + kb * 2048;
            int kp2 = tid128 & 15;
            int nblk = tid128 >> 4;
            int bs = kp2 >> 3;
            int kk = kp2 & 7;
            int bl4 = kk & 3;
            int breg = kk >> 2;
            int k0 = kb * 32 + kp2 * 2;
            #pragma unroll
            for (int wi = 0; wi < 8; wi++) {
                int n0 = nblk * 16 + wi * 2;               // col rel. to colBase
                int cabs = colBlk * 128 + n0;
                __half2 f0 = __floats2half2_rn(W[(size_t)k0 * 256 + cabs],
                                               W[(size_t)(k0 + 1) * 256 + cabs]);
                __half2 f1 = __floats2half2_rn(W[(size_t)k0 * 256 + cabs + 1],
                                               W[(size_t)(k0 + 1) * 256 + cabs + 1]);
                int gn = n0 >> 3;
                int l0 = n0 & 7;
                P[((gn * 2 + bs) * 32 + l0 * 4 + bl4) * 2 + breg] = *(unsigned*)&f0;
                P[((gn * 2 + bs) * 32 + (l0 + 1) * 4 + bl4) * 2 + breg] = *(unsigned*)&f1;
            }
        }
        return;
    }
    int node = b * 8 + (tid >> 5);
    int lane = tid & 31;
    int base = lane * 8;

    float xv[8];
    const float* xp = x + (size_t)node * D + base;
    *(float4*)&xv[0] = *(const float4*)(xp);
    *(float4*)&xv[4] = *(const float4*)(xp + 4);

    float x0 = fmaxf(__shfl_sync(0xffffffffu, xv[0], 0), 1.f + EPSF);
    float sc = acoshf(x0) / sqrtf(x0 * x0 - 1.f);

    float uo[8];
    #pragma unroll
    for (int i = 0; i < 8; i++) uo[i] = sc * xv[i];
    if (lane == 0) uo[0] = 0.f;

    float* up = g_u + (size_t)node * D + base;
    *(float4*)(up)     = *(float4*)&uo[0];
    *(float4*)(up + 4) = *(float4*)&uo[4];

    const float4 z4 = make_float4(0.f, 0.f, 0.f, 0.f);
    float* Hp = g_H + (size_t)node * D + base;
    *(float4*)(Hp)     = z4;
    *(float4*)(Hp + 4) = z4;
    if (lane == 0) g_S[node] = 0.f;
}

// ---------------- tf32 MMA GEMM with pre-packed B ----------------------------
__device__ __forceinline__ void mma_gemm_body_f32(const float* __restrict__ A,
                                                  const unsigned* __restrict__ PB,
                                                  float* __restrict__ C, int M) {
    __shared__ __align__(16) unsigned smA[2][2048];
    __shared__ __align__(16) unsigned smB[2][4096];
    int tid = threadIdx.x;
    int lane = tid & 31;
    int w = tid >> 5;
    int wm = w & 1, wn = w >> 1;
    int rowBase = blockIdx.y * 64;

    int aRow0 = rowBase + (tid >> 5) * 16 + (tid & 7);
    const float* pa0 = A + (size_t)aRow0 * 256 + ((tid >> 3) & 3) * 8;
    const float* pa1 = pa0 + 8 * 256;
    bool ok0 = aRow0 < M, ok1 = (aRow0 + 8) < M;
    const uint4* pbp = (const uint4*)(PB + blockIdx.x * 32768);

    StA stA;
    uint4 rb[8];
    mma_stage_fetchA(stA, pa0, pa1, ok0, ok1);
    #pragma unroll
    for (int q = 0; q < 8; q++) rb[q] = pbp[q * 128 + tid];
    mma_stage_storeA(&smA[0][tid * 16], stA);
    #pragma unroll
    for (int q = 0; q < 8; q++) ((uint4*)smB[0])[q * 128 + tid] = rb[q];
    __syncthreads();

    float d[2][8][4];
    #pragma unroll
    for (int t = 0; t < 2; t++)
        #pragma unroll
        for (int u = 0; u < 8; u++)
            #pragma unroll
            for (int c = 0; c < 4; c++) d[t][u][c] = 0.f;

    int buf = 0;
    for (int kb = 0; kb < 8; kb++) {
        if (kb < 7) {
            mma_stage_fetchA(stA, pa0 + (kb + 1) * 32, pa1 + (kb + 1) * 32, ok0, ok1);
            #pragma unroll
            for (int q = 0; q < 8; q++)
                rb[q] = pbp[(kb + 1) * 1024 + q * 128 + tid];
        }
        #pragma unroll
        for (int s = 0; s < 4; s++) {
            uint4 fa0 = *(const uint4*)&smA[buf][((2 * wm + 0) * 4 + s) * 128 + lane * 4];
            uint4 fa1 = *(const uint4*)&smA[buf][((2 * wm + 1) * 4 + s) * 128 + lane * 4];
            uint2 fb[8];
            #pragma unroll
            for (int u = 0; u < 8; u++)
                fb[u] = *(const uint2*)&smB[buf][wn * 2048 + (u * 4 + s) * 64 + lane * 2];
            #pragma unroll
            for (int u = 0; u < 8; u++) {
                mma_tf32(d[0][u], fa0, fb[u]);
                mma_tf32(d[1][u], fa1, fb[u]);
            }
        }
        if (kb < 7) {
            int nb = buf ^ 1;
            mma_stage_storeA(&smA[nb][tid * 16], stA);
            #pragma unroll
            for (int q = 0; q < 8; q++) ((uint4*)smB[nb])[q * 128 + tid] = rb[q];
            __syncthreads();
            buf = nb;
        }
    }

    int colBase = blockIdx.x * 128;
    #pragma unroll
    for (int t = 0; t < 2; t++) {
        int r0 = rowBase + (2 * wm + t) * 16 + (lane >> 2);
        int r1 = r0 + 8;
        #pragma unroll
        for (int u = 0; u < 8; u++) {
            int c0 = colBase + wn * 64 + u * 8 + (lane & 3) * 2;
            if (r0 < M)
                *(float2*)(C + (size_t)r0 * 256 + c0) =
                    make_float2(d[t][u][0], d[t][u][1]);
            if (r1 < M)
                *(float2*)(C + (size_t)r1 * 256 + c0) =
                    make_float2(d[t][u][2], d[t][u][3]);
        }
    }
}

__global__ __launch_bounds__(128, 3) void mma_lin() {
    mma_gemm_body_f32(g_u, g_WlinP, g_h, NN);
}
__global__ __launch_bounds__(128, 3) void mma_agg() {
    mma_gemm_body_f32(g_H, g_We2P, g_agg, NN);
}

// ---------------- fp16 MMA GEMM (m16n8k16) with pre-packed B -----------------
__global__ __launch_bounds__(128, 3) void mma_qph() {
    int z = blockIdx.z;
    const __half* A = (z == 0) ? g_xph : g_xtanh;
    __half* C = (z == 0) ? g_Qh : (z == 1 ? g_P1h : g_P2h);
    const int M = NN;

    __shared__ __align__(16) unsigned smA[2][1024];
    __shared__ __align__(16) unsigned smB[2][2048];
    int tid = threadIdx.x;
    int lane = tid & 31;
    int w = tid >> 5;
    int wm = w & 1, wn = w >> 1;
    int rowBase = blockIdx.y * 64;
    int colBase = blockIdx.x * 128;

    int ar = tid >> 1;
    int as = tid & 1;
    int aRow = rowBase + ar;
    bool aok = aRow < M;
    const __half* pa = A + (size_t)aRow * 256 + as * 16;
    int ag = ar >> 4;
    int rr = ar & 15;
    int abase = ((ag * 2 + as) * 32 + (rr & 7) * 4) * 4 + (rr >> 3);
    const uint4* pbp = (const uint4*)(g_WqpP + z * 32768 + blockIdx.x * 16384);

    const uint4 zz = make_uint4(0u, 0u, 0u, 0u);
    uint4 va, vb, rb[4];

    va = aok ? *(const uint4*)(pa)     : zz;
    vb = aok ? *(const uint4*)(pa + 8) : zz;
    #pragma unroll
    for (int q = 0; q < 4; q++) rb[q] = pbp[q * 128 + tid];

    {
        unsigned* dA = &smA[0][abase];
        dA[0] = va.x; dA[4] = va.y; dA[8]  = va.z; dA[12] = va.w;
        dA[2] = vb.x; dA[6] = vb.y; dA[10] = vb.z; dA[14] = vb.w;
        #pragma unroll
        for (int q = 0; q < 4; q++) ((uint4*)smB[0])[q * 128 + tid] = rb[q];
    }
    __syncthreads();

    float d[2][8][4];
    #pragma unroll
    for (int t = 0; t < 2; t++)
        #pragma unroll
        for (int u = 0; u < 8; u++)
            #pragma unroll
            for (int c = 0; c < 4; c++) d[t][u][c] = 0.f;

    int buf = 0;
    for (int kb = 0; kb < 8; kb++) {
        if (kb < 7) {
            const __half* pan = pa + (kb + 1) * 32;
            va = aok ? *(const uint4*)(pan)     : zz;
            vb = aok ? *(const uint4*)(pan + 8) : zz;
            #pragma unroll
            for (int q = 0; q < 4; q++)
                rb[q] = pbp[(kb + 1) * 512 + q * 128 + tid];
        }
        #pragma unroll
        for (int s = 0; s < 2; s++) {
            uint4 fa0 = *(const uint4*)&smA[buf][(((wm * 2 + 0) * 2 + s) * 32 + lane) * 4];
            uint4 fa1 = *(const uint4*)&smA[buf][(((wm * 2 + 1) * 2 + s) * 32 + lane) * 4];
            uint2 fb[8];
            #pragma unroll
            for (int u = 0; u < 8; u++)
                fb[u] = *(const uint2*)&smB[buf][(((wn * 8 + u) * 2 + s) * 32 + lane) * 2];
            #pragma unroll
            for (int u = 0; u < 8; u++) {
                mma_f16(d[0][u], fa0, fb[u]);
                mma_f16(d[1][u], fa1, fb[u]);
            }
        }
        if (kb < 7) {
            int nb = buf ^ 1;
            unsigned* dA = &smA[nb][abase];
            dA[0] = va.x; dA[4] = va.y; dA[8]  = va.z; dA[12] = va.w;
            dA[2] = vb.x; dA[6] = vb.y; dA[10] = vb.z; dA[14] = vb.w;
            #pragma unroll
            for (int q = 0; q < 4; q++) ((uint4*)smB[nb])[q * 128 + tid] = rb[q];
            __syncthreads();
            buf = nb;
        }
    }

    #pragma unroll
    for (int t = 0; t < 2; t++) {
        int r0 = rowBase + (2 * wm + t) * 16 + (lane >> 2);
        int r1 = r0 + 8;
        #pragma unroll
        for (int u = 0; u < 8; u++) {
            int c0 = colBase + wn * 64 + u * 8 + (lane & 3) * 2;
            if (r0 < M)
                *(__half2*)(C + (size_t)r0 * 256 + c0) =
                    __floats2half2_rn(d[t][u][0], d[t][u][1]);
            if (r1 < M)
                *(__half2*)(C + (size_t)r1 * 256 + c0) =
                    __floats2half2_rn(d[t][u][2], d[t][u][3]);
        }
    }
}

// ---------------- node prep: one warp per node --------------------------------
__global__ __launch_bounds__(256) void k_node_xp(const float* __restrict__ bias) {
    int node = blockIdx.x * 8 + (threadIdx.x >> 5);
    int lane = threadIdx.x & 31;
    int base = lane * 8;

    float h[8];
    const float* hp = g_h + (size_t)node * D + base;
    *(float4*)&h[0] = *(const float4*)(hp);
    *(float4*)&h[4] = *(const float4*)(hp + 4);
    if (lane == 0) h[0] = 0.f;

    float acc = 0.f;
    #pragma unroll
    for (int i = 0; i < 8; i++) acc += h[i] * h[i];
    float r1 = warpSum(acc);
    float nn = sqrtf(fmaxf(r1, EPSF));
    float sh_n = sinhf(nn) / nn;
    float xp00 = coshf(nn);
    float xp0[8];
    #pragma unroll
    for (int i = 0; i < 8; i++) xp0[i] = sh_n * h[i];
    if (lane == 0) xp0[0] = xp00;

    float b[8];
    *(float4*)&b[0] = *(const float4*)(bias + base);
    *(float4*)&b[4] = *(const float4*)(bias + base + 4);
    if (lane == 0) b[0] = 0.f;

    acc = 0.f;
    #pragma unroll
    for (int i = 0; i < 8; i++) acc += xp0[i] * b[i];
    float c = warpSum(acc);
    float fac = c / (1.f + xp00);
    float u[8];
    #pragma unroll
    for (int i = 0; i < 8; i++) u[i] = b[i] + fac * xp0[i];
    if (lane == 0) u[0] += fac;

    acc = 0.f;
    #pragma unroll
    for (int i = 0; i < 8; i++) acc += u[i] * u[i];
    float su2 = warpSum(acc);
    float lin = su2 - 2.f * c * c;
    float nu = sqrtf(fmaxf(lin, EPSF));
    float ch = coshf(nu), sh = sinhf(nu) / nu;

    float xp[8];
    #pragma unroll
    for (int i = 0; i < 8; i++) xp[i] = ch * xp0[i] + sh * u[i];
    float* xpp = g_xp + (size_t)node * D + base;
    *(float4*)(xpp)     = *(float4*)&xp[0];
    *(float4*)(xpp + 4) = *(float4*)&xp[4];

    {
        __half2 q0 = __floats2half2_rn(xp[0], xp[1]);
        __half2 q1 = __floats2half2_rn(xp[2], xp[3]);
        __half2 q2 = __floats2half2_rn(xp[4], xp[5]);
        __half2 q3 = __floats2half2_rn(xp[6], xp[7]);
        uint4 o;
        o.x = *(unsigned*)&q0; o.y = *(unsigned*)&q1;
        o.z = *(unsigned*)&q2; o.w = *(unsigned*)&q3;
        *(uint4*)(g_xph + (size_t)node * D + base) = o;
    }

    float xpc0 = ch * xp00 + sh * c;
    float x0c = fmaxf(xpc0, 1.f + EPSF);
    float sc = acoshf(x0c) / sqrtf(x0c * x0c - 1.f);
    float xt[8];
    #pragma unroll
    for (int i = 0; i < 8; i++) xt[i] = sc * xp[i];
    if (lane == 0) xt[0] = 0.f;
    {
        __half2 q0 = __floats2half2_rn(xt[0], xt[1]);
        __half2 q1 = __floats2half2_rn(xt[2], xt[3]);
        __half2 q2 = __floats2half2_rn(xt[4], xt[5]);
        __half2 q3 = __floats2half2_rn(xt[6], xt[7]);
        uint4 o;
        o.x = *(unsigned*)&q0; o.y = *(unsigned*)&q1;
        o.z = *(unsigned*)&q2; o.w = *(unsigned*)&q3;
        *(uint4*)(g_xtanh + (size_t)node * D + base) = o;
    }
}

// ---------------- edge kernel: 32 edges per block (4 per warp), fp16 gathers --
__global__ __launch_bounds__(256) void k_edge(
    const float* __restrict__ eattr, const int* __restrict__ row,
    const int* __restrict__ col, const float* __restrict__ emask,
    const float* __restrict__ Wa1, const float* __restrict__ ba1,
    const float* __restrict__ Wa2, const float* __restrict__ ba2,
    const float* __restrict__ We1, const float* __restrict__ be1) {
    __shared__ float sw[8][256];
    int tid = threadIdx.x;
    sw[0][tid] = Wa1[512 * D + tid];
    sw[1][tid] = Wa1[513 * D + tid];
    sw[2][tid] = ba1[tid];
    sw[3][tid] = Wa2[tid];
    sw[4][tid] = We1[tid];
    sw[5][tid] = We1[256 * D + tid];
    sw[6][tid] = We1[257 * D + tid];
    sw[7][tid] = be1[tid];
    __syncthreads();

    int warp = tid >> 5;
    int lane = tid & 31;
    int base = lane * 8;
    float ba2v = ba2[0];

    #pragma unroll
    for (int it = 0; it < 4; it++) {
        int e = blockIdx.x * 32 + it * 8 + warp;

        int r = row[e];
        int c = col[e];

        float xr[8], xc[8];
        ld8h(g_xph + (size_t)r * D + base, xr);
        ld8h(g_xph + (size_t)c * D + base, xc);

        float part = 0.f;
        #pragma unroll
        for (int i = 0; i < 8; i++) part -= xr[i] * xc[i];
        part = warpSum(part);

        float x0 = __shfl_sync(0xffffffffu, xr[0], 0);
        float y0 = __shfl_sync(0xffffffffu, xc[0], 0);

        float a = fmaxf(part + 2.f * x0 * y0, 1.f + EPSF);
        float dd = acoshf(a);
        float q = sqrtf(a * a - 1.f);
        float s = dd / q;
        float v0 = s * (y0 - a * x0);
        float beta = -v0 / (1.f + x0);
        float alpha = beta - s * a;

        float ea0 = eattr[e];
        float m = emask[e];

        float P1v[8], P2v[8];
        ld8h(g_P1h + (size_t)r * D + base, P1v);
        ld8h(g_P2h + (size_t)c * D + base, P2v);

        float lp = 0.f;
        #pragma unroll
        for (int i = 0; i < 8; i++) {
            int j = base + i;
            float ha = P1v[i] + P2v[i] + ea0 * sw[0][j] + dd * sw[1][j] + sw[2][j];
            lp += silu_fast(ha) * sw[3][j];
        }
        lp = warpSum(lp);
        float att = m * sigm_fast(lp + ba2v);

        float QR[8], QC[8];
        ld8h(g_Qh + (size_t)r * D + base, QR);
        ld8h(g_Qh + (size_t)c * D + base, QC);

        float val[8];
        #pragma unroll
        for (int i = 0; i < 8; i++) {
            int j = base + i;
            float hm = alpha * QR[i] + s * QC[i] + beta * sw[4][j] +
                       ea0 * sw[5][j] + dd * sw[6][j] + sw[7][j];
            val[i] = att * silu_fast(hm);
        }

        float* Hr = g_H + (size_t)r * D + base;
        asm volatile("red.global.add.v4.f32 [%0], {%1,%2,%3,%4};"
                     :: "l"(Hr), "f"(val[0]), "f"(val[1]), "f"(val[2]), "f"(val[3])
                     : "memory");
        asm volatile("red.global.add.v4.f32 [%0], {%1,%2,%3,%4};"
                     :: "l"(Hr + 4), "f"(val[4]), "f"(val[5]), "f"(val[6]), "f"(val[7])
                     : "memory");
        if (lane == 0) atomicAdd(&g_S[r], att);
    }
}

// ---------------- final node kernel: one warp per node -----------------------
__global__ __launch_bounds__(256) void k_final(const float* __restrict__ be2,
                                               const float* __restrict__ lng,
                                               const float* __restrict__ lnb,
                                               float* __restrict__ out) {
    int node = blockIdx.x * 8 + (threadIdx.x >> 5);
    int lane = threadIdx.x & 31;
    int base = lane * 8;

    float Sv = g_S[node];
    float ag[8], be[8], xp[8];
    const float* agp = g_agg + (size_t)node * D + base;
    *(float4*)&ag[0] = *(const float4*)(agp);
    *(float4*)&ag[4] = *(const float4*)(agp + 4);
    *(float4*)&be[0] = *(const float4*)(be2 + base);
    *(float4*)&be[4] = *(const float4*)(be2 + base + 4);
    const float* xpp = g_xp + (size_t)node * D + base;
    *(float4*)&xp[0] = *(const float4*)(xpp);
    *(float4*)&xp[4] = *(const float4*)(xpp + 4);

    #pragma unroll
    for (int i = 0; i < 8; i++) ag[i] += Sv * be[i];
    if (lane == 0) ag[0] = 0.f;

    float xp0 = __shfl_sync(0xffffffffu, xp[0], 0);

    float acc = 0.f;
    #pragma unroll
    for (int i = 0; i < 8; i++) acc += xp[i] * ag[i];
    float cc = warpSum(acc);
    float fac = cc / (1.f + xp0);
    float sup[8];
    #pragma unroll
    for (int i = 0; i < 8; i++) sup[i] = ag[i] + fac * xp[i];
    if (lane == 0) sup[0] += fac;

    acc = 0.f;
    #pragma unroll
    for (int i = 0; i < 8; i++) acc += sup[i] * sup[i];
    float su2 = warpSum(acc);
    float lin = su2 - 2.f * cc * cc;
    float nu = sqrtf(fmaxf(lin, EPSF));
    float ch = coshf(nu), sh = sinhf(nu) / nu;

    float y[8];
    #pragma unroll
    for (int i = 0; i < 8; i++) y[i] = ch * xp[i] + sh * sup[i];
    float y0 = ch * xp0 + sh * cc;

    float y0c = fmaxf(y0, 1.f + EPSF);
    float sc = acoshf(y0c) / sqrtf(y0c * y0c - 1.f);
    float xo[8];
    #pragma unroll
    for (int i = 0; i < 8; i++) xo[i] = sc * y[i];
    if (lane == 0) xo[0] = 0.f;

    acc = 0.f;
    #pragma unroll
    for (int i = 0; i < 8; i++) acc += xo[i];
    float mean = warpSum(acc) * (1.f / 255.f);
    float dev[8];
    #pragma unroll
    for (int i = 0; i < 8; i++) dev[i] = xo[i] - mean;
    if (lane == 0) dev[0] = 0.f;
    acc = 0.f;
    #pragma unroll
    for (int i = 0; i < 8; i++) acc += dev[i] * dev[i];
    float var = warpSum(acc) * (1.f / 255.f);
    float inv = 1.f / sqrtf(var + 1e-5f);

    float sl[8];
    #pragma unroll
    for (int i = 0; i < 8; i++) {
        int j = base + i;
        float lg = (j > 0) ? lng[j - 1] : 0.f;
        float lb = (j > 0) ? lnb[j - 1] : 0.f;
        float ln = dev[i] * inv * lg + lb;
        sl[i] = siluf(ln);
    }
    if (lane == 0) sl[0] = 0.f;

    acc = 0.f;
    #pragma unroll
    for (int i = 0; i < 8; i++) acc += sl[i] * sl[i];
    float n2 = warpSum(acc);
    float nn = sqrtf(fmaxf(n2, EPSF));
    float shn = sinhf(nn) / nn;

    float o[8];
    #pragma unroll
    for (int i = 0; i < 8; i++) o[i] = shn * sl[i];
    if (lane == 0) o[0] = coshf(nn);
    float* op = out + (size_t)node * D + base;
    *(float4*)(op)     = *(float4*)&o[0];
    *(float4*)(op + 4) = *(float4*)&o[4];
}

// ---------------- launch -----------------------------------------------------
extern "C" void kernel_launch(void* const* d_in, const int* in_sizes, int n_in,
                              void* d_out, int out_size) {
    const float* x     = (const float*)d_in[0];
    const float* eattr = (const float*)d_in[1];
    const int*   row   = (const int*)d_in[2];
    const int*   col   = (const int*)d_in[3];
    const float* emask = (const float*)d_in[5];
    const float* W_lin = (const float*)d_in[6];
    const float* bias  = (const float*)d_in[7];
    const float* W_e1  = (const float*)d_in[8];
    const float* b_e1  = (const float*)d_in[9];
    const float* W_e2  = (const float*)d_in[10];
    const float* b_e2  = (const float*)d_in[11];
    const float* W_a1  = (const float*)d_in[12];
    const float* b_a1  = (const float*)d_in[13];
    const float* W_a2  = (const float*)d_in[14];
    const float* b_a2  = (const float*)d_in[15];
    const float* ln_g  = (const float*)d_in[16];
    const float* ln_b  = (const float*)d_in[17];
    float* out = (float*)d_out;

    dim3 gMma(2, (NN + 63) / 64);
    dim3 gMmaQP(2, (NN + 63) / 64, 3);

    k_logmap0_fused<<<LOG_BLOCKS + 56, 256>>>(x, W_e1, W_a1, W_lin, W_e2);
    mma_lin<<<gMma, 128>>>();                           // tf32, packed B
    k_node_xp<<<NN / 8, 256>>>(bias);
    mma_qph<<<gMmaQP, 128>>>();                         // fp16, packed B
    k_edge<<<NE / 32, 256>>>(eattr, row, col, emask, W_a1, b_a1, W_a2, b_a2, W_e1, b_e1);
    mma_agg<<<gMma, 128>>>();                           // tf32, packed B
    k_final<<<NN / 8, 256>>>(b_e2, ln_g, ln_b, out);
}